// round 1
// baseline (speedup 1.0000x reference)
#include <cuda_runtime.h>
#include <math.h>

// ---------------- problem constants ----------------
static const int NB   = 8;     // batch
static const int NN   = 1024;  // nodes (32*32)
static const int CIN  = 64;    // input channels
static const int HD   = 384;   // hidden
static const int NL   = 3;     // layers
static const int KNN  = 16;    // k
static const int NHE  = 3;     // heads
static const int DHE  = 128;   // head dim

// ---------------- device scratch (no allocs allowed) ----------------
__device__ float g_feats [NB*NN*CIN];
__device__ float g_h0    [NB*NN*HD];
__device__ float g_nh    [NB*NN*HD];
__device__ float g_sim   [NB*NN*NN];
__device__ int   g_knn   [NB*NN*KNN];
__device__ float g_hcur  [NB*NN*HD];
__device__ float g_xw    [NB*NN*HD];
__device__ float g_hloc  [NB*NN*HD];
__device__ float g_q     [NB*NN*HD];
__device__ float g_k     [NB*NN*HD];
__device__ float g_v     [NB*NN*HD];
__device__ float g_sc    [(long long)NB*NHE*NN*NN];
__device__ float g_ao    [NB*NN*HD];
__device__ float g_o     [NB*NN*HD];
__device__ float g_comb  [NB*NN*HD];
__device__ float g_mlp1  [NB*NN*2*HD];
__device__ float g_ff    [NB*NN*HD];
__device__ float g_pool  [NB*HD];
__device__ float g_z     [NB*HD];

// ---------------- generic tiled GEMM ----------------
// C[m,n] = alpha * sum_k A[m,k]*B[k,n]  (+bias[n]) (+Res[m,n]) (relu)
// TRANSB: B indexed as B[n,k] (row-major [N,K])
// batching: bz -> zo=bz/zi, zin=bz%zi; ptr += zo*sX + zin*sXi
#define BM 64
#define BN 64
#define BK 16

template<bool TRANSB, bool RELU>
__global__ void __launch_bounds__(256)
gemm_k(const float* __restrict__ A, const float* __restrict__ B,
       const float* __restrict__ bias, const float* __restrict__ Res,
       float* __restrict__ C,
       int M, int Nn, int K, int lda, int ldb, int ldc,
       long long sA, long long sAi, long long sB, long long sBi,
       long long sC, long long sCi, int zi, float alpha)
{
    int bz = blockIdx.z;
    int zo = bz / zi, zin = bz % zi;
    A += zo * sA + zin * sAi;
    B += zo * sB + zin * sBi;
    C += zo * sC + zin * sCi;
    if (Res) Res += zo * sC + zin * sCi;

    int m0 = blockIdx.y * BM;
    int n0 = blockIdx.x * BN;

    __shared__ float As[BK][BM];
    __shared__ float Bs[BK][BN];

    int tid = threadIdx.x;
    int tx = tid & 15, ty = tid >> 4;

    // load maps
    int a_m  = tid >> 2;
    int a_k  = (tid & 3) * 4;
    int b_k  = (tid >> 6) * 4;   // non-trans
    int b_n  = tid & 63;
    int bt_n = tid >> 2;         // trans
    int bt_k = (tid & 3) * 4;

    float acc[4][4] = {};

    for (int k0 = 0; k0 < K; k0 += BK) {
        float4 av = *(const float4*)(A + (long long)(m0 + a_m) * lda + k0 + a_k);
        As[a_k + 0][a_m] = av.x;
        As[a_k + 1][a_m] = av.y;
        As[a_k + 2][a_m] = av.z;
        As[a_k + 3][a_m] = av.w;
        if (TRANSB) {
            float4 bv = *(const float4*)(B + (long long)(n0 + bt_n) * ldb + k0 + bt_k);
            Bs[bt_k + 0][bt_n] = bv.x;
            Bs[bt_k + 1][bt_n] = bv.y;
            Bs[bt_k + 2][bt_n] = bv.z;
            Bs[bt_k + 3][bt_n] = bv.w;
        } else {
            #pragma unroll
            for (int r = 0; r < 4; r++)
                Bs[b_k + r][b_n] = B[(long long)(k0 + b_k + r) * ldb + n0 + b_n];
        }
        __syncthreads();
        #pragma unroll
        for (int kk = 0; kk < BK; kk++) {
            float4 a4 = *(const float4*)&As[kk][ty * 4];
            float4 b4 = *(const float4*)&Bs[kk][tx * 4];
            float a[4] = {a4.x, a4.y, a4.z, a4.w};
            float b[4] = {b4.x, b4.y, b4.z, b4.w};
            #pragma unroll
            for (int i = 0; i < 4; i++)
                #pragma unroll
                for (int j = 0; j < 4; j++)
                    acc[i][j] = fmaf(a[i], b[j], acc[i][j]);
        }
        __syncthreads();
    }

    #pragma unroll
    for (int i = 0; i < 4; i++) {
        int m = m0 + ty * 4 + i;
        #pragma unroll
        for (int j = 0; j < 4; j++) {
            int n = n0 + tx * 4 + j;
            float vv = acc[i][j] * alpha;
            if (bias) vv += bias[n];
            if (Res)  vv += Res[(long long)m * ldc + n];
            if (RELU) vv = fmaxf(vv, 0.f);
            C[(long long)m * ldc + n] = vv;
        }
    }
}

// ---------------- small kernels ----------------
__global__ void feats_kernel(const float* __restrict__ x, float* __restrict__ feats)
{
    long long i = (long long)blockIdx.x * blockDim.x + threadIdx.x;
    if (i >= (long long)NB * NN * CIN) return;
    int c = (int)(i & (CIN - 1));
    long long bn = i >> 6;
    int n = (int)(bn & (NN - 1));
    int b = (int)(bn >> 10);
    feats[i] = x[((long long)b * CIN + c) * NN + n];
}

// 128-thread two-value block reduce
__device__ __forceinline__ void block_reduce2(float& s1, float& s2)
{
    __shared__ float b1[4], b2[4];
    #pragma unroll
    for (int o = 16; o > 0; o >>= 1) {
        s1 += __shfl_down_sync(0xffffffffu, s1, o);
        s2 += __shfl_down_sync(0xffffffffu, s2, o);
    }
    int w = threadIdx.x >> 5;
    if ((threadIdx.x & 31) == 0) { b1[w] = s1; b2[w] = s2; }
    __syncthreads();
    s1 = b1[0] + b1[1] + b1[2] + b1[3];
    s2 = b2[0] + b2[1] + b2[2] + b2[3];
}

__global__ void norm_kernel(const float* __restrict__ h0, float* __restrict__ nh)
{
    long long bn = blockIdx.x;
    int t = threadIdx.x; // 128
    const float* r = h0 + bn * HD;
    float v0 = r[t], v1 = r[t + 128], v2 = r[t + 256];
    float ss = v0 * v0 + v1 * v1 + v2 * v2, dummy = 0.f;
    block_reduce2(ss, dummy);
    float rinv = rsqrtf(ss);
    float* o = nh + bn * HD;
    o[t] = v0 * rinv; o[t + 128] = v1 * rinv; o[t + 256] = v2 * rinv;
}

__global__ void topk_kernel(const float* __restrict__ sim, int* __restrict__ knn)
{
    int t = blockIdx.x * blockDim.x + threadIdx.x;
    if (t >= NB * NN) return;
    int n = t & (NN - 1);
    const float* row = sim + (long long)t * NN;
    float vals[KNN];
    int   idxs[KNN];
    #pragma unroll
    for (int j = 0; j < KNN; j++) { vals[j] = -1e30f; idxs[j] = 0; }
    float vmin = -1e30f; int smin = 0;
    for (int m = 0; m < NN; m++) {
        if (m == n) continue;
        float s = row[m];
        if (s > vmin) {
            vals[smin] = s; idxs[smin] = m;
            vmin = vals[0]; smin = 0;
            #pragma unroll
            for (int j = 1; j < KNN; j++)
                if (vals[j] < vmin) { vmin = vals[j]; smin = j; }
        }
    }
    int* o = knn + (long long)t * KNN;
    #pragma unroll
    for (int j = 0; j < KNN; j++) o[j] = idxs[j];
}

// h_local = LN(hcur + (sum_{j in knn} xw[j] + xw[self]) / 17)
__global__ void gcn_agg_ln(const float* __restrict__ hcur, const float* __restrict__ xw,
                           const int* __restrict__ knn,
                           const float* __restrict__ scale, const float* __restrict__ bias,
                           float* __restrict__ out)
{
    int bn = blockIdx.x;
    int b = bn >> 10;
    int t = threadIdx.x; // 128
    __shared__ int sidx[KNN];
    if (t < KNN) sidx[t] = knn[(long long)bn * KNN + t];
    __syncthreads();
    const float* xr = xw + (long long)bn * HD;
    float a0 = xr[t], a1 = xr[t + 128], a2 = xr[t + 256];
    #pragma unroll 4
    for (int j = 0; j < KNN; j++) {
        const float* r = xw + ((long long)(b * NN) + sidx[j]) * HD;
        a0 += r[t]; a1 += r[t + 128]; a2 += r[t + 256];
    }
    const float* h = hcur + (long long)bn * HD;
    const float inv17 = 1.f / 17.f;
    float v0 = h[t] + a0 * inv17;
    float v1 = h[t + 128] + a1 * inv17;
    float v2 = h[t + 256] + a2 * inv17;
    float s1 = v0 + v1 + v2;
    float s2 = v0 * v0 + v1 * v1 + v2 * v2;
    block_reduce2(s1, s2);
    float mu = s1 * (1.f / HD);
    float var = s2 * (1.f / HD) - mu * mu;
    float rstd = rsqrtf(var + 1e-5f);
    float* o = out + (long long)bn * HD;
    o[t]       = (v0 - mu) * rstd * scale[t]       + bias[t];
    o[t + 128] = (v1 - mu) * rstd * scale[t + 128] + bias[t + 128];
    o[t + 256] = (v2 - mu) * rstd * scale[t + 256] + bias[t + 256];
}

// out = (plus? plus : 0) + LN(a + (b? b : 0))
__global__ void add_ln_kernel(const float* __restrict__ a, const float* __restrict__ b,
                              const float* __restrict__ plus,
                              const float* __restrict__ scale, const float* __restrict__ bias,
                              float* __restrict__ out)
{
    long long bn = blockIdx.x;
    int t = threadIdx.x; // 128
    const float* ar = a + bn * HD;
    float v0 = ar[t], v1 = ar[t + 128], v2 = ar[t + 256];
    if (b) {
        const float* br = b + bn * HD;
        v0 += br[t]; v1 += br[t + 128]; v2 += br[t + 256];
    }
    float s1 = v0 + v1 + v2;
    float s2 = v0 * v0 + v1 * v1 + v2 * v2;
    block_reduce2(s1, s2);
    float mu = s1 * (1.f / HD);
    float var = s2 * (1.f / HD) - mu * mu;
    float rstd = rsqrtf(var + 1e-5f);
    float y0 = (v0 - mu) * rstd * scale[t]       + bias[t];
    float y1 = (v1 - mu) * rstd * scale[t + 128] + bias[t + 128];
    float y2 = (v2 - mu) * rstd * scale[t + 256] + bias[t + 256];
    if (plus) {
        const float* pr = plus + bn * HD;
        y0 += pr[t]; y1 += pr[t + 128]; y2 += pr[t + 256];
    }
    float* o = out + bn * HD;
    o[t] = y0; o[t + 128] = y1; o[t + 256] = y2;
}

__global__ void softmax_kernel(float* __restrict__ sc)
{
    long long r = blockIdx.x;
    float* row = sc + r * (long long)NN;
    int t = threadIdx.x; // 256
    float x0 = row[t], x1 = row[t + 256], x2 = row[t + 512], x3 = row[t + 768];
    float m = fmaxf(fmaxf(x0, x1), fmaxf(x2, x3));
    __shared__ float bm[8], bs[8];
    #pragma unroll
    for (int o = 16; o > 0; o >>= 1) m = fmaxf(m, __shfl_down_sync(0xffffffffu, m, o));
    if ((t & 31) == 0) bm[t >> 5] = m;
    __syncthreads();
    float mm = bm[0];
    #pragma unroll
    for (int i = 1; i < 8; i++) mm = fmaxf(mm, bm[i]);
    float e0 = __expf(x0 - mm), e1 = __expf(x1 - mm), e2 = __expf(x2 - mm), e3 = __expf(x3 - mm);
    float s = e0 + e1 + e2 + e3;
    #pragma unroll
    for (int o = 16; o > 0; o >>= 1) s += __shfl_down_sync(0xffffffffu, s, o);
    if ((t & 31) == 0) bs[t >> 5] = s;
    __syncthreads();
    float ssum = bs[0] + bs[1] + bs[2] + bs[3] + bs[4] + bs[5] + bs[6] + bs[7];
    float inv = 1.f / ssum;
    row[t] = e0 * inv; row[t + 256] = e1 * inv; row[t + 512] = e2 * inv; row[t + 768] = e3 * inv;
}

__global__ void pool_kernel(const float* __restrict__ h, float* __restrict__ pooled)
{
    int b = blockIdx.x;
    int t = threadIdx.x; // 384
    float s = 0.f;
    const float* base = h + (long long)b * NN * HD + t;
    for (int n = 0; n < NN; n++) s += base[(long long)n * HD];
    pooled[b * HD + t] = s * (1.f / NN);
}

__global__ void fin1_kernel(const float* __restrict__ pooled, const float* __restrict__ W,
                            const float* __restrict__ bias, float* __restrict__ z)
{
    int b = blockIdx.x;
    int j = threadIdx.x; // 384
    const float* p = pooled + b * HD;
    float s = bias[j];
    for (int k = 0; k < HD; k++) s = fmaf(p[k], W[k * HD + j], s);
    z[b * HD + j] = fmaxf(s, 0.f);
}

__global__ void fin2_kernel(const float* __restrict__ z, const float* __restrict__ W,
                            const float* __restrict__ bias, float* __restrict__ out)
{
    int b = blockIdx.x;
    int j = threadIdx.x; // 128
    const float* p = z + b * HD;
    float s = bias[j];
    for (int k = 0; k < HD; k++) s = fmaf(p[k], W[k * 128 + j], s);
    out[b * 128 + j] = s;
}

// ---------------- host-side GEMM dispatcher ----------------
static void gemm(const float* A, const float* B, const float* bias, const float* Res, float* C,
                 int M, int Nn, int K, int lda, int ldb, int ldc,
                 long long sA, long long sAi, long long sB, long long sBi,
                 long long sC, long long sCi, int zi, int nz,
                 float alpha, bool transb, bool relu)
{
    dim3 grid(Nn / BN, M / BM, nz), block(256);
    if (transb) {
        if (relu) gemm_k<true, true ><<<grid, block>>>(A, B, bias, Res, C, M, Nn, K, lda, ldb, ldc, sA, sAi, sB, sBi, sC, sCi, zi, alpha);
        else      gemm_k<true, false><<<grid, block>>>(A, B, bias, Res, C, M, Nn, K, lda, ldb, ldc, sA, sAi, sB, sBi, sC, sCi, zi, alpha);
    } else {
        if (relu) gemm_k<false, true ><<<grid, block>>>(A, B, bias, Res, C, M, Nn, K, lda, ldb, ldc, sA, sAi, sB, sBi, sC, sCi, zi, alpha);
        else      gemm_k<false, false><<<grid, block>>>(A, B, bias, Res, C, M, Nn, K, lda, ldb, ldc, sA, sAi, sB, sBi, sC, sCi, zi, alpha);
    }
}

template<typename T> static T* sym_addr(const void* sym)
{
    void* p = nullptr;
    cudaGetSymbolAddress(&p, sym);
    return (T*)p;
}

extern "C" void kernel_launch(void* const* d_in, const int* in_sizes, int n_in,
                              void* d_out, int out_size)
{
    const float* x      = (const float*)d_in[0];
    const float* W_enc  = (const float*)d_in[1];
    const float* b_enc  = (const float*)d_in[2];
    const float* gcn_W  = (const float*)d_in[3];
    const float* gcn_b  = (const float*)d_in[4];
    const float* Wq     = (const float*)d_in[5];
    const float* bq     = (const float*)d_in[6];
    const float* Wk     = (const float*)d_in[7];
    const float* bk     = (const float*)d_in[8];
    const float* Wv     = (const float*)d_in[9];
    const float* bv     = (const float*)d_in[10];
    const float* Wo     = (const float*)d_in[11];
    const float* bo     = (const float*)d_in[12];
    const float* lnsc   = (const float*)d_in[13];
    const float* lnbi   = (const float*)d_in[14];
    const float* W1     = (const float*)d_in[15];
    const float* b1     = (const float*)d_in[16];
    const float* W2     = (const float*)d_in[17];
    const float* b2     = (const float*)d_in[18];
    const float* lin1_W = (const float*)d_in[19];
    const float* lin1_b = (const float*)d_in[20];
    const float* lin2_W = (const float*)d_in[21];
    const float* lin2_b = (const float*)d_in[22];
    float* outp = (float*)d_out;

    float* featsp = sym_addr<float>(g_feats);
    float* h0p    = sym_addr<float>(g_h0);
    float* nhp    = sym_addr<float>(g_nh);
    float* simp   = sym_addr<float>(g_sim);
    int*   knnp   = sym_addr<int>(g_knn);
    float* hcurp  = sym_addr<float>(g_hcur);
    float* xwp    = sym_addr<float>(g_xw);
    float* hlocp  = sym_addr<float>(g_hloc);
    float* qp     = sym_addr<float>(g_q);
    float* kp     = sym_addr<float>(g_k);
    float* vp     = sym_addr<float>(g_v);
    float* scp    = sym_addr<float>(g_sc);
    float* aop    = sym_addr<float>(g_ao);
    float* op     = sym_addr<float>(g_o);
    float* combp  = sym_addr<float>(g_comb);
    float* mlp1p  = sym_addr<float>(g_mlp1);
    float* ffp    = sym_addr<float>(g_ff);
    float* poolp  = sym_addr<float>(g_pool);
    float* zp     = sym_addr<float>(g_z);

    const long long NH = (long long)NN * HD;       // per-batch hidden stride
    const long long SS = (long long)NN * NN;       // per-head score stride

    // ---- encoder ----
    feats_kernel<<<(NB * NN * CIN + 255) / 256, 256>>>(x, featsp);
    gemm(featsp, W_enc, b_enc, nullptr, h0p,
         NN, HD, CIN, CIN, HD, HD,
         (long long)NN * CIN, 0, 0, 0, NH, 0, 1, NB, 1.f, false, false);

    // ---- graph build ----
    norm_kernel<<<NB * NN, 128>>>(h0p, nhp);
    gemm(nhp, nhp, nullptr, nullptr, simp,
         NN, NN, HD, HD, HD, NN,
         NH, 0, NH, 0, SS, 0, 1, NB, 1.f, true, false);
    topk_kernel<<<(NB * NN + 255) / 256, 256>>>(simp, knnp);

    const float* hin = h0p;
    for (int l = 0; l < NL; l++) {
        const float* scl = lnsc + (l * 3) * HD;
        const float* bil = lnbi + (l * 3) * HD;

        // local GCN branch
        gemm(hin, gcn_W + (long long)l * HD * HD, gcn_b + l * HD, nullptr, xwp,
             NN, HD, HD, HD, HD, HD, NH, 0, 0, 0, NH, 0, 1, NB, 1.f, false, false);
        gcn_agg_ln<<<NB * NN, 128>>>(hin, xwp, knnp, scl, bil, hlocp);

        // attention branch
        gemm(hin, Wq + (long long)l * HD * HD, bq + l * HD, nullptr, qp,
             NN, HD, HD, HD, HD, HD, NH, 0, 0, 0, NH, 0, 1, NB, 1.f, false, false);
        gemm(hin, Wk + (long long)l * HD * HD, bk + l * HD, nullptr, kp,
             NN, HD, HD, HD, HD, HD, NH, 0, 0, 0, NH, 0, 1, NB, 1.f, false, false);
        gemm(hin, Wv + (long long)l * HD * HD, bv + l * HD, nullptr, vp,
             NN, HD, HD, HD, HD, HD, NH, 0, 0, 0, NH, 0, 1, NB, 1.f, false, false);
        // scores[b,h] = q_h @ k_h^T / sqrt(128)
        gemm(qp, kp, nullptr, nullptr, scp,
             NN, NN, DHE, HD, HD, NN,
             NH, DHE, NH, DHE, (long long)NHE * SS, SS, NHE, NB * NHE,
             0.08838834764831843f, true, false);
        softmax_kernel<<<NB * NHE * NN, 256>>>(scp);
        // attn @ V
        gemm(scp, vp, nullptr, nullptr, aop,
             NN, DHE, NN, NN, HD, HD,
             (long long)NHE * SS, SS, NH, DHE, NH, DHE, NHE, NB * NHE,
             1.f, false, false);
        gemm(aop, Wo + (long long)l * HD * HD, bo + l * HD, nullptr, op,
             NN, HD, HD, HD, HD, HD, NH, 0, 0, 0, NH, 0, 1, NB, 1.f, false, false);
        // comb = h_local + LN(hcur + o)
        add_ln_kernel<<<NB * NN, 128>>>(hin, op, hlocp, scl + HD, bil + HD, combp);

        // FFN
        gemm(combp, W1 + (long long)l * HD * 2 * HD, b1 + l * 2 * HD, nullptr, mlp1p,
             NN, 2 * HD, HD, HD, 2 * HD, 2 * HD,
             NH, 0, 0, 0, (long long)NN * 2 * HD, 0, 1, NB, 1.f, false, true);
        gemm(mlp1p, W2 + (long long)l * 2 * HD * HD, b2 + l * HD, combp, ffp,
             NN, HD, 2 * HD, 2 * HD, HD, HD,
             (long long)NN * 2 * HD, 0, 0, 0, NH, 0, 1, NB, 1.f, false, false);
        add_ln_kernel<<<NB * NN, 128>>>(ffp, nullptr, nullptr, scl + 2 * HD, bil + 2 * HD, hcurp);
        hin = hcurp;
    }

    // ---- head ----
    pool_kernel<<<NB, HD>>>(hin, poolp);
    fin1_kernel<<<NB, HD>>>(poolp, lin1_W, lin1_b, zp);
    fin2_kernel<<<NB, 128>>>(zp, lin2_W, lin2_b, outp);
}

// round 2
// speedup vs baseline: 1.2741x; 1.2741x over previous
#include <cuda_runtime.h>
#include <math.h>

// ---------------- problem constants ----------------
static const int NB   = 8;     // batch
static const int NN   = 1024;  // nodes (32*32)
static const int CIN  = 64;    // input channels
static const int HD   = 384;   // hidden
static const int NL   = 3;     // layers
static const int KNN  = 16;    // k
static const int NHE  = 3;     // heads
static const int DHE  = 128;   // head dim

// ---------------- device scratch (no allocs allowed) ----------------
__device__ float g_feats [NB*NN*CIN];
__device__ float g_h0    [NB*NN*HD];
__device__ float g_nh    [NB*NN*HD];
__device__ float g_sim   [NB*NN*NN];
__device__ int   g_knn   [NB*NN*KNN];
__device__ float g_hcur  [NB*NN*HD];
__device__ float g_xw    [NB*NN*HD];
__device__ float g_hloc  [NB*NN*HD];
__device__ float g_q     [NB*NN*HD];
__device__ float g_k     [NB*NN*HD];
__device__ float g_v     [NB*NN*HD];
__device__ float g_sc    [(long long)NB*NHE*NN*NN];
__device__ float g_ao    [NB*NN*HD];
__device__ float g_o     [NB*NN*HD];
__device__ float g_comb  [NB*NN*HD];
__device__ float g_mlp1  [NB*NN*2*HD];
__device__ float g_ff    [NB*NN*HD];
__device__ float g_pool  [NB*HD];
__device__ float g_z     [NB*HD];

// ---------------- 128x128x8 SGEMM, 8x8/thread, double buffered ----------------
// C[m,n] = alpha * sum_k A[m,k]*B[k,n]  (+bias[n]) (+Res[m,n]) (relu)
// TRANSB: B indexed as B[n,k] (row-major [N,K])
#define BM 128
#define BN 128
#define BKK 8
#define SPAD 132   // padded row to avoid STS bank conflicts

template<bool TRANSB, bool RELU>
__global__ void __launch_bounds__(256, 2)
gemm_k(const float* __restrict__ A, const float* __restrict__ B,
       const float* __restrict__ bias, const float* __restrict__ Res,
       float* __restrict__ C,
       int M, int Nn, int K, int lda, int ldb, int ldc,
       long long sA, long long sAi, long long sB, long long sBi,
       long long sC, long long sCi, int zi, float alpha)
{
    int bz = blockIdx.z;
    int zo = bz / zi, zin = bz % zi;
    A += zo * sA + zin * sAi;
    B += zo * sB + zin * sBi;
    C += zo * sC + zin * sCi;
    if (Res) Res += zo * sC + zin * sCi;

    int m0 = blockIdx.y * BM;
    int n0 = blockIdx.x * BN;

    __shared__ float As[2][BKK][SPAD];
    __shared__ float Bs[2][BKK][SPAD];

    int tid = threadIdx.x;
    int tx = tid & 15;         // 16 col groups
    int ty = tid >> 4;         // 16 row groups

    // load maps (each thread loads one float4 of A and one of B per K-step)
    int a_m = tid >> 1;
    int a_k = (tid & 1) * 4;
    const float* Aload = A + (long long)(m0 + a_m) * lda + a_k;

    const float* Bload;
    int b_k = 0, b_n = 0;
    if (TRANSB) {
        // B[n,k]: same map as A
        Bload = B + (long long)(n0 + a_m) * ldb + a_k;
    } else {
        b_k = tid >> 5;            // 0..7
        b_n = (tid & 31) * 4;      // 0..124
        Bload = B + (long long)b_k * ldb + n0 + b_n;
    }

    // initial tile -> buffer 0
    float4 av = *(const float4*)Aload;
    float4 bv = *(const float4*)Bload;

    As[0][a_k + 0][a_m] = av.x;
    As[0][a_k + 1][a_m] = av.y;
    As[0][a_k + 2][a_m] = av.z;
    As[0][a_k + 3][a_m] = av.w;
    if (TRANSB) {
        Bs[0][a_k + 0][a_m] = bv.x;
        Bs[0][a_k + 1][a_m] = bv.y;
        Bs[0][a_k + 2][a_m] = bv.z;
        Bs[0][a_k + 3][a_m] = bv.w;
    } else {
        *(float4*)&Bs[0][b_k][b_n] = bv;
    }
    __syncthreads();

    float acc[8][8];
    #pragma unroll
    for (int i = 0; i < 8; i++)
        #pragma unroll
        for (int j = 0; j < 8; j++) acc[i][j] = 0.f;

    int cur = 0;
    for (int k0 = 0; ; ) {
        int k1 = k0 + BKK;
        bool more = (k1 < K);
        if (more) {
            av = *(const float4*)(Aload + k1 * (TRANSB ? 1 : 1) + 0 + (long long)0 + k1 - k1 + k1); // placeholder avoided below
        }
        // (real prefetch, written plainly)
        if (more) {
            av = *(const float4*)(Aload + k1);
            if (TRANSB) bv = *(const float4*)(Bload + k1);
            else        bv = *(const float4*)(Bload + (long long)k1 * ldb);
        }

        #pragma unroll
        for (int kk = 0; kk < BKK; kk++) {
            float4 a0 = *(const float4*)&As[cur][kk][ty * 4];
            float4 a1 = *(const float4*)&As[cur][kk][64 + ty * 4];
            float4 b0 = *(const float4*)&Bs[cur][kk][tx * 4];
            float4 b1 = *(const float4*)&Bs[cur][kk][64 + tx * 4];
            float a[8] = {a0.x, a0.y, a0.z, a0.w, a1.x, a1.y, a1.z, a1.w};
            float b[8] = {b0.x, b0.y, b0.z, b0.w, b1.x, b1.y, b1.z, b1.w};
            #pragma unroll
            for (int i = 0; i < 8; i++)
                #pragma unroll
                for (int j = 0; j < 8; j++)
                    acc[i][j] = fmaf(a[i], b[j], acc[i][j]);
        }
        if (!more) break;

        int nxt = cur ^ 1;
        As[nxt][a_k + 0][a_m] = av.x;
        As[nxt][a_k + 1][a_m] = av.y;
        As[nxt][a_k + 2][a_m] = av.z;
        As[nxt][a_k + 3][a_m] = av.w;
        if (TRANSB) {
            Bs[nxt][a_k + 0][a_m] = bv.x;
            Bs[nxt][a_k + 1][a_m] = bv.y;
            Bs[nxt][a_k + 2][a_m] = bv.z;
            Bs[nxt][a_k + 3][a_m] = bv.w;
        } else {
            *(float4*)&Bs[nxt][b_k][b_n] = bv;
        }
        __syncthreads();
        cur = nxt;
        k0 = k1;
    }

    // epilogue: rows {ty*4+i, 64+ty*4+i}, cols {tx*4+j, 64+tx*4+j}
    #pragma unroll
    for (int ih = 0; ih < 2; ih++) {
        #pragma unroll
        for (int i = 0; i < 4; i++) {
            int m = m0 + ih * 64 + ty * 4 + i;
            #pragma unroll
            for (int jh = 0; jh < 2; jh++) {
                int n = n0 + jh * 64 + tx * 4;
                float4 r;
                r.x = acc[ih * 4 + i][jh * 4 + 0] * alpha;
                r.y = acc[ih * 4 + i][jh * 4 + 1] * alpha;
                r.z = acc[ih * 4 + i][jh * 4 + 2] * alpha;
                r.w = acc[ih * 4 + i][jh * 4 + 3] * alpha;
                if (bias) {
                    float4 bb = *(const float4*)(bias + n);
                    r.x += bb.x; r.y += bb.y; r.z += bb.z; r.w += bb.w;
                }
                if (Res) {
                    float4 rr = *(const float4*)(Res + (long long)m * ldc + n);
                    r.x += rr.x; r.y += rr.y; r.z += rr.z; r.w += rr.w;
                }
                if (RELU) {
                    r.x = fmaxf(r.x, 0.f); r.y = fmaxf(r.y, 0.f);
                    r.z = fmaxf(r.z, 0.f); r.w = fmaxf(r.w, 0.f);
                }
                *(float4*)(C + (long long)m * ldc + n) = r;
            }
        }
    }
}

// ---------------- small kernels ----------------
__global__ void feats_kernel(const float* __restrict__ x, float* __restrict__ feats)
{
    long long i = (long long)blockIdx.x * blockDim.x + threadIdx.x;
    if (i >= (long long)NB * NN * CIN) return;
    int c = (int)(i & (CIN - 1));
    long long bn = i >> 6;
    int n = (int)(bn & (NN - 1));
    int b = (int)(bn >> 10);
    feats[i] = x[((long long)b * CIN + c) * NN + n];
}

// 128-thread two-value block reduce
__device__ __forceinline__ void block_reduce2(float& s1, float& s2)
{
    __shared__ float b1[4], b2[4];
    #pragma unroll
    for (int o = 16; o > 0; o >>= 1) {
        s1 += __shfl_down_sync(0xffffffffu, s1, o);
        s2 += __shfl_down_sync(0xffffffffu, s2, o);
    }
    int w = threadIdx.x >> 5;
    if ((threadIdx.x & 31) == 0) { b1[w] = s1; b2[w] = s2; }
    __syncthreads();
    s1 = b1[0] + b1[1] + b1[2] + b1[3];
    s2 = b2[0] + b2[1] + b2[2] + b2[3];
}

__global__ void norm_kernel(const float* __restrict__ h0, float* __restrict__ nh)
{
    long long bn = blockIdx.x;
    int t = threadIdx.x; // 128
    const float* r = h0 + bn * HD;
    float v0 = r[t], v1 = r[t + 128], v2 = r[t + 256];
    float ss = v0 * v0 + v1 * v1 + v2 * v2, dummy = 0.f;
    block_reduce2(ss, dummy);
    float rinv = rsqrtf(ss);
    float* o = nh + bn * HD;
    o[t] = v0 * rinv; o[t + 128] = v1 * rinv; o[t + 256] = v2 * rinv;
}

// one warp per row; each lane holds 32 candidates in registers;
// 16 rounds of warp-argmax (lowest index on ties, matching lax.top_k)
__global__ void topk_warp_kernel(const float* __restrict__ sim, int* __restrict__ knn)
{
    int warp = blockIdx.x * (blockDim.x >> 5) + (threadIdx.x >> 5);
    if (warp >= NB * NN) return;
    int lane = threadIdx.x & 31;
    int n = warp & (NN - 1);
    const float* row = sim + (long long)warp * NN;
    float v[32];
    #pragma unroll
    for (int j = 0; j < 32; j++) {
        int m = j * 32 + lane;
        v[j] = (m == n) ? -3e38f : row[m];
    }
    unsigned taken = 0;
    int* o = knn + (long long)warp * KNN;
    for (int r = 0; r < KNN; r++) {
        float bv = -3e38f; int bj = 0;
        #pragma unroll
        for (int j = 0; j < 32; j++) {
            bool free_ = !((taken >> j) & 1u);
            if (free_ && v[j] > bv) { bv = v[j]; bj = j; }
        }
        int bidx = bj * 32 + lane;
        #pragma unroll
        for (int off = 16; off > 0; off >>= 1) {
            float ov = __shfl_xor_sync(0xffffffffu, bv, off);
            int   oi = __shfl_xor_sync(0xffffffffu, bidx, off);
            if (ov > bv || (ov == bv && oi < bidx)) { bv = ov; bidx = oi; }
        }
        if ((bidx & 31) == lane) taken |= 1u << (bidx >> 5);
        if (lane == 0) o[r] = bidx;
    }
}

// h_local = LN(hcur + (sum_{j in knn} xw[j] + xw[self]) / 17)
__global__ void gcn_agg_ln(const float* __restrict__ hcur, const float* __restrict__ xw,
                           const int* __restrict__ knn,
                           const float* __restrict__ scale, const float* __restrict__ bias,
                           float* __restrict__ out)
{
    int bn = blockIdx.x;
    int b = bn >> 10;
    int t = threadIdx.x; // 128
    __shared__ int sidx[KNN];
    if (t < KNN) sidx[t] = knn[(long long)bn * KNN + t];
    __syncthreads();
    const float* xr = xw + (long long)bn * HD;
    float a0 = xr[t], a1 = xr[t + 128], a2 = xr[t + 256];
    #pragma unroll 4
    for (int j = 0; j < KNN; j++) {
        const float* r = xw + ((long long)(b * NN) + sidx[j]) * HD;
        a0 += r[t]; a1 += r[t + 128]; a2 += r[t + 256];
    }
    const float* h = hcur + (long long)bn * HD;
    const float inv17 = 1.f / 17.f;
    float v0 = h[t] + a0 * inv17;
    float v1 = h[t + 128] + a1 * inv17;
    float v2 = h[t + 256] + a2 * inv17;
    float s1 = v0 + v1 + v2;
    float s2 = v0 * v0 + v1 * v1 + v2 * v2;
    block_reduce2(s1, s2);
    float mu = s1 * (1.f / HD);
    float var = s2 * (1.f / HD) - mu * mu;
    float rstd = rsqrtf(var + 1e-5f);
    float* o = out + (long long)bn * HD;
    o[t]       = (v0 - mu) * rstd * scale[t]       + bias[t];
    o[t + 128] = (v1 - mu) * rstd * scale[t + 128] + bias[t + 128];
    o[t + 256] = (v2 - mu) * rstd * scale[t + 256] + bias[t + 256];
}

// out = (plus? plus : 0) + LN(a + (b? b : 0))
__global__ void add_ln_kernel(const float* __restrict__ a, const float* __restrict__ b,
                              const float* __restrict__ plus,
                              const float* __restrict__ scale, const float* __restrict__ bias,
                              float* __restrict__ out)
{
    long long bn = blockIdx.x;
    int t = threadIdx.x; // 128
    const float* ar = a + bn * HD;
    float v0 = ar[t], v1 = ar[t + 128], v2 = ar[t + 256];
    if (b) {
        const float* br = b + bn * HD;
        v0 += br[t]; v1 += br[t + 128]; v2 += br[t + 256];
    }
    float s1 = v0 + v1 + v2;
    float s2 = v0 * v0 + v1 * v1 + v2 * v2;
    block_reduce2(s1, s2);
    float mu = s1 * (1.f / HD);
    float var = s2 * (1.f / HD) - mu * mu;
    float rstd = rsqrtf(var + 1e-5f);
    float y0 = (v0 - mu) * rstd * scale[t]       + bias[t];
    float y1 = (v1 - mu) * rstd * scale[t + 128] + bias[t + 128];
    float y2 = (v2 - mu) * rstd * scale[t + 256] + bias[t + 256];
    if (plus) {
        const float* pr = plus + bn * HD;
        y0 += pr[t]; y1 += pr[t + 128]; y2 += pr[t + 256];
    }
    float* o = out + bn * HD;
    o[t] = y0; o[t + 128] = y1; o[t + 256] = y2;
}

__global__ void softmax_kernel(float* __restrict__ sc)
{
    long long r = blockIdx.x;
    float* row = sc + r * (long long)NN;
    int t = threadIdx.x; // 256
    float x0 = row[t], x1 = row[t + 256], x2 = row[t + 512], x3 = row[t + 768];
    float m = fmaxf(fmaxf(x0, x1), fmaxf(x2, x3));
    __shared__ float bm[8], bs[8];
    #pragma unroll
    for (int o = 16; o > 0; o >>= 1) m = fmaxf(m, __shfl_down_sync(0xffffffffu, m, o));
    if ((t & 31) == 0) bm[t >> 5] = m;
    __syncthreads();
    float mm = bm[0];
    #pragma unroll
    for (int i = 1; i < 8; i++) mm = fmaxf(mm, bm[i]);
    float e0 = __expf(x0 - mm), e1 = __expf(x1 - mm), e2 = __expf(x2 - mm), e3 = __expf(x3 - mm);
    float s = e0 + e1 + e2 + e3;
    #pragma unroll
    for (int o = 16; o > 0; o >>= 1) s += __shfl_down_sync(0xffffffffu, s, o);
    if ((t & 31) == 0) bs[t >> 5] = s;
    __syncthreads();
    float ssum = bs[0] + bs[1] + bs[2] + bs[3] + bs[4] + bs[5] + bs[6] + bs[7];
    float inv = 1.f / ssum;
    row[t] = e0 * inv; row[t + 256] = e1 * inv; row[t + 512] = e2 * inv; row[t + 768] = e3 * inv;
}

__global__ void pool_kernel(const float* __restrict__ h, float* __restrict__ pooled)
{
    int b = blockIdx.x;
    int t = threadIdx.x; // 384
    float s = 0.f;
    const float* base = h + (long long)b * NN * HD + t;
    for (int n = 0; n < NN; n++) s += base[(long long)n * HD];
    pooled[b * HD + t] = s * (1.f / NN);
}

__global__ void fin1_kernel(const float* __restrict__ pooled, const float* __restrict__ W,
                            const float* __restrict__ bias, float* __restrict__ z)
{
    int b = blockIdx.x;
    int j = threadIdx.x; // 384
    const float* p = pooled + b * HD;
    float s = bias[j];
    for (int k = 0; k < HD; k++) s = fmaf(p[k], W[k * HD + j], s);
    z[b * HD + j] = fmaxf(s, 0.f);
}

__global__ void fin2_kernel(const float* __restrict__ z, const float* __restrict__ W,
                            const float* __restrict__ bias, float* __restrict__ out)
{
    int b = blockIdx.x;
    int j = threadIdx.x; // 128
    const float* p = z + b * HD;
    float s = bias[j];
    for (int k = 0; k < HD; k++) s = fmaf(p[k], W[k * 128 + j], s);
    out[b * 128 + j] = s;
}

// ---------------- host-side GEMM dispatcher ----------------
static void gemm(const float* A, const float* B, const float* bias, const float* Res, float* C,
                 int M, int Nn, int K, int lda, int ldb, int ldc,
                 long long sA, long long sAi, long long sB, long long sBi,
                 long long sC, long long sCi, int zi, int nz,
                 float alpha, bool transb, bool relu)
{
    dim3 grid(Nn / BN, M / BM, nz), block(256);
    if (transb) {
        if (relu) gemm_k<true, true ><<<grid, block>>>(A, B, bias, Res, C, M, Nn, K, lda, ldb, ldc, sA, sAi, sB, sBi, sC, sCi, zi, alpha);
        else      gemm_k<true, false><<<grid, block>>>(A, B, bias, Res, C, M, Nn, K, lda, ldb, ldc, sA, sAi, sB, sBi, sC, sCi, zi, alpha);
    } else {
        if (relu) gemm_k<false, true ><<<grid, block>>>(A, B, bias, Res, C, M, Nn, K, lda, ldb, ldc, sA, sAi, sB, sBi, sC, sCi, zi, alpha);
        else      gemm_k<false, false><<<grid, block>>>(A, B, bias, Res, C, M, Nn, K, lda, ldb, ldc, sA, sAi, sB, sBi, sC, sCi, zi, alpha);
    }
}

template<typename T> static T* sym_addr(const void* sym)
{
    void* p = nullptr;
    cudaGetSymbolAddress(&p, sym);
    return (T*)p;
}

extern "C" void kernel_launch(void* const* d_in, const int* in_sizes, int n_in,
                              void* d_out, int out_size)
{
    const float* x      = (const float*)d_in[0];
    const float* W_enc  = (const float*)d_in[1];
    const float* b_enc  = (const float*)d_in[2];
    const float* gcn_W  = (const float*)d_in[3];
    const float* gcn_b  = (const float*)d_in[4];
    const float* Wq     = (const float*)d_in[5];
    const float* bq     = (const float*)d_in[6];
    const float* Wk     = (const float*)d_in[7];
    const float* bk     = (const float*)d_in[8];
    const float* Wv     = (const float*)d_in[9];
    const float* bv     = (const float*)d_in[10];
    const float* Wo     = (const float*)d_in[11];
    const float* bo     = (const float*)d_in[12];
    const float* lnsc   = (const float*)d_in[13];
    const float* lnbi   = (const float*)d_in[14];
    const float* W1     = (const float*)d_in[15];
    const float* b1     = (const float*)d_in[16];
    const float* W2     = (const float*)d_in[17];
    const float* b2     = (const float*)d_in[18];
    const float* lin1_W = (const float*)d_in[19];
    const float* lin1_b = (const float*)d_in[20];
    const float* lin2_W = (const float*)d_in[21];
    const float* lin2_b = (const float*)d_in[22];
    float* outp = (float*)d_out;

    float* featsp = sym_addr<float>(g_feats);
    float* h0p    = sym_addr<float>(g_h0);
    float* nhp    = sym_addr<float>(g_nh);
    float* simp   = sym_addr<float>(g_sim);
    int*   knnp   = sym_addr<int>(g_knn);
    float* hcurp  = sym_addr<float>(g_hcur);
    float* xwp    = sym_addr<float>(g_xw);
    float* hlocp  = sym_addr<float>(g_hloc);
    float* qp     = sym_addr<float>(g_q);
    float* kp     = sym_addr<float>(g_k);
    float* vp     = sym_addr<float>(g_v);
    float* scp    = sym_addr<float>(g_sc);
    float* aop    = sym_addr<float>(g_ao);
    float* op     = sym_addr<float>(g_o);
    float* combp  = sym_addr<float>(g_comb);
    float* mlp1p  = sym_addr<float>(g_mlp1);
    float* ffp    = sym_addr<float>(g_ff);
    float* poolp  = sym_addr<float>(g_pool);
    float* zp     = sym_addr<float>(g_z);

    const long long NH = (long long)NN * HD;       // per-batch hidden stride
    const long long SS = (long long)NN * NN;       // per-head score stride

    // ---- encoder ----
    feats_kernel<<<(NB * NN * CIN + 255) / 256, 256>>>(x, featsp);
    gemm(featsp, W_enc, b_enc, nullptr, h0p,
         NN, HD, CIN, CIN, HD, HD,
         (long long)NN * CIN, 0, 0, 0, NH, 0, 1, NB, 1.f, false, false);

    // ---- graph build ----
    norm_kernel<<<NB * NN, 128>>>(h0p, nhp);
    gemm(nhp, nhp, nullptr, nullptr, simp,
         NN, NN, HD, HD, HD, NN,
         NH, 0, NH, 0, SS, 0, 1, NB, 1.f, true, false);
    topk_warp_kernel<<<NB * NN / 8, 256>>>(simp, knnp);

    const float* hin = h0p;
    for (int l = 0; l < NL; l++) {
        const float* scl = lnsc + (l * 3) * HD;
        const float* bil = lnbi + (l * 3) * HD;

        // local GCN branch
        gemm(hin, gcn_W + (long long)l * HD * HD, gcn_b + l * HD, nullptr, xwp,
             NN, HD, HD, HD, HD, HD, NH, 0, 0, 0, NH, 0, 1, NB, 1.f, false, false);
        gcn_agg_ln<<<NB * NN, 128>>>(hin, xwp, knnp, scl, bil, hlocp);

        // attention branch
        gemm(hin, Wq + (long long)l * HD * HD, bq + l * HD, nullptr, qp,
             NN, HD, HD, HD, HD, HD, NH, 0, 0, 0, NH, 0, 1, NB, 1.f, false, false);
        gemm(hin, Wk + (long long)l * HD * HD, bk + l * HD, nullptr, kp,
             NN, HD, HD, HD, HD, HD, NH, 0, 0, 0, NH, 0, 1, NB, 1.f, false, false);
        gemm(hin, Wv + (long long)l * HD * HD, bv + l * HD, nullptr, vp,
             NN, HD, HD, HD, HD, HD, NH, 0, 0, 0, NH, 0, 1, NB, 1.f, false, false);
        // scores[b,h] = q_h @ k_h^T / sqrt(128)
        gemm(qp, kp, nullptr, nullptr, scp,
             NN, NN, DHE, HD, HD, NN,
             NH, DHE, NH, DHE, (long long)NHE * SS, SS, NHE, NB * NHE,
             0.08838834764831843f, true, false);
        softmax_kernel<<<NB * NHE * NN, 256>>>(scp);
        // attn @ V
        gemm(scp, vp, nullptr, nullptr, aop,
             NN, DHE, NN, NN, HD, HD,
             (long long)NHE * SS, SS, NH, DHE, NH, DHE, NHE, NB * NHE,
             1.f, false, false);
        gemm(aop, Wo + (long long)l * HD * HD, bo + l * HD, nullptr, op,
             NN, HD, HD, HD, HD, HD, NH, 0, 0, 0, NH, 0, 1, NB, 1.f, false, false);
        // comb = h_local + LN(hcur + o)
        add_ln_kernel<<<NB * NN, 128>>>(hin, op, hlocp, scl + HD, bil + HD, combp);

        // FFN
        gemm(combp, W1 + (long long)l * HD * 2 * HD, b1 + l * 2 * HD, nullptr, mlp1p,
             NN, 2 * HD, HD, HD, 2 * HD, 2 * HD,
             NH, 0, 0, 0, (long long)NN * 2 * HD, 0, 1, NB, 1.f, false, true);
        gemm(mlp1p, W2 + (long long)l * 2 * HD * HD, b2 + l * HD, combp, ffp,
             NN, HD, 2 * HD, 2 * HD, HD, HD,
             (long long)NN * 2 * HD, 0, 0, 0, NH, 0, 1, NB, 1.f, false, false);
        add_ln_kernel<<<NB * NN, 128>>>(ffp, nullptr, nullptr, scl + 2 * HD, bil + 2 * HD, hcurp);
        hin = hcurp;
    }

    // ---- head ----
    pool_kernel<<<NB, HD>>>(hin, poolp);
    fin1_kernel<<<NB, HD>>>(poolp, lin1_W, lin1_b, zp);
    fin2_kernel<<<NB, 128>>>(zp, lin2_W, lin2_b, outp);
}

// round 3
// speedup vs baseline: 2.2316x; 1.7516x over previous
#include <cuda_runtime.h>
#include <math.h>
#include <stdint.h>

// ---------------- problem constants ----------------
static const int NB   = 8;     // batch
static const int NN   = 1024;  // nodes (32*32)
static const int CIN  = 64;    // input channels
static const int HD   = 384;   // hidden
static const int NL   = 3;     // layers
static const int KNN  = 16;    // k
static const int NHE  = 3;     // heads
static const int DHE  = 128;   // head dim

// ---------------- device scratch (no allocs allowed) ----------------
__device__ float g_feats [NB*NN*CIN];
__device__ float g_h0    [NB*NN*HD];
__device__ float g_nh    [NB*NN*HD];
__device__ float g_sim   [NB*NN*NN];
__device__ int   g_knn   [NB*NN*KNN];
__device__ float g_hcur  [NB*NN*HD];
__device__ float g_xw    [NB*NN*HD];
__device__ float g_hloc  [NB*NN*HD];
__device__ float g_q     [NB*NN*HD];
__device__ float g_k     [NB*NN*HD];
__device__ float g_v     [NB*NN*HD];
__device__ float g_sc    [(long long)NB*NHE*NN*NN];
__device__ float g_ao    [NB*NN*HD];
__device__ float g_o     [NB*NN*HD];
__device__ float g_comb  [NB*NN*HD];
__device__ float g_mlp1  [NB*NN*2*HD];
__device__ float g_ff    [NB*NN*HD];
__device__ float g_pool  [NB*HD];
__device__ float g_z     [NB*HD];

// ================= fp32 SIMT GEMM (exact path: encoder + cosine-sim) =======
#define BM 128
#define BN 128
#define BKK 8
#define SPAD 132

template<bool TRANSB, bool RELU>
__global__ void __launch_bounds__(256, 2)
gemm_k(const float* __restrict__ A, const float* __restrict__ B,
       const float* __restrict__ bias, const float* __restrict__ Res,
       float* __restrict__ C,
       int M, int Nn, int K, int lda, int ldb, int ldc,
       long long sA, long long sAi, long long sB, long long sBi,
       long long sC, long long sCi, int zi, float alpha)
{
    int bz = blockIdx.z;
    int zo = bz / zi, zin = bz % zi;
    A += zo * sA + zin * sAi;
    B += zo * sB + zin * sBi;
    C += zo * sC + zin * sCi;
    if (Res) Res += zo * sC + zin * sCi;

    int m0 = blockIdx.y * BM;
    int n0 = blockIdx.x * BN;

    __shared__ float As[2][BKK][SPAD];
    __shared__ float Bs[2][BKK][SPAD];

    int tid = threadIdx.x;
    int tx = tid & 15;
    int ty = tid >> 4;

    int a_m = tid >> 1;
    int a_k = (tid & 1) * 4;
    const float* Aload = A + (long long)(m0 + a_m) * lda + a_k;

    const float* Bload;
    int b_k = 0, b_n = 0;
    if (TRANSB) {
        Bload = B + (long long)(n0 + a_m) * ldb + a_k;
    } else {
        b_k = tid >> 5;
        b_n = (tid & 31) * 4;
        Bload = B + (long long)b_k * ldb + n0 + b_n;
    }

    float4 av = *(const float4*)Aload;
    float4 bv = *(const float4*)Bload;

    As[0][a_k + 0][a_m] = av.x;
    As[0][a_k + 1][a_m] = av.y;
    As[0][a_k + 2][a_m] = av.z;
    As[0][a_k + 3][a_m] = av.w;
    if (TRANSB) {
        Bs[0][a_k + 0][a_m] = bv.x;
        Bs[0][a_k + 1][a_m] = bv.y;
        Bs[0][a_k + 2][a_m] = bv.z;
        Bs[0][a_k + 3][a_m] = bv.w;
    } else {
        *(float4*)&Bs[0][b_k][b_n] = bv;
    }
    __syncthreads();

    float acc[8][8];
    #pragma unroll
    for (int i = 0; i < 8; i++)
        #pragma unroll
        for (int j = 0; j < 8; j++) acc[i][j] = 0.f;

    int cur = 0;
    for (int k0 = 0; ; ) {
        int k1 = k0 + BKK;
        bool more = (k1 < K);
        if (more) {
            av = *(const float4*)(Aload + k1);
            if (TRANSB) bv = *(const float4*)(Bload + k1);
            else        bv = *(const float4*)(Bload + (long long)k1 * ldb);
        }

        #pragma unroll
        for (int kk = 0; kk < BKK; kk++) {
            float4 a0 = *(const float4*)&As[cur][kk][ty * 4];
            float4 a1 = *(const float4*)&As[cur][kk][64 + ty * 4];
            float4 b0 = *(const float4*)&Bs[cur][kk][tx * 4];
            float4 b1 = *(const float4*)&Bs[cur][kk][64 + tx * 4];
            float a[8] = {a0.x, a0.y, a0.z, a0.w, a1.x, a1.y, a1.z, a1.w};
            float b[8] = {b0.x, b0.y, b0.z, b0.w, b1.x, b1.y, b1.z, b1.w};
            #pragma unroll
            for (int i = 0; i < 8; i++)
                #pragma unroll
                for (int j = 0; j < 8; j++)
                    acc[i][j] = fmaf(a[i], b[j], acc[i][j]);
        }
        if (!more) break;

        int nxt = cur ^ 1;
        As[nxt][a_k + 0][a_m] = av.x;
        As[nxt][a_k + 1][a_m] = av.y;
        As[nxt][a_k + 2][a_m] = av.z;
        As[nxt][a_k + 3][a_m] = av.w;
        if (TRANSB) {
            Bs[nxt][a_k + 0][a_m] = bv.x;
            Bs[nxt][a_k + 1][a_m] = bv.y;
            Bs[nxt][a_k + 2][a_m] = bv.z;
            Bs[nxt][a_k + 3][a_m] = bv.w;
        } else {
            *(float4*)&Bs[nxt][b_k][b_n] = bv;
        }
        __syncthreads();
        cur = nxt;
        k0 = k1;
    }

    #pragma unroll
    for (int ih = 0; ih < 2; ih++) {
        #pragma unroll
        for (int i = 0; i < 4; i++) {
            int m = m0 + ih * 64 + ty * 4 + i;
            #pragma unroll
            for (int jh = 0; jh < 2; jh++) {
                int n = n0 + jh * 64 + tx * 4;
                float4 r;
                r.x = acc[ih * 4 + i][jh * 4 + 0] * alpha;
                r.y = acc[ih * 4 + i][jh * 4 + 1] * alpha;
                r.z = acc[ih * 4 + i][jh * 4 + 2] * alpha;
                r.w = acc[ih * 4 + i][jh * 4 + 3] * alpha;
                if (bias) {
                    float4 bb = *(const float4*)(bias + n);
                    r.x += bb.x; r.y += bb.y; r.z += bb.z; r.w += bb.w;
                }
                if (Res) {
                    float4 rr = *(const float4*)(Res + (long long)m * ldc + n);
                    r.x += rr.x; r.y += rr.y; r.z += rr.z; r.w += rr.w;
                }
                if (RELU) {
                    r.x = fmaxf(r.x, 0.f); r.y = fmaxf(r.y, 0.f);
                    r.z = fmaxf(r.z, 0.f); r.w = fmaxf(r.w, 0.f);
                }
                *(float4*)(C + (long long)m * ldc + n) = r;
            }
        }
    }
}

// ================= tf32 tensor-core GEMM ====================================
// 128x128 block tile, BK=16, 8 warps (4m x 2n), warp tile 32x64,
// mma.sync.m16n8k8 tf32, double-buffered smem, +8 padding (conflict-free frags)
#define TBK 16
#define ASTR 136
#define BSTR 136

__device__ __forceinline__ uint32_t f2tf(float x)
{
    uint32_t r;
    asm("cvt.rna.tf32.f32 %0, %1;" : "=r"(r) : "f"(x));
    return r;
}

template<bool TRANSB, bool RELU>
__global__ void __launch_bounds__(256, 2)
tf32gemm_k(const float* __restrict__ A, const float* __restrict__ B,
           const float* __restrict__ bias, const float* __restrict__ Res,
           float* __restrict__ C,
           int K, int lda, int ldb, int ldc,
           long long sA, long long sAi, long long sB, long long sBi,
           long long sC, long long sCi, int zi, float alpha)
{
    int bz = blockIdx.z;
    int zo = bz / zi, zin = bz % zi;
    A += zo * sA + zin * sAi;
    B += zo * sB + zin * sBi;
    C += zo * sC + zin * sCi;
    if (Res) Res += zo * sC + zin * sCi;

    int m0 = blockIdx.y * 128;
    int n0 = blockIdx.x * 128;

    __shared__ uint32_t As[2][TBK][ASTR];
    __shared__ uint32_t Bs[2][TBK][BSTR];

    int tid = threadIdx.x;
    int lane = tid & 31;
    int wid = tid >> 5;
    int wm = (wid & 3) * 32;
    int wn = (wid >> 2) * 64;
    int tig = lane & 3;     // thread-in-group (k / 2n index)
    int grp = lane >> 2;    // group id (m / n index)

    // global load maps
    int a_m = tid >> 1;             // 0..127
    int a_k = (tid & 1) * 4;        // 0 or 4 (also +8)
    const float* Aload = A + (long long)(m0 + a_m) * lda + a_k;

    const float* Bload;
    int b_k = 0, b_n = 0;
    if (TRANSB) {
        Bload = B + (long long)(n0 + a_m) * ldb + a_k;   // B[n,k]
    } else {
        b_k = tid >> 5;                                  // 0..7 (also +8)
        b_n = (tid & 31) * 4;
        Bload = B + (long long)b_k * ldb + n0 + b_n;
    }

    float4 pa0, pa1, pb0, pb1;

    // ---- stage 0 load ----
    pa0 = *(const float4*)(Aload);
    pa1 = *(const float4*)(Aload + 8);
    if (TRANSB) {
        pb0 = *(const float4*)(Bload);
        pb1 = *(const float4*)(Bload + 8);
    } else {
        pb0 = *(const float4*)(Bload);
        pb1 = *(const float4*)(Bload + (long long)8 * ldb);
    }

    As[0][a_k + 0][a_m] = f2tf(pa0.x);
    As[0][a_k + 1][a_m] = f2tf(pa0.y);
    As[0][a_k + 2][a_m] = f2tf(pa0.z);
    As[0][a_k + 3][a_m] = f2tf(pa0.w);
    As[0][a_k + 8][a_m] = f2tf(pa1.x);
    As[0][a_k + 9][a_m] = f2tf(pa1.y);
    As[0][a_k +10][a_m] = f2tf(pa1.z);
    As[0][a_k +11][a_m] = f2tf(pa1.w);
    if (TRANSB) {
        Bs[0][a_k + 0][a_m] = f2tf(pb0.x);
        Bs[0][a_k + 1][a_m] = f2tf(pb0.y);
        Bs[0][a_k + 2][a_m] = f2tf(pb0.z);
        Bs[0][a_k + 3][a_m] = f2tf(pb0.w);
        Bs[0][a_k + 8][a_m] = f2tf(pb1.x);
        Bs[0][a_k + 9][a_m] = f2tf(pb1.y);
        Bs[0][a_k +10][a_m] = f2tf(pb1.z);
        Bs[0][a_k +11][a_m] = f2tf(pb1.w);
    } else {
        uint4 u0 = { f2tf(pb0.x), f2tf(pb0.y), f2tf(pb0.z), f2tf(pb0.w) };
        uint4 u1 = { f2tf(pb1.x), f2tf(pb1.y), f2tf(pb1.z), f2tf(pb1.w) };
        *(uint4*)&Bs[0][b_k    ][b_n] = u0;
        *(uint4*)&Bs[0][b_k + 8][b_n] = u1;
    }
    __syncthreads();

    float acc[2][8][4];
    #pragma unroll
    for (int mt = 0; mt < 2; mt++)
        #pragma unroll
        for (int nt = 0; nt < 8; nt++)
            #pragma unroll
            for (int r = 0; r < 4; r++) acc[mt][nt][r] = 0.f;

    int cur = 0;
    for (int k0 = 0; ; ) {
        int k1 = k0 + TBK;
        bool more = (k1 < K);
        if (more) {
            pa0 = *(const float4*)(Aload + k1);
            pa1 = *(const float4*)(Aload + k1 + 8);
            if (TRANSB) {
                pb0 = *(const float4*)(Bload + k1);
                pb1 = *(const float4*)(Bload + k1 + 8);
            } else {
                pb0 = *(const float4*)(Bload + (long long)k1 * ldb);
                pb1 = *(const float4*)(Bload + (long long)(k1 + 8) * ldb);
            }
        }

        #pragma unroll
        for (int ks = 0; ks < TBK; ks += 8) {
            uint32_t af[2][4], bf[8][2];
            #pragma unroll
            for (int mt = 0; mt < 2; mt++) {
                af[mt][0] = As[cur][ks + tig    ][wm + mt * 16 + grp];
                af[mt][1] = As[cur][ks + tig    ][wm + mt * 16 + grp + 8];
                af[mt][2] = As[cur][ks + tig + 4][wm + mt * 16 + grp];
                af[mt][3] = As[cur][ks + tig + 4][wm + mt * 16 + grp + 8];
            }
            #pragma unroll
            for (int nt = 0; nt < 8; nt++) {
                bf[nt][0] = Bs[cur][ks + tig    ][wn + nt * 8 + grp];
                bf[nt][1] = Bs[cur][ks + tig + 4][wn + nt * 8 + grp];
            }
            #pragma unroll
            for (int mt = 0; mt < 2; mt++)
                #pragma unroll
                for (int nt = 0; nt < 8; nt++) {
                    asm volatile(
                        "mma.sync.aligned.m16n8k8.row.col.f32.tf32.tf32.f32 "
                        "{%0,%1,%2,%3}, {%4,%5,%6,%7}, {%8,%9}, {%0,%1,%2,%3};"
                        : "+f"(acc[mt][nt][0]), "+f"(acc[mt][nt][1]),
                          "+f"(acc[mt][nt][2]), "+f"(acc[mt][nt][3])
                        : "r"(af[mt][0]), "r"(af[mt][1]), "r"(af[mt][2]), "r"(af[mt][3]),
                          "r"(bf[nt][0]), "r"(bf[nt][1]));
                }
        }
        if (!more) break;

        int nxt = cur ^ 1;
        As[nxt][a_k + 0][a_m] = f2tf(pa0.x);
        As[nxt][a_k + 1][a_m] = f2tf(pa0.y);
        As[nxt][a_k + 2][a_m] = f2tf(pa0.z);
        As[nxt][a_k + 3][a_m] = f2tf(pa0.w);
        As[nxt][a_k + 8][a_m] = f2tf(pa1.x);
        As[nxt][a_k + 9][a_m] = f2tf(pa1.y);
        As[nxt][a_k +10][a_m] = f2tf(pa1.z);
        As[nxt][a_k +11][a_m] = f2tf(pa1.w);
        if (TRANSB) {
            Bs[nxt][a_k + 0][a_m] = f2tf(pb0.x);
            Bs[nxt][a_k + 1][a_m] = f2tf(pb0.y);
            Bs[nxt][a_k + 2][a_m] = f2tf(pb0.z);
            Bs[nxt][a_k + 3][a_m] = f2tf(pb0.w);
            Bs[nxt][a_k + 8][a_m] = f2tf(pb1.x);
            Bs[nxt][a_k + 9][a_m] = f2tf(pb1.y);
            Bs[nxt][a_k +10][a_m] = f2tf(pb1.z);
            Bs[nxt][a_k +11][a_m] = f2tf(pb1.w);
        } else {
            uint4 u0 = { f2tf(pb0.x), f2tf(pb0.y), f2tf(pb0.z), f2tf(pb0.w) };
            uint4 u1 = { f2tf(pb1.x), f2tf(pb1.y), f2tf(pb1.z), f2tf(pb1.w) };
            *(uint4*)&Bs[nxt][b_k    ][b_n] = u0;
            *(uint4*)&Bs[nxt][b_k + 8][b_n] = u1;
        }
        __syncthreads();
        cur = nxt;
        k0 = k1;
    }

    // epilogue: acc[mt][nt] -> rows m0+wm+mt*16+grp(+8), cols n0+wn+nt*8+2*tig(+1)
    #pragma unroll
    for (int mt = 0; mt < 2; mt++) {
        #pragma unroll
        for (int half = 0; half < 2; half++) {
            int m = m0 + wm + mt * 16 + grp + half * 8;
            #pragma unroll
            for (int nt = 0; nt < 8; nt++) {
                int n = n0 + wn + nt * 8 + 2 * tig;
                float2 r;
                r.x = acc[mt][nt][half * 2 + 0] * alpha;
                r.y = acc[mt][nt][half * 2 + 1] * alpha;
                if (bias) {
                    r.x += bias[n];
                    r.y += bias[n + 1];
                }
                if (Res) {
                    const float2 rr = *(const float2*)(Res + (long long)m * ldc + n);
                    r.x += rr.x; r.y += rr.y;
                }
                if (RELU) {
                    r.x = fmaxf(r.x, 0.f);
                    r.y = fmaxf(r.y, 0.f);
                }
                *(float2*)(C + (long long)m * ldc + n) = r;
            }
        }
    }
}

// ---------------- small kernels ----------------
__global__ void feats_kernel(const float* __restrict__ x, float* __restrict__ feats)
{
    long long i = (long long)blockIdx.x * blockDim.x + threadIdx.x;
    if (i >= (long long)NB * NN * CIN) return;
    int c = (int)(i & (CIN - 1));
    long long bn = i >> 6;
    int n = (int)(bn & (NN - 1));
    int b = (int)(bn >> 10);
    feats[i] = x[((long long)b * CIN + c) * NN + n];
}

__device__ __forceinline__ void block_reduce2(float& s1, float& s2)
{
    __shared__ float b1[4], b2[4];
    #pragma unroll
    for (int o = 16; o > 0; o >>= 1) {
        s1 += __shfl_down_sync(0xffffffffu, s1, o);
        s2 += __shfl_down_sync(0xffffffffu, s2, o);
    }
    int w = threadIdx.x >> 5;
    if ((threadIdx.x & 31) == 0) { b1[w] = s1; b2[w] = s2; }
    __syncthreads();
    s1 = b1[0] + b1[1] + b1[2] + b1[3];
    s2 = b2[0] + b2[1] + b2[2] + b2[3];
}

__global__ void norm_kernel(const float* __restrict__ h0, float* __restrict__ nh)
{
    long long bn = blockIdx.x;
    int t = threadIdx.x; // 128
    const float* r = h0 + bn * HD;
    float v0 = r[t], v1 = r[t + 128], v2 = r[t + 256];
    float ss = v0 * v0 + v1 * v1 + v2 * v2, dummy = 0.f;
    block_reduce2(ss, dummy);
    float rinv = rsqrtf(ss);
    float* o = nh + bn * HD;
    o[t] = v0 * rinv; o[t + 128] = v1 * rinv; o[t + 256] = v2 * rinv;
}

__global__ void topk_warp_kernel(const float* __restrict__ sim, int* __restrict__ knn)
{
    int warp = blockIdx.x * (blockDim.x >> 5) + (threadIdx.x >> 5);
    if (warp >= NB * NN) return;
    int lane = threadIdx.x & 31;
    int n = warp & (NN - 1);
    const float* row = sim + (long long)warp * NN;
    float v[32];
    #pragma unroll
    for (int j = 0; j < 32; j++) {
        int m = j * 32 + lane;
        v[j] = (m == n) ? -3e38f : row[m];
    }
    unsigned taken = 0;
    int* o = knn + (long long)warp * KNN;
    for (int r = 0; r < KNN; r++) {
        float bv = -3e38f; int bj = 0;
        #pragma unroll
        for (int j = 0; j < 32; j++) {
            bool free_ = !((taken >> j) & 1u);
            if (free_ && v[j] > bv) { bv = v[j]; bj = j; }
        }
        int bidx = bj * 32 + lane;
        #pragma unroll
        for (int off = 16; off > 0; off >>= 1) {
            float ov = __shfl_xor_sync(0xffffffffu, bv, off);
            int   oi = __shfl_xor_sync(0xffffffffu, bidx, off);
            if (ov > bv || (ov == bv && oi < bidx)) { bv = ov; bidx = oi; }
        }
        if ((bidx & 31) == lane) taken |= 1u << (bidx >> 5);
        if (lane == 0) o[r] = bidx;
    }
}

__global__ void gcn_agg_ln(const float* __restrict__ hcur, const float* __restrict__ xw,
                           const int* __restrict__ knn,
                           const float* __restrict__ scale, const float* __restrict__ bias,
                           float* __restrict__ out)
{
    int bn = blockIdx.x;
    int b = bn >> 10;
    int t = threadIdx.x; // 128
    __shared__ int sidx[KNN];
    if (t < KNN) sidx[t] = knn[(long long)bn * KNN + t];
    __syncthreads();
    const float* xr = xw + (long long)bn * HD;
    float a0 = xr[t], a1 = xr[t + 128], a2 = xr[t + 256];
    #pragma unroll 4
    for (int j = 0; j < KNN; j++) {
        const float* r = xw + ((long long)(b * NN) + sidx[j]) * HD;
        a0 += r[t]; a1 += r[t + 128]; a2 += r[t + 256];
    }
    const float* h = hcur + (long long)bn * HD;
    const float inv17 = 1.f / 17.f;
    float v0 = h[t] + a0 * inv17;
    float v1 = h[t + 128] + a1 * inv17;
    float v2 = h[t + 256] + a2 * inv17;
    float s1 = v0 + v1 + v2;
    float s2 = v0 * v0 + v1 * v1 + v2 * v2;
    block_reduce2(s1, s2);
    float mu = s1 * (1.f / HD);
    float var = s2 * (1.f / HD) - mu * mu;
    float rstd = rsqrtf(var + 1e-5f);
    float* o = out + (long long)bn * HD;
    o[t]       = (v0 - mu) * rstd * scale[t]       + bias[t];
    o[t + 128] = (v1 - mu) * rstd * scale[t + 128] + bias[t + 128];
    o[t + 256] = (v2 - mu) * rstd * scale[t + 256] + bias[t + 256];
}

__global__ void add_ln_kernel(const float* __restrict__ a, const float* __restrict__ b,
                              const float* __restrict__ plus,
                              const float* __restrict__ scale, const float* __restrict__ bias,
                              float* __restrict__ out)
{
    long long bn = blockIdx.x;
    int t = threadIdx.x; // 128
    const float* ar = a + bn * HD;
    float v0 = ar[t], v1 = ar[t + 128], v2 = ar[t + 256];
    if (b) {
        const float* br = b + bn * HD;
        v0 += br[t]; v1 += br[t + 128]; v2 += br[t + 256];
    }
    float s1 = v0 + v1 + v2;
    float s2 = v0 * v0 + v1 * v1 + v2 * v2;
    block_reduce2(s1, s2);
    float mu = s1 * (1.f / HD);
    float var = s2 * (1.f / HD) - mu * mu;
    float rstd = rsqrtf(var + 1e-5f);
    float y0 = (v0 - mu) * rstd * scale[t]       + bias[t];
    float y1 = (v1 - mu) * rstd * scale[t + 128] + bias[t + 128];
    float y2 = (v2 - mu) * rstd * scale[t + 256] + bias[t + 256];
    if (plus) {
        const float* pr = plus + bn * HD;
        y0 += pr[t]; y1 += pr[t + 128]; y2 += pr[t + 256];
    }
    float* o = out + bn * HD;
    o[t] = y0; o[t + 128] = y1; o[t + 256] = y2;
}

__global__ void softmax_kernel(float* __restrict__ sc)
{
    long long r = blockIdx.x;
    float* row = sc + r * (long long)NN;
    int t = threadIdx.x; // 256
    float x0 = row[t], x1 = row[t + 256], x2 = row[t + 512], x3 = row[t + 768];
    float m = fmaxf(fmaxf(x0, x1), fmaxf(x2, x3));
    __shared__ float bm[8], bs[8];
    #pragma unroll
    for (int o = 16; o > 0; o >>= 1) m = fmaxf(m, __shfl_down_sync(0xffffffffu, m, o));
    if ((t & 31) == 0) bm[t >> 5] = m;
    __syncthreads();
    float mm = bm[0];
    #pragma unroll
    for (int i = 1; i < 8; i++) mm = fmaxf(mm, bm[i]);
    float e0 = __expf(x0 - mm), e1 = __expf(x1 - mm), e2 = __expf(x2 - mm), e3 = __expf(x3 - mm);
    float s = e0 + e1 + e2 + e3;
    #pragma unroll
    for (int o = 16; o > 0; o >>= 1) s += __shfl_down_sync(0xffffffffu, s, o);
    if ((t & 31) == 0) bs[t >> 5] = s;
    __syncthreads();
    float ssum = bs[0] + bs[1] + bs[2] + bs[3] + bs[4] + bs[5] + bs[6] + bs[7];
    float inv = 1.f / ssum;
    row[t] = e0 * inv; row[t + 256] = e1 * inv; row[t + 512] = e2 * inv; row[t + 768] = e3 * inv;
}

__global__ void pool_kernel(const float* __restrict__ h, float* __restrict__ pooled)
{
    int b = blockIdx.x;
    int t = threadIdx.x; // 384
    float s = 0.f;
    const float* base = h + (long long)b * NN * HD + t;
    for (int n = 0; n < NN; n++) s += base[(long long)n * HD];
    pooled[b * HD + t] = s * (1.f / NN);
}

__global__ void fin1_kernel(const float* __restrict__ pooled, const float* __restrict__ W,
                            const float* __restrict__ bias, float* __restrict__ z)
{
    int b = blockIdx.x;
    int j = threadIdx.x; // 384
    const float* p = pooled + b * HD;
    float s = bias[j];
    for (int k = 0; k < HD; k++) s = fmaf(p[k], W[k * HD + j], s);
    z[b * HD + j] = fmaxf(s, 0.f);
}

__global__ void fin2_kernel(const float* __restrict__ z, const float* __restrict__ W,
                            const float* __restrict__ bias, float* __restrict__ out)
{
    int b = blockIdx.x;
    int j = threadIdx.x; // 128
    const float* p = z + b * HD;
    float s = bias[j];
    for (int k = 0; k < HD; k++) s = fmaf(p[k], W[k * 128 + j], s);
    out[b * 128 + j] = s;
}

// ---------------- host-side GEMM dispatchers ----------------
static void gemm_f32(const float* A, const float* B, const float* bias, const float* Res, float* C,
                     int M, int Nn, int K, int lda, int ldb, int ldc,
                     long long sA, long long sAi, long long sB, long long sBi,
                     long long sC, long long sCi, int zi, int nz,
                     float alpha, bool transb, bool relu)
{
    dim3 grid(Nn / BN, M / BM, nz), block(256);
    if (transb) {
        if (relu) gemm_k<true, true ><<<grid, block>>>(A, B, bias, Res, C, M, Nn, K, lda, ldb, ldc, sA, sAi, sB, sBi, sC, sCi, zi, alpha);
        else      gemm_k<true, false><<<grid, block>>>(A, B, bias, Res, C, M, Nn, K, lda, ldb, ldc, sA, sAi, sB, sBi, sC, sCi, zi, alpha);
    } else {
        if (relu) gemm_k<false, true ><<<grid, block>>>(A, B, bias, Res, C, M, Nn, K, lda, ldb, ldc, sA, sAi, sB, sBi, sC, sCi, zi, alpha);
        else      gemm_k<false, false><<<grid, block>>>(A, B, bias, Res, C, M, Nn, K, lda, ldb, ldc, sA, sAi, sB, sBi, sC, sCi, zi, alpha);
    }
}

static void gemm_tf(const float* A, const float* B, const float* bias, const float* Res, float* C,
                    int M, int Nn, int K, int lda, int ldb, int ldc,
                    long long sA, long long sAi, long long sB, long long sBi,
                    long long sC, long long sCi, int zi, int nz,
                    float alpha, bool transb, bool relu)
{
    dim3 grid(Nn / 128, M / 128, nz), block(256);
    if (transb) {
        if (relu) tf32gemm_k<true, true ><<<grid, block>>>(A, B, bias, Res, C, K, lda, ldb, ldc, sA, sAi, sB, sBi, sC, sCi, zi, alpha);
        else      tf32gemm_k<true, false><<<grid, block>>>(A, B, bias, Res, C, K, lda, ldb, ldc, sA, sAi, sB, sBi, sC, sCi, zi, alpha);
    } else {
        if (relu) tf32gemm_k<false, true ><<<grid, block>>>(A, B, bias, Res, C, K, lda, ldb, ldc, sA, sAi, sB, sBi, sC, sCi, zi, alpha);
        else      tf32gemm_k<false, false><<<grid, block>>>(A, B, bias, Res, C, K, lda, ldb, ldc, sA, sAi, sB, sBi, sC, sCi, zi, alpha);
    }
}

template<typename T> static T* sym_addr(const void* sym)
{
    void* p = nullptr;
    cudaGetSymbolAddress(&p, sym);
    return (T*)p;
}

extern "C" void kernel_launch(void* const* d_in, const int* in_sizes, int n_in,
                              void* d_out, int out_size)
{
    const float* x      = (const float*)d_in[0];
    const float* W_enc  = (const float*)d_in[1];
    const float* b_enc  = (const float*)d_in[2];
    const float* gcn_W  = (const float*)d_in[3];
    const float* gcn_b  = (const float*)d_in[4];
    const float* Wq     = (const float*)d_in[5];
    const float* bq     = (const float*)d_in[6];
    const float* Wk     = (const float*)d_in[7];
    const float* bk     = (const float*)d_in[8];
    const float* Wv     = (const float*)d_in[9];
    const float* bv     = (const float*)d_in[10];
    const float* Wo     = (const float*)d_in[11];
    const float* bo     = (const float*)d_in[12];
    const float* lnsc   = (const float*)d_in[13];
    const float* lnbi   = (const float*)d_in[14];
    const float* W1     = (const float*)d_in[15];
    const float* b1     = (const float*)d_in[16];
    const float* W2     = (const float*)d_in[17];
    const float* b2     = (const float*)d_in[18];
    const float* lin1_W = (const float*)d_in[19];
    const float* lin1_b = (const float*)d_in[20];
    const float* lin2_W = (const float*)d_in[21];
    const float* lin2_b = (const float*)d_in[22];
    float* outp = (float*)d_out;

    float* featsp = sym_addr<float>(g_feats);
    float* h0p    = sym_addr<float>(g_h0);
    float* nhp    = sym_addr<float>(g_nh);
    float* simp   = sym_addr<float>(g_sim);
    int*   knnp   = sym_addr<int>(g_knn);
    float* hcurp  = sym_addr<float>(g_hcur);
    float* xwp    = sym_addr<float>(g_xw);
    float* hlocp  = sym_addr<float>(g_hloc);
    float* qp     = sym_addr<float>(g_q);
    float* kp     = sym_addr<float>(g_k);
    float* vp     = sym_addr<float>(g_v);
    float* scp    = sym_addr<float>(g_sc);
    float* aop    = sym_addr<float>(g_ao);
    float* op     = sym_addr<float>(g_o);
    float* combp  = sym_addr<float>(g_comb);
    float* mlp1p  = sym_addr<float>(g_mlp1);
    float* ffp    = sym_addr<float>(g_ff);
    float* poolp  = sym_addr<float>(g_pool);
    float* zp     = sym_addr<float>(g_z);

    const long long NH = (long long)NN * HD;       // per-batch hidden stride
    const long long SS = (long long)NN * NN;       // per-head score stride

    // ---- encoder (exact fp32: feeds graph build) ----
    feats_kernel<<<(NB * NN * CIN + 255) / 256, 256>>>(x, featsp);
    gemm_f32(featsp, W_enc, b_enc, nullptr, h0p,
             NN, HD, CIN, CIN, HD, HD,
             (long long)NN * CIN, 0, 0, 0, NH, 0, 1, NB, 1.f, false, false);

    // ---- graph build (exact fp32 so kNN selection is stable) ----
    norm_kernel<<<NB * NN, 128>>>(h0p, nhp);
    gemm_f32(nhp, nhp, nullptr, nullptr, simp,
             NN, NN, HD, HD, HD, NN,
             NH, 0, NH, 0, SS, 0, 1, NB, 1.f, true, false);
    topk_warp_kernel<<<NB * NN / 8, 256>>>(simp, knnp);

    const float* hin = h0p;
    for (int l = 0; l < NL; l++) {
        const float* scl = lnsc + (l * 3) * HD;
        const float* bil = lnbi + (l * 3) * HD;

        // local GCN branch
        gemm_tf(hin, gcn_W + (long long)l * HD * HD, gcn_b + l * HD, nullptr, xwp,
                NN, HD, HD, HD, HD, HD, NH, 0, 0, 0, NH, 0, 1, NB, 1.f, false, false);
        gcn_agg_ln<<<NB * NN, 128>>>(hin, xwp, knnp, scl, bil, hlocp);

        // attention branch
        gemm_tf(hin, Wq + (long long)l * HD * HD, bq + l * HD, nullptr, qp,
                NN, HD, HD, HD, HD, HD, NH, 0, 0, 0, NH, 0, 1, NB, 1.f, false, false);
        gemm_tf(hin, Wk + (long long)l * HD * HD, bk + l * HD, nullptr, kp,
                NN, HD, HD, HD, HD, HD, NH, 0, 0, 0, NH, 0, 1, NB, 1.f, false, false);
        gemm_tf(hin, Wv + (long long)l * HD * HD, bv + l * HD, nullptr, vp,
                NN, HD, HD, HD, HD, HD, NH, 0, 0, 0, NH, 0, 1, NB, 1.f, false, false);
        // scores[b,h] = q_h @ k_h^T / sqrt(128)
        gemm_tf(qp, kp, nullptr, nullptr, scp,
                NN, NN, DHE, HD, HD, NN,
                NH, DHE, NH, DHE, (long long)NHE * SS, SS, NHE, NB * NHE,
                0.08838834764831843f, true, false);
        softmax_kernel<<<NB * NHE * NN, 256>>>(scp);
        // attn @ V
        gemm_tf(scp, vp, nullptr, nullptr, aop,
                NN, DHE, NN, NN, HD, HD,
                (long long)NHE * SS, SS, NH, DHE, NH, DHE, NHE, NB * NHE,
                1.f, false, false);
        gemm_tf(aop, Wo + (long long)l * HD * HD, bo + l * HD, nullptr, op,
                NN, HD, HD, HD, HD, HD, NH, 0, 0, 0, NH, 0, 1, NB, 1.f, false, false);
        // comb = h_local + LN(hcur + o)
        add_ln_kernel<<<NB * NN, 128>>>(hin, op, hlocp, scl + HD, bil + HD, combp);

        // FFN
        gemm_tf(combp, W1 + (long long)l * HD * 2 * HD, b1 + l * 2 * HD, nullptr, mlp1p,
                NN, 2 * HD, HD, HD, 2 * HD, 2 * HD,
                NH, 0, 0, 0, (long long)NN * 2 * HD, 0, 1, NB, 1.f, false, true);
        gemm_tf(mlp1p, W2 + (long long)l * 2 * HD * HD, b2 + l * HD, combp, ffp,
                NN, HD, 2 * HD, 2 * HD, HD, HD,
                (long long)NN * 2 * HD, 0, 0, 0, NH, 0, 1, NB, 1.f, false, false);
        add_ln_kernel<<<NB * NN, 128>>>(ffp, nullptr, nullptr, scl + 2 * HD, bil + 2 * HD, hcurp);
        hin = hcurp;
    }

    // ---- head ----
    pool_kernel<<<NB, HD>>>(hin, poolp);
    fin1_kernel<<<NB, HD>>>(poolp, lin1_W, lin1_b, zp);
    fin2_kernel<<<NB, 128>>>(zp, lin2_W, lin2_b, outp);
}

// round 4
// speedup vs baseline: 2.6393x; 1.1827x over previous
#include <cuda_runtime.h>
#include <math.h>
#include <stdint.h>

// ---------------- problem constants ----------------
static const int NB   = 8;     // batch
static const int NN   = 1024;  // nodes (32*32)
static const int CIN  = 64;    // input channels
static const int HD   = 384;   // hidden
static const int NL   = 3;     // layers
static const int KNN  = 16;    // k
static const int NHE  = 3;     // heads
static const int DHE  = 128;   // head dim

// ---------------- device scratch (no allocs allowed) ----------------
__device__ float g_feats [NB*NN*CIN];
__device__ float g_h0    [NB*NN*HD];
__device__ float g_h0r   [NB*NN*HD];
__device__ float g_nh    [NB*NN*HD];
__device__ float g_sim   [NB*NN*NN];
__device__ int   g_knn   [NB*NN*KNN];
__device__ float g_hcur  [NB*NN*HD];
__device__ float g_xw    [NB*NN*HD];
__device__ float g_hloc  [NB*NN*HD];
__device__ float g_q     [NB*NN*HD];
__device__ float g_k     [NB*NN*HD];
__device__ float g_v     [NB*NN*HD];
__device__ float g_sc    [(long long)NB*NHE*NN*NN];
__device__ float g_ao    [NB*NN*HD];
__device__ float g_o     [NB*NN*HD];
__device__ float g_comb  [NB*NN*HD];
__device__ float g_mlp1  [NB*NN*2*HD];
__device__ float g_ff    [NB*NN*HD];
__device__ float g_pool  [NB*HD];
__device__ float g_z     [NB*HD];
// rounded-weight blob
__device__ float g_wr    [3981312];
// offsets into g_wr (floats)
static const long long WR_GCN = 0;
static const long long WR_WQ  = 442368;
static const long long WR_WK  = 884736;
static const long long WR_WV  = 1327104;
static const long long WR_WO  = 1769472;
static const long long WR_W1  = 2211840;
static const long long WR_W2  = 3096576;

__device__ __forceinline__ float rna_tf32(float x)
{
    uint32_t r;
    asm("cvt.rna.tf32.f32 %0, %1;" : "=r"(r) : "f"(x));
    return __uint_as_float(r);
}

// ================= fp32 SIMT GEMM (exact path: encoder + cosine-sim) =======
#define BM 128
#define BN 128
#define BKK 8
#define SPAD 132

template<bool TRANSB, bool RELU>
__global__ void __launch_bounds__(256, 2)
gemm_k(const float* __restrict__ A, const float* __restrict__ B,
       const float* __restrict__ bias, const float* __restrict__ Res,
       float* __restrict__ C,
       int M, int Nn, int K, int lda, int ldb, int ldc,
       long long sA, long long sAi, long long sB, long long sBi,
       long long sC, long long sCi, int zi, float alpha)
{
    int bz = blockIdx.z;
    int zo = bz / zi, zin = bz % zi;
    A += zo * sA + zin * sAi;
    B += zo * sB + zin * sBi;
    C += zo * sC + zin * sCi;
    if (Res) Res += zo * sC + zin * sCi;

    int m0 = blockIdx.y * BM;
    int n0 = blockIdx.x * BN;

    __shared__ float As[2][BKK][SPAD];
    __shared__ float Bs[2][BKK][SPAD];

    int tid = threadIdx.x;
    int tx = tid & 15;
    int ty = tid >> 4;

    int a_m = tid >> 1;
    int a_k = (tid & 1) * 4;
    const float* Aload = A + (long long)(m0 + a_m) * lda + a_k;

    const float* Bload;
    int b_k = 0, b_n = 0;
    if (TRANSB) {
        Bload = B + (long long)(n0 + a_m) * ldb + a_k;
    } else {
        b_k = tid >> 5;
        b_n = (tid & 31) * 4;
        Bload = B + (long long)b_k * ldb + n0 + b_n;
    }

    float4 av = *(const float4*)Aload;
    float4 bv = *(const float4*)Bload;

    As[0][a_k + 0][a_m] = av.x;
    As[0][a_k + 1][a_m] = av.y;
    As[0][a_k + 2][a_m] = av.z;
    As[0][a_k + 3][a_m] = av.w;
    if (TRANSB) {
        Bs[0][a_k + 0][a_m] = bv.x;
        Bs[0][a_k + 1][a_m] = bv.y;
        Bs[0][a_k + 2][a_m] = bv.z;
        Bs[0][a_k + 3][a_m] = bv.w;
    } else {
        *(float4*)&Bs[0][b_k][b_n] = bv;
    }
    __syncthreads();

    float acc[8][8];
    #pragma unroll
    for (int i = 0; i < 8; i++)
        #pragma unroll
        for (int j = 0; j < 8; j++) acc[i][j] = 0.f;

    int cur = 0;
    for (int k0 = 0; ; ) {
        int k1 = k0 + BKK;
        bool more = (k1 < K);
        if (more) {
            av = *(const float4*)(Aload + k1);
            if (TRANSB) bv = *(const float4*)(Bload + k1);
            else        bv = *(const float4*)(Bload + (long long)k1 * ldb);
        }

        #pragma unroll
        for (int kk = 0; kk < BKK; kk++) {
            float4 a0 = *(const float4*)&As[cur][kk][ty * 4];
            float4 a1 = *(const float4*)&As[cur][kk][64 + ty * 4];
            float4 b0 = *(const float4*)&Bs[cur][kk][tx * 4];
            float4 b1 = *(const float4*)&Bs[cur][kk][64 + tx * 4];
            float a[8] = {a0.x, a0.y, a0.z, a0.w, a1.x, a1.y, a1.z, a1.w};
            float b[8] = {b0.x, b0.y, b0.z, b0.w, b1.x, b1.y, b1.z, b1.w};
            #pragma unroll
            for (int i = 0; i < 8; i++)
                #pragma unroll
                for (int j = 0; j < 8; j++)
                    acc[i][j] = fmaf(a[i], b[j], acc[i][j]);
        }
        if (!more) break;

        int nxt = cur ^ 1;
        As[nxt][a_k + 0][a_m] = av.x;
        As[nxt][a_k + 1][a_m] = av.y;
        As[nxt][a_k + 2][a_m] = av.z;
        As[nxt][a_k + 3][a_m] = av.w;
        if (TRANSB) {
            Bs[nxt][a_k + 0][a_m] = bv.x;
            Bs[nxt][a_k + 1][a_m] = bv.y;
            Bs[nxt][a_k + 2][a_m] = bv.z;
            Bs[nxt][a_k + 3][a_m] = bv.w;
        } else {
            *(float4*)&Bs[nxt][b_k][b_n] = bv;
        }
        __syncthreads();
        cur = nxt;
        k0 = k1;
    }

    #pragma unroll
    for (int ih = 0; ih < 2; ih++) {
        #pragma unroll
        for (int i = 0; i < 4; i++) {
            int m = m0 + ih * 64 + ty * 4 + i;
            #pragma unroll
            for (int jh = 0; jh < 2; jh++) {
                int n = n0 + jh * 64 + tx * 4;
                float4 r;
                r.x = acc[ih * 4 + i][jh * 4 + 0] * alpha;
                r.y = acc[ih * 4 + i][jh * 4 + 1] * alpha;
                r.z = acc[ih * 4 + i][jh * 4 + 2] * alpha;
                r.w = acc[ih * 4 + i][jh * 4 + 3] * alpha;
                if (bias) {
                    float4 bb = *(const float4*)(bias + n);
                    r.x += bb.x; r.y += bb.y; r.z += bb.z; r.w += bb.w;
                }
                if (Res) {
                    float4 rr = *(const float4*)(Res + (long long)m * ldc + n);
                    r.x += rr.x; r.y += rr.y; r.z += rr.z; r.w += rr.w;
                }
                if (RELU) {
                    r.x = fmaxf(r.x, 0.f); r.y = fmaxf(r.y, 0.f);
                    r.z = fmaxf(r.z, 0.f); r.w = fmaxf(r.w, 0.f);
                }
                *(float4*)(C + (long long)m * ldc + n) = r;
            }
        }
    }
}

// ================= tf32 tensor-core GEMM with cp.async ====================
// Inputs MUST be pre-rounded to tf32 (rna). 128x128 block, BK=16, 8 warps
// (4m x 2n), warp tile 32x64, mma.m16n8k8, 2-stage cp.async pipeline.
// Smem layouts: A and trans-B row-major [m][k] stride 20 (conflict-free);
// non-trans B [k][n] stride 136.
#define ASTRIDE 20
#define BNSTRIDE 136

__device__ __forceinline__ void cpa16(void* dst, const void* src)
{
    uint32_t s = (uint32_t)__cvta_generic_to_shared(dst);
    asm volatile("cp.async.cg.shared.global [%0], [%1], 16;" :: "r"(s), "l"(src));
}

template<bool TRANSB, bool RELU, bool TF32OUT>
__global__ void __launch_bounds__(256, 2)
tf32gemm_k(const float* __restrict__ A, const float* __restrict__ B,
           const float* __restrict__ bias, const float* __restrict__ Res,
           float* __restrict__ C,
           int K, int lda, int ldb, int ldc,
           long long sA, long long sAi, long long sB, long long sBi,
           long long sC, long long sCi, int zi, float alpha)
{
    int bz = blockIdx.z;
    int zo = bz / zi, zin = bz % zi;
    A += zo * sA + zin * sAi;
    B += zo * sB + zin * sBi;
    C += zo * sC + zin * sCi;
    if (Res) Res += zo * sC + zin * sCi;

    int m0 = blockIdx.y * 128;
    int n0 = blockIdx.x * 128;

    __shared__ __align__(16) float As[2][128 * ASTRIDE];
    constexpr int BSZ = TRANSB ? 128 * ASTRIDE : 16 * BNSTRIDE;
    __shared__ __align__(16) float Bs[2][BSZ];

    int tid = threadIdx.x;
    int lane = tid & 31;
    int wid = tid >> 5;
    int wm = (wid & 3) * 32;
    int wn = (wid >> 2) * 64;
    int tig = lane & 3;
    int grp = lane >> 2;

    // cp.async load maps
    int ra = tid >> 2;           // 0..63
    int ca = (tid & 3) * 4;      // 0,4,8,12
    const float* Asrc0 = A + (long long)(m0 + ra) * lda + ca;
    const float* Asrc1 = A + (long long)(m0 + ra + 64) * lda + ca;
    int aoff0 = ra * ASTRIDE + ca;
    int aoff1 = (ra + 64) * ASTRIDE + ca;

    const float *Bsrc0, *Bsrc1;
    int boff0, boff1;
    if (TRANSB) {
        Bsrc0 = B + (long long)(n0 + ra) * ldb + ca;
        Bsrc1 = B + (long long)(n0 + ra + 64) * ldb + ca;
        boff0 = aoff0;
        boff1 = aoff1;
    } else {
        int rb = tid >> 5;            // 0..7
        int cb = (tid & 31) * 4;      // 0..124
        Bsrc0 = B + (long long)rb * ldb + n0 + cb;
        Bsrc1 = B + (long long)(rb + 8) * ldb + n0 + cb;
        boff0 = rb * BNSTRIDE + cb;
        boff1 = (rb + 8) * BNSTRIDE + cb;
    }

    // stage-0 prefetch
    {
        cpa16(&As[0][aoff0], Asrc0);
        cpa16(&As[0][aoff1], Asrc1);
        if (TRANSB) {
            cpa16(&Bs[0][boff0], Bsrc0);
            cpa16(&Bs[0][boff1], Bsrc1);
        } else {
            cpa16(&Bs[0][boff0], Bsrc0);
            cpa16(&Bs[0][boff1], Bsrc1);
        }
        asm volatile("cp.async.commit_group;");
    }

    float acc[2][8][4];
    #pragma unroll
    for (int mt = 0; mt < 2; mt++)
        #pragma unroll
        for (int nt = 0; nt < 8; nt++)
            #pragma unroll
            for (int r = 0; r < 4; r++) acc[mt][nt][r] = 0.f;

    int cur = 0;
    int k0 = 0;
    for (;;) {
        int k1 = k0 + 16;
        bool more = (k1 < K);
        if (more) {
            int nxt = cur ^ 1;
            cpa16(&As[nxt][aoff0], Asrc0 + k1);
            cpa16(&As[nxt][aoff1], Asrc1 + k1);
            if (TRANSB) {
                cpa16(&Bs[nxt][boff0], Bsrc0 + k1);
                cpa16(&Bs[nxt][boff1], Bsrc1 + k1);
            } else {
                cpa16(&Bs[nxt][boff0], Bsrc0 + (long long)k1 * ldb);
                cpa16(&Bs[nxt][boff1], Bsrc1 + (long long)k1 * ldb);
            }
            asm volatile("cp.async.commit_group;");
            asm volatile("cp.async.wait_group 1;");
        } else {
            asm volatile("cp.async.wait_group 0;");
        }
        __syncthreads();

        #pragma unroll
        for (int ks = 0; ks < 16; ks += 8) {
            uint32_t af[2][4], bf[8][2];
            #pragma unroll
            for (int mt = 0; mt < 2; mt++) {
                int mA = wm + mt * 16 + grp;
                af[mt][0] = __float_as_uint(As[cur][mA * ASTRIDE + ks + tig]);
                af[mt][1] = __float_as_uint(As[cur][(mA + 8) * ASTRIDE + ks + tig]);
                af[mt][2] = __float_as_uint(As[cur][mA * ASTRIDE + ks + tig + 4]);
                af[mt][3] = __float_as_uint(As[cur][(mA + 8) * ASTRIDE + ks + tig + 4]);
            }
            #pragma unroll
            for (int nt = 0; nt < 8; nt++) {
                int nB = wn + nt * 8 + grp;
                if (TRANSB) {
                    bf[nt][0] = __float_as_uint(Bs[cur][nB * ASTRIDE + ks + tig]);
                    bf[nt][1] = __float_as_uint(Bs[cur][nB * ASTRIDE + ks + tig + 4]);
                } else {
                    bf[nt][0] = __float_as_uint(Bs[cur][(ks + tig) * BNSTRIDE + nB]);
                    bf[nt][1] = __float_as_uint(Bs[cur][(ks + tig + 4) * BNSTRIDE + nB]);
                }
            }
            #pragma unroll
            for (int mt = 0; mt < 2; mt++)
                #pragma unroll
                for (int nt = 0; nt < 8; nt++) {
                    asm volatile(
                        "mma.sync.aligned.m16n8k8.row.col.f32.tf32.tf32.f32 "
                        "{%0,%1,%2,%3}, {%4,%5,%6,%7}, {%8,%9}, {%0,%1,%2,%3};"
                        : "+f"(acc[mt][nt][0]), "+f"(acc[mt][nt][1]),
                          "+f"(acc[mt][nt][2]), "+f"(acc[mt][nt][3])
                        : "r"(af[mt][0]), "r"(af[mt][1]), "r"(af[mt][2]), "r"(af[mt][3]),
                          "r"(bf[nt][0]), "r"(bf[nt][1]));
                }
        }
        if (!more) break;
        __syncthreads();   // all warps done with 'cur' before next prefetch overwrites
        cur ^= 1;
        k0 = k1;
    }

    // epilogue
    #pragma unroll
    for (int mt = 0; mt < 2; mt++) {
        #pragma unroll
        for (int half = 0; half < 2; half++) {
            int m = m0 + wm + mt * 16 + grp + half * 8;
            #pragma unroll
            for (int nt = 0; nt < 8; nt++) {
                int n = n0 + wn + nt * 8 + 2 * tig;
                float2 r;
                r.x = acc[mt][nt][half * 2 + 0] * alpha;
                r.y = acc[mt][nt][half * 2 + 1] * alpha;
                if (bias) {
                    r.x += bias[n];
                    r.y += bias[n + 1];
                }
                if (Res) {
                    const float2 rr = *(const float2*)(Res + (long long)m * ldc + n);
                    r.x += rr.x; r.y += rr.y;
                }
                if (RELU) {
                    r.x = fmaxf(r.x, 0.f);
                    r.y = fmaxf(r.y, 0.f);
                }
                if (TF32OUT) {
                    r.x = rna_tf32(r.x);
                    r.y = rna_tf32(r.y);
                }
                *(float2*)(C + (long long)m * ldc + n) = r;
            }
        }
    }
}

// ---------------- small kernels ----------------
__global__ void feats_kernel(const float* __restrict__ x, float* __restrict__ feats)
{
    long long i = (long long)blockIdx.x * blockDim.x + threadIdx.x;
    if (i >= (long long)NB * NN * CIN) return;
    int c = (int)(i & (CIN - 1));
    long long bn = i >> 6;
    int n = (int)(bn & (NN - 1));
    int b = (int)(bn >> 10);
    feats[i] = x[((long long)b * CIN + c) * NN + n];
}

__global__ void round_copy_kernel(const float* __restrict__ src, float* __restrict__ dst, int n)
{
    int i = blockIdx.x * blockDim.x + threadIdx.x;
    if (i < n) dst[i] = rna_tf32(src[i]);
}

__device__ __forceinline__ void block_reduce2(float& s1, float& s2)
{
    __shared__ float b1[4], b2[4];
    #pragma unroll
    for (int o = 16; o > 0; o >>= 1) {
        s1 += __shfl_down_sync(0xffffffffu, s1, o);
        s2 += __shfl_down_sync(0xffffffffu, s2, o);
    }
    int w = threadIdx.x >> 5;
    if ((threadIdx.x & 31) == 0) { b1[w] = s1; b2[w] = s2; }
    __syncthreads();
    s1 = b1[0] + b1[1] + b1[2] + b1[3];
    s2 = b2[0] + b2[1] + b2[2] + b2[3];
}

__global__ void norm_kernel(const float* __restrict__ h0, float* __restrict__ nh)
{
    long long bn = blockIdx.x;
    int t = threadIdx.x; // 128
    const float* r = h0 + bn * HD;
    float v0 = r[t], v1 = r[t + 128], v2 = r[t + 256];
    float ss = v0 * v0 + v1 * v1 + v2 * v2, dummy = 0.f;
    block_reduce2(ss, dummy);
    float rinv = rsqrtf(ss);
    float* o = nh + bn * HD;
    o[t] = v0 * rinv; o[t + 128] = v1 * rinv; o[t + 256] = v2 * rinv;
}

__global__ void topk_warp_kernel(const float* __restrict__ sim, int* __restrict__ knn)
{
    int warp = blockIdx.x * (blockDim.x >> 5) + (threadIdx.x >> 5);
    if (warp >= NB * NN) return;
    int lane = threadIdx.x & 31;
    int n = warp & (NN - 1);
    const float* row = sim + (long long)warp * NN;
    float v[32];
    #pragma unroll
    for (int j = 0; j < 32; j++) {
        int m = j * 32 + lane;
        v[j] = (m == n) ? -3e38f : row[m];
    }
    unsigned taken = 0;
    int* o = knn + (long long)warp * KNN;
    for (int r = 0; r < KNN; r++) {
        float bv = -3e38f; int bj = 0;
        #pragma unroll
        for (int j = 0; j < 32; j++) {
            bool free_ = !((taken >> j) & 1u);
            if (free_ && v[j] > bv) { bv = v[j]; bj = j; }
        }
        int bidx = bj * 32 + lane;
        #pragma unroll
        for (int off = 16; off > 0; off >>= 1) {
            float ov = __shfl_xor_sync(0xffffffffu, bv, off);
            int   oi = __shfl_xor_sync(0xffffffffu, bidx, off);
            if (ov > bv || (ov == bv && oi < bidx)) { bv = ov; bidx = oi; }
        }
        if ((bidx & 31) == lane) taken |= 1u << (bidx >> 5);
        if (lane == 0) o[r] = bidx;
    }
}

__global__ void gcn_agg_ln(const float* __restrict__ hcur, const float* __restrict__ xw,
                           const int* __restrict__ knn,
                           const float* __restrict__ scale, const float* __restrict__ bias,
                           float* __restrict__ out)
{
    int bn = blockIdx.x;
    int b = bn >> 10;
    int t = threadIdx.x; // 128
    __shared__ int sidx[KNN];
    if (t < KNN) sidx[t] = knn[(long long)bn * KNN + t];
    __syncthreads();
    const float* xr = xw + (long long)bn * HD;
    float a0 = xr[t], a1 = xr[t + 128], a2 = xr[t + 256];
    #pragma unroll 4
    for (int j = 0; j < KNN; j++) {
        const float* r = xw + ((long long)(b * NN) + sidx[j]) * HD;
        a0 += r[t]; a1 += r[t + 128]; a2 += r[t + 256];
    }
    const float* h = hcur + (long long)bn * HD;
    const float inv17 = 1.f / 17.f;
    float v0 = h[t] + a0 * inv17;
    float v1 = h[t + 128] + a1 * inv17;
    float v2 = h[t + 256] + a2 * inv17;
    float s1 = v0 + v1 + v2;
    float s2 = v0 * v0 + v1 * v1 + v2 * v2;
    block_reduce2(s1, s2);
    float mu = s1 * (1.f / HD);
    float var = s2 * (1.f / HD) - mu * mu;
    float rstd = rsqrtf(var + 1e-5f);
    float* o = out + (long long)bn * HD;
    o[t]       = (v0 - mu) * rstd * scale[t]       + bias[t];
    o[t + 128] = (v1 - mu) * rstd * scale[t + 128] + bias[t + 128];
    o[t + 256] = (v2 - mu) * rstd * scale[t + 256] + bias[t + 256];
}

// out = (plus? plus : 0) + LN(a + (b? b : 0)); optional tf32 rounding of out
__global__ void add_ln_kernel(const float* __restrict__ a, const float* __restrict__ b,
                              const float* __restrict__ plus,
                              const float* __restrict__ scale, const float* __restrict__ bias,
                              float* __restrict__ out, int rnd)
{
    long long bn = blockIdx.x;
    int t = threadIdx.x; // 128
    const float* ar = a + bn * HD;
    float v0 = ar[t], v1 = ar[t + 128], v2 = ar[t + 256];
    if (b) {
        const float* br = b + bn * HD;
        v0 += br[t]; v1 += br[t + 128]; v2 += br[t + 256];
    }
    float s1 = v0 + v1 + v2;
    float s2 = v0 * v0 + v1 * v1 + v2 * v2;
    block_reduce2(s1, s2);
    float mu = s1 * (1.f / HD);
    float var = s2 * (1.f / HD) - mu * mu;
    float rstd = rsqrtf(var + 1e-5f);
    float y0 = (v0 - mu) * rstd * scale[t]       + bias[t];
    float y1 = (v1 - mu) * rstd * scale[t + 128] + bias[t + 128];
    float y2 = (v2 - mu) * rstd * scale[t + 256] + bias[t + 256];
    if (plus) {
        const float* pr = plus + bn * HD;
        y0 += pr[t]; y1 += pr[t + 128]; y2 += pr[t + 256];
    }
    if (rnd) { y0 = rna_tf32(y0); y1 = rna_tf32(y1); y2 = rna_tf32(y2); }
    float* o = out + bn * HD;
    o[t] = y0; o[t + 128] = y1; o[t + 256] = y2;
}

__global__ void softmax_kernel(float* __restrict__ sc)
{
    long long r = blockIdx.x;
    float* row = sc + r * (long long)NN;
    int t = threadIdx.x; // 256
    float x0 = row[t], x1 = row[t + 256], x2 = row[t + 512], x3 = row[t + 768];
    float m = fmaxf(fmaxf(x0, x1), fmaxf(x2, x3));
    __shared__ float bm[8], bs[8];
    #pragma unroll
    for (int o = 16; o > 0; o >>= 1) m = fmaxf(m, __shfl_down_sync(0xffffffffu, m, o));
    if ((t & 31) == 0) bm[t >> 5] = m;
    __syncthreads();
    float mm = bm[0];
    #pragma unroll
    for (int i = 1; i < 8; i++) mm = fmaxf(mm, bm[i]);
    float e0 = __expf(x0 - mm), e1 = __expf(x1 - mm), e2 = __expf(x2 - mm), e3 = __expf(x3 - mm);
    float s = e0 + e1 + e2 + e3;
    #pragma unroll
    for (int o = 16; o > 0; o >>= 1) s += __shfl_down_sync(0xffffffffu, s, o);
    if ((t & 31) == 0) bs[t >> 5] = s;
    __syncthreads();
    float ssum = bs[0] + bs[1] + bs[2] + bs[3] + bs[4] + bs[5] + bs[6] + bs[7];
    float inv = 1.f / ssum;
    row[t]       = rna_tf32(e0 * inv);
    row[t + 256] = rna_tf32(e1 * inv);
    row[t + 512] = rna_tf32(e2 * inv);
    row[t + 768] = rna_tf32(e3 * inv);
}

__global__ void pool_kernel(const float* __restrict__ h, float* __restrict__ pooled)
{
    int b = blockIdx.x;
    int t = threadIdx.x; // 384
    float s = 0.f;
    const float* base = h + (long long)b * NN * HD + t;
    for (int n = 0; n < NN; n++) s += base[(long long)n * HD];
    pooled[b * HD + t] = s * (1.f / NN);
}

__global__ void fin1_kernel(const float* __restrict__ pooled, const float* __restrict__ W,
                            const float* __restrict__ bias, float* __restrict__ z)
{
    int b = blockIdx.x;
    int j = threadIdx.x; // 384
    const float* p = pooled + b * HD;
    float s = bias[j];
    for (int k = 0; k < HD; k++) s = fmaf(p[k], W[k * HD + j], s);
    z[b * HD + j] = fmaxf(s, 0.f);
}

__global__ void fin2_kernel(const float* __restrict__ z, const float* __restrict__ W,
                            const float* __restrict__ bias, float* __restrict__ out)
{
    int b = blockIdx.x;
    int j = threadIdx.x; // 128
    const float* p = z + b * HD;
    float s = bias[j];
    for (int k = 0; k < HD; k++) s = fmaf(p[k], W[k * 128 + j], s);
    out[b * 128 + j] = s;
}

// ---------------- host-side GEMM dispatchers ----------------
static void gemm_f32(const float* A, const float* B, const float* bias, const float* Res, float* C,
                     int M, int Nn, int K, int lda, int ldb, int ldc,
                     long long sA, long long sAi, long long sB, long long sBi,
                     long long sC, long long sCi, int zi, int nz,
                     float alpha, bool transb, bool relu)
{
    dim3 grid(Nn / BN, M / BM, nz), block(256);
    if (transb) {
        if (relu) gemm_k<true, true ><<<grid, block>>>(A, B, bias, Res, C, M, Nn, K, lda, ldb, ldc, sA, sAi, sB, sBi, sC, sCi, zi, alpha);
        else      gemm_k<true, false><<<grid, block>>>(A, B, bias, Res, C, M, Nn, K, lda, ldb, ldc, sA, sAi, sB, sBi, sC, sCi, zi, alpha);
    } else {
        if (relu) gemm_k<false, true ><<<grid, block>>>(A, B, bias, Res, C, M, Nn, K, lda, ldb, ldc, sA, sAi, sB, sBi, sC, sCi, zi, alpha);
        else      gemm_k<false, false><<<grid, block>>>(A, B, bias, Res, C, M, Nn, K, lda, ldb, ldc, sA, sAi, sB, sBi, sC, sCi, zi, alpha);
    }
}

static void gemm_tf(const float* A, const float* B, const float* bias, const float* Res, float* C,
                    int M, int Nn, int K, int lda, int ldb, int ldc,
                    long long sA, long long sAi, long long sB, long long sBi,
                    long long sC, long long sCi, int zi, int nz,
                    float alpha, bool transb, bool relu, bool tf32out)
{
    dim3 grid(Nn / 128, M / 128, nz), block(256);
    #define DISP(TB, RL, TO) tf32gemm_k<TB, RL, TO><<<grid, block>>>(A, B, bias, Res, C, K, lda, ldb, ldc, sA, sAi, sB, sBi, sC, sCi, zi, alpha)
    if (transb) {
        if (relu)  { if (tf32out) DISP(true, true, true);  else DISP(true, true, false); }
        else       { if (tf32out) DISP(true, false, true); else DISP(true, false, false); }
    } else {
        if (relu)  { if (tf32out) DISP(false, true, true);  else DISP(false, true, false); }
        else       { if (tf32out) DISP(false, false, true); else DISP(false, false, false); }
    }
    #undef DISP
}

template<typename T> static T* sym_addr(const void* sym)
{
    void* p = nullptr;
    cudaGetSymbolAddress(&p, sym);
    return (T*)p;
}

extern "C" void kernel_launch(void* const* d_in, const int* in_sizes, int n_in,
                              void* d_out, int out_size)
{
    const float* x      = (const float*)d_in[0];
    const float* W_enc  = (const float*)d_in[1];
    const float* b_enc  = (const float*)d_in[2];
    const float* gcn_W  = (const float*)d_in[3];
    const float* gcn_b  = (const float*)d_in[4];
    const float* Wq     = (const float*)d_in[5];
    const float* bq     = (const float*)d_in[6];
    const float* Wk     = (const float*)d_in[7];
    const float* bk     = (const float*)d_in[8];
    const float* Wv     = (const float*)d_in[9];
    const float* bv     = (const float*)d_in[10];
    const float* Wo     = (const float*)d_in[11];
    const float* bo     = (const float*)d_in[12];
    const float* lnsc   = (const float*)d_in[13];
    const float* lnbi   = (const float*)d_in[14];
    const float* W1     = (const float*)d_in[15];
    const float* b1     = (const float*)d_in[16];
    const float* W2     = (const float*)d_in[17];
    const float* b2     = (const float*)d_in[18];
    const float* lin1_W = (const float*)d_in[19];
    const float* lin1_b = (const float*)d_in[20];
    const float* lin2_W = (const float*)d_in[21];
    const float* lin2_b = (const float*)d_in[22];
    float* outp = (float*)d_out;

    float* featsp = sym_addr<float>(g_feats);
    float* h0p    = sym_addr<float>(g_h0);
    float* h0rp   = sym_addr<float>(g_h0r);
    float* nhp    = sym_addr<float>(g_nh);
    float* simp   = sym_addr<float>(g_sim);
    int*   knnp   = sym_addr<int>(g_knn);
    float* hcurp  = sym_addr<float>(g_hcur);
    float* xwp    = sym_addr<float>(g_xw);
    float* hlocp  = sym_addr<float>(g_hloc);
    float* qp     = sym_addr<float>(g_q);
    float* kp     = sym_addr<float>(g_k);
    float* vp     = sym_addr<float>(g_v);
    float* scp    = sym_addr<float>(g_sc);
    float* aop    = sym_addr<float>(g_ao);
    float* op     = sym_addr<float>(g_o);
    float* combp  = sym_addr<float>(g_comb);
    float* mlp1p  = sym_addr<float>(g_mlp1);
    float* ffp    = sym_addr<float>(g_ff);
    float* poolp  = sym_addr<float>(g_pool);
    float* zp     = sym_addr<float>(g_z);
    float* wrp    = sym_addr<float>(g_wr);

    const long long NH = (long long)NN * HD;       // per-batch hidden stride
    const long long SS = (long long)NN * NN;       // per-head score stride
    const int WSQ = HD * HD;                       // 147456

    // ---- pre-round weights to tf32 (rna) ----
    {
        int n1 = 3 * WSQ;           // 442368
        int n2 = 3 * HD * 2 * HD;   // 884736
        round_copy_kernel<<<(n1 + 255) / 256, 256>>>(gcn_W, wrp + WR_GCN, n1);
        round_copy_kernel<<<(n1 + 255) / 256, 256>>>(Wq,    wrp + WR_WQ,  n1);
        round_copy_kernel<<<(n1 + 255) / 256, 256>>>(Wk,    wrp + WR_WK,  n1);
        round_copy_kernel<<<(n1 + 255) / 256, 256>>>(Wv,    wrp + WR_WV,  n1);
        round_copy_kernel<<<(n1 + 255) / 256, 256>>>(Wo,    wrp + WR_WO,  n1);
        round_copy_kernel<<<(n2 + 255) / 256, 256>>>(W1,    wrp + WR_W1,  n2);
        round_copy_kernel<<<(n2 + 255) / 256, 256>>>(W2,    wrp + WR_W2,  n2);
    }

    // ---- encoder (exact fp32: feeds graph build) ----
    feats_kernel<<<(NB * NN * CIN + 255) / 256, 256>>>(x, featsp);
    gemm_f32(featsp, W_enc, b_enc, nullptr, h0p,
             NN, HD, CIN, CIN, HD, HD,
             (long long)NN * CIN, 0, 0, 0, NH, 0, 1, NB, 1.f, false, false);

    // ---- graph build (exact fp32 so kNN selection is stable) ----
    norm_kernel<<<NB * NN, 128>>>(h0p, nhp);
    gemm_f32(nhp, nhp, nullptr, nullptr, simp,
             NN, NN, HD, HD, HD, NN,
             NH, 0, NH, 0, SS, 0, 1, NB, 1.f, true, false);
    topk_warp_kernel<<<NB * NN / 8, 256>>>(simp, knnp);

    // rounded copy of h0 for the tf32 layer stack
    {
        int n = NB * NN * HD;
        round_copy_kernel<<<(n + 255) / 256, 256>>>(h0p, h0rp, n);
    }

    const float* hin = h0rp;
    for (int l = 0; l < NL; l++) {
        const float* scl = lnsc + (l * 3) * HD;
        const float* bil = lnbi + (l * 3) * HD;

        // local GCN branch
        gemm_tf(hin, wrp + WR_GCN + (long long)l * WSQ, gcn_b + l * HD, nullptr, xwp,
                NN, HD, HD, HD, HD, HD, NH, 0, 0, 0, NH, 0, 1, NB, 1.f, false, false, false);
        gcn_agg_ln<<<NB * NN, 128>>>(hin, xwp, knnp, scl, bil, hlocp);

        // attention branch
        gemm_tf(hin, wrp + WR_WQ + (long long)l * WSQ, bq + l * HD, nullptr, qp,
                NN, HD, HD, HD, HD, HD, NH, 0, 0, 0, NH, 0, 1, NB, 1.f, false, false, true);
        gemm_tf(hin, wrp + WR_WK + (long long)l * WSQ, bk + l * HD, nullptr, kp,
                NN, HD, HD, HD, HD, HD, NH, 0, 0, 0, NH, 0, 1, NB, 1.f, false, false, true);
        gemm_tf(hin, wrp + WR_WV + (long long)l * WSQ, bv + l * HD, nullptr, vp,
                NN, HD, HD, HD, HD, HD, NH, 0, 0, 0, NH, 0, 1, NB, 1.f, false, false, true);
        // scores[b,h] = q_h @ k_h^T / sqrt(128)
        gemm_tf(qp, kp, nullptr, nullptr, scp,
                NN, NN, DHE, HD, HD, NN,
                NH, DHE, NH, DHE, (long long)NHE * SS, SS, NHE, NB * NHE,
                0.08838834764831843f, true, false, false);
        softmax_kernel<<<NB * NHE * NN, 256>>>(scp);
        // attn @ V
        gemm_tf(scp, vp, nullptr, nullptr, aop,
                NN, DHE, NN, NN, HD, HD,
                (long long)NHE * SS, SS, NH, DHE, NH, DHE, NHE, NB * NHE,
                1.f, false, false, true);
        gemm_tf(aop, wrp + WR_WO + (long long)l * WSQ, bo + l * HD, nullptr, op,
                NN, HD, HD, HD, HD, HD, NH, 0, 0, 0, NH, 0, 1, NB, 1.f, false, false, false);
        // comb = h_local + LN(hcur + o)   (rounded: feeds MLP GEMMs)
        add_ln_kernel<<<NB * NN, 128>>>(hin, op, hlocp, scl + HD, bil + HD, combp, 1);

        // FFN
        gemm_tf(combp, wrp + WR_W1 + (long long)l * HD * 2 * HD, b1 + l * 2 * HD, nullptr, mlp1p,
                NN, 2 * HD, HD, HD, 2 * HD, 2 * HD,
                NH, 0, 0, 0, (long long)NN * 2 * HD, 0, 1, NB, 1.f, false, true, true);
        gemm_tf(mlp1p, wrp + WR_W2 + (long long)l * 2 * HD * HD, b2 + l * HD, combp, ffp,
                NN, HD, 2 * HD, 2 * HD, HD, HD,
                (long long)NN * 2 * HD, 0, 0, 0, NH, 0, 1, NB, 1.f, false, false, false);
        add_ln_kernel<<<NB * NN, 128>>>(ffp, nullptr, nullptr, scl + 2 * HD, bil + 2 * HD, hcurp, 1);
        hin = hcurp;
    }

    // ---- head ----
    pool_kernel<<<NB, HD>>>(hin, poolp);
    fin1_kernel<<<NB, HD>>>(poolp, lin1_W, lin1_b, zp);
    fin2_kernel<<<NB, 128>>>(zp, lin2_W, lin2_b, outp);
}

// round 5
// speedup vs baseline: 2.6876x; 1.0183x over previous
#include <cuda_runtime.h>
#include <math.h>
#include <stdint.h>

// ---------------- problem constants ----------------
static const int NB   = 8;     // batch
static const int NN   = 1024;  // nodes (32*32)
static const int CIN  = 64;    // input channels
static const int HD   = 384;   // hidden
static const int NL   = 3;     // layers
static const int KNN  = 16;    // k
static const int NHE  = 3;     // heads
static const int DHE  = 128;   // head dim
static const int HD4  = 4 * HD; // 1536 packed width

// ---------------- device scratch (no allocs allowed) ----------------
__device__ float g_feats [NB*NN*CIN];
__device__ float g_h0    [NB*NN*HD];
__device__ float g_h0r   [NB*NN*HD];
__device__ float g_nh    [NB*NN*HD];
__device__ float g_sim   [NB*NN*NN];
__device__ int   g_knn   [NB*NN*KNN];
__device__ float g_hcur  [NB*NN*HD];
__device__ float g_qkvg  [NB*NN*4*HD];   // packed [gcn | q | k | v]
__device__ float g_hloc  [NB*NN*HD];
__device__ float g_sc    [(long long)NB*NHE*NN*NN];
__device__ float g_ao    [NB*NN*HD];
__device__ float g_o     [NB*NN*HD];
__device__ float g_comb  [NB*NN*HD];
__device__ float g_mlp1  [NB*NN*2*HD];
__device__ float g_ff    [NB*NN*HD];
__device__ float g_pool  [NB*HD];
__device__ float g_z     [NB*HD];
// packed fused projection weights [L][384][1536] + biases [L][1536]
__device__ float g_wpack [3*384*1536];
__device__ float g_bpack [3*1536];
// rounded weights: WO, W1, W2
__device__ float g_wr    [2211840];
static const long long WR_WO  = 0;
static const long long WR_W1  = 442368;
static const long long WR_W2  = 1327104;

__device__ __forceinline__ float rna_tf32(float x)
{
    uint32_t r;
    asm("cvt.rna.tf32.f32 %0, %1;" : "=r"(r) : "f"(x));
    return __uint_as_float(r);
}

// ================= fp32 SIMT GEMM (exact path: encoder + cosine-sim) =======
#define BM 128
#define BN 128
#define BKK 8
#define SPAD 132

template<bool TRANSB, bool RELU>
__global__ void __launch_bounds__(256, 2)
gemm_k(const float* __restrict__ A, const float* __restrict__ B,
       const float* __restrict__ bias, const float* __restrict__ Res,
       float* __restrict__ C,
       int M, int Nn, int K, int lda, int ldb, int ldc,
       long long sA, long long sAi, long long sB, long long sBi,
       long long sC, long long sCi, int zi, float alpha)
{
    int bz = blockIdx.z;
    int zo = bz / zi, zin = bz % zi;
    A += zo * sA + zin * sAi;
    B += zo * sB + zin * sBi;
    C += zo * sC + zin * sCi;
    if (Res) Res += zo * sC + zin * sCi;

    int m0 = blockIdx.y * BM;
    int n0 = blockIdx.x * BN;

    __shared__ float As[2][BKK][SPAD];
    __shared__ float Bs[2][BKK][SPAD];

    int tid = threadIdx.x;
    int tx = tid & 15;
    int ty = tid >> 4;

    int a_m = tid >> 1;
    int a_k = (tid & 1) * 4;
    const float* Aload = A + (long long)(m0 + a_m) * lda + a_k;

    const float* Bload;
    int b_k = 0, b_n = 0;
    if (TRANSB) {
        Bload = B + (long long)(n0 + a_m) * ldb + a_k;
    } else {
        b_k = tid >> 5;
        b_n = (tid & 31) * 4;
        Bload = B + (long long)b_k * ldb + n0 + b_n;
    }

    float4 av = *(const float4*)Aload;
    float4 bv = *(const float4*)Bload;

    As[0][a_k + 0][a_m] = av.x;
    As[0][a_k + 1][a_m] = av.y;
    As[0][a_k + 2][a_m] = av.z;
    As[0][a_k + 3][a_m] = av.w;
    if (TRANSB) {
        Bs[0][a_k + 0][a_m] = bv.x;
        Bs[0][a_k + 1][a_m] = bv.y;
        Bs[0][a_k + 2][a_m] = bv.z;
        Bs[0][a_k + 3][a_m] = bv.w;
    } else {
        *(float4*)&Bs[0][b_k][b_n] = bv;
    }
    __syncthreads();

    float acc[8][8];
    #pragma unroll
    for (int i = 0; i < 8; i++)
        #pragma unroll
        for (int j = 0; j < 8; j++) acc[i][j] = 0.f;

    int cur = 0;
    for (int k0 = 0; ; ) {
        int k1 = k0 + BKK;
        bool more = (k1 < K);
        if (more) {
            av = *(const float4*)(Aload + k1);
            if (TRANSB) bv = *(const float4*)(Bload + k1);
            else        bv = *(const float4*)(Bload + (long long)k1 * ldb);
        }

        #pragma unroll
        for (int kk = 0; kk < BKK; kk++) {
            float4 a0 = *(const float4*)&As[cur][kk][ty * 4];
            float4 a1 = *(const float4*)&As[cur][kk][64 + ty * 4];
            float4 b0 = *(const float4*)&Bs[cur][kk][tx * 4];
            float4 b1 = *(const float4*)&Bs[cur][kk][64 + tx * 4];
            float a[8] = {a0.x, a0.y, a0.z, a0.w, a1.x, a1.y, a1.z, a1.w};
            float b[8] = {b0.x, b0.y, b0.z, b0.w, b1.x, b1.y, b1.z, b1.w};
            #pragma unroll
            for (int i = 0; i < 8; i++)
                #pragma unroll
                for (int j = 0; j < 8; j++)
                    acc[i][j] = fmaf(a[i], b[j], acc[i][j]);
        }
        if (!more) break;

        int nxt = cur ^ 1;
        As[nxt][a_k + 0][a_m] = av.x;
        As[nxt][a_k + 1][a_m] = av.y;
        As[nxt][a_k + 2][a_m] = av.z;
        As[nxt][a_k + 3][a_m] = av.w;
        if (TRANSB) {
            Bs[nxt][a_k + 0][a_m] = bv.x;
            Bs[nxt][a_k + 1][a_m] = bv.y;
            Bs[nxt][a_k + 2][a_m] = bv.z;
            Bs[nxt][a_k + 3][a_m] = bv.w;
        } else {
            *(float4*)&Bs[nxt][b_k][b_n] = bv;
        }
        __syncthreads();
        cur = nxt;
        k0 = k1;
    }

    #pragma unroll
    for (int ih = 0; ih < 2; ih++) {
        #pragma unroll
        for (int i = 0; i < 4; i++) {
            int m = m0 + ih * 64 + ty * 4 + i;
            #pragma unroll
            for (int jh = 0; jh < 2; jh++) {
                int n = n0 + jh * 64 + tx * 4;
                float4 r;
                r.x = acc[ih * 4 + i][jh * 4 + 0] * alpha;
                r.y = acc[ih * 4 + i][jh * 4 + 1] * alpha;
                r.z = acc[ih * 4 + i][jh * 4 + 2] * alpha;
                r.w = acc[ih * 4 + i][jh * 4 + 3] * alpha;
                if (bias) {
                    float4 bb = *(const float4*)(bias + n);
                    r.x += bb.x; r.y += bb.y; r.z += bb.z; r.w += bb.w;
                }
                if (Res) {
                    float4 rr = *(const float4*)(Res + (long long)m * ldc + n);
                    r.x += rr.x; r.y += rr.y; r.z += rr.z; r.w += rr.w;
                }
                if (RELU) {
                    r.x = fmaxf(r.x, 0.f); r.y = fmaxf(r.y, 0.f);
                    r.z = fmaxf(r.z, 0.f); r.w = fmaxf(r.w, 0.f);
                }
                *(float4*)(C + (long long)m * ldc + n) = r;
            }
        }
    }
}

// ================= tf32 tensor-core GEMM with cp.async ====================
// Inputs MUST be pre-rounded to tf32 (rna). 128xNTILE block, BK=16, 8 warps
// (4m x 2n), warp tile 32x(NTILE/2), mma.m16n8k8, 2-stage cp.async pipeline.
#define ASTRIDE 20
#define BN128STR 136
#define BN64STR  68

__device__ __forceinline__ void cpa16(void* dst, const void* src)
{
    uint32_t s = (uint32_t)__cvta_generic_to_shared(dst);
    asm volatile("cp.async.cg.shared.global [%0], [%1], 16;" :: "r"(s), "l"(src));
}

template<bool TRANSB, bool RELU, bool TF32OUT, int NTILE>
__global__ void __launch_bounds__(256, 2)
tf32gemm_k(const float* __restrict__ A, const float* __restrict__ B,
           const float* __restrict__ bias, const float* __restrict__ Res,
           float* __restrict__ C,
           int K, int lda, int ldb, int ldc,
           long long sA, long long sAi, long long sB, long long sBi,
           long long sC, long long sCi, int zi, float alpha)
{
    constexpr int NT = NTILE / 16;            // 8 or 4 n-frags per warp
    constexpr int BSTR = (NTILE == 128) ? BN128STR : BN64STR;

    int bz = blockIdx.z;
    int zo = bz / zi, zin = bz % zi;
    A += zo * sA + zin * sAi;
    B += zo * sB + zin * sBi;
    C += zo * sC + zin * sCi;
    if (Res) Res += zo * sC + zin * sCi;

    int m0 = blockIdx.y * 128;
    int n0 = blockIdx.x * NTILE;

    __shared__ __align__(16) float As[2][128 * ASTRIDE];
    constexpr int BSZ = TRANSB ? (NTILE * ASTRIDE) : (16 * BSTR);
    __shared__ __align__(16) float Bs[2][BSZ];

    int tid = threadIdx.x;
    int lane = tid & 31;
    int wid = tid >> 5;
    int wm = (wid & 3) * 32;
    int wn = (wid >> 2) * (NTILE / 2);
    int tig = lane & 3;
    int grp = lane >> 2;

    // A cp.async map: 128 rows x 16 cols -> 2 float4 per thread
    int ra = tid >> 2;           // 0..63
    int ca = (tid & 3) * 4;      // 0,4,8,12
    const float* Asrc0 = A + (long long)(m0 + ra) * lda + ca;
    const float* Asrc1 = A + (long long)(m0 + ra + 64) * lda + ca;
    int aoff0 = ra * ASTRIDE + ca;
    int aoff1 = (ra + 64) * ASTRIDE + ca;

    const float *Bsrc0 = nullptr, *Bsrc1 = nullptr;
    int boff0 = 0, boff1 = 0;
    if (TRANSB) {
        if (NTILE == 128) {
            Bsrc0 = B + (long long)(n0 + ra) * ldb + ca;
            Bsrc1 = B + (long long)(n0 + ra + 64) * ldb + ca;
            boff0 = aoff0;
            boff1 = aoff1;
        } else {
            Bsrc0 = B + (long long)(n0 + ra) * ldb + ca;
            boff0 = ra * ASTRIDE + ca;
        }
    } else {
        if (NTILE == 128) {
            int rb = tid >> 5;            // 0..7
            int cb = (tid & 31) * 4;      // 0..124
            Bsrc0 = B + (long long)rb * ldb + n0 + cb;
            Bsrc1 = B + (long long)(rb + 8) * ldb + n0 + cb;
            boff0 = rb * BSTR + cb;
            boff1 = (rb + 8) * BSTR + cb;
        } else {
            int rb = tid >> 4;            // 0..15
            int cb = (tid & 15) * 4;      // 0..60
            Bsrc0 = B + (long long)rb * ldb + n0 + cb;
            boff0 = rb * BSTR + cb;
        }
    }
    constexpr bool BTWO = (NTILE == 128);

    // stage-0 prefetch
    {
        cpa16(&As[0][aoff0], Asrc0);
        cpa16(&As[0][aoff1], Asrc1);
        cpa16(&Bs[0][boff0], Bsrc0);
        if (BTWO) cpa16(&Bs[0][boff1], Bsrc1);
        asm volatile("cp.async.commit_group;");
    }

    float acc[2][NT][4];
    #pragma unroll
    for (int mt = 0; mt < 2; mt++)
        #pragma unroll
        for (int nt = 0; nt < NT; nt++)
            #pragma unroll
            for (int r = 0; r < 4; r++) acc[mt][nt][r] = 0.f;

    int cur = 0;
    int k0 = 0;
    for (;;) {
        int k1 = k0 + 16;
        bool more = (k1 < K);
        if (more) {
            int nxt = cur ^ 1;
            cpa16(&As[nxt][aoff0], Asrc0 + k1);
            cpa16(&As[nxt][aoff1], Asrc1 + k1);
            if (TRANSB) {
                cpa16(&Bs[nxt][boff0], Bsrc0 + k1);
                if (BTWO) cpa16(&Bs[nxt][boff1], Bsrc1 + k1);
            } else {
                cpa16(&Bs[nxt][boff0], Bsrc0 + (long long)k1 * ldb);
                if (BTWO) cpa16(&Bs[nxt][boff1], Bsrc1 + (long long)k1 * ldb);
            }
            asm volatile("cp.async.commit_group;");
            asm volatile("cp.async.wait_group 1;");
        } else {
            asm volatile("cp.async.wait_group 0;");
        }
        __syncthreads();

        #pragma unroll
        for (int ks = 0; ks < 16; ks += 8) {
            uint32_t af[2][4], bf[NT][2];
            #pragma unroll
            for (int mt = 0; mt < 2; mt++) {
                int mA = wm + mt * 16 + grp;
                af[mt][0] = __float_as_uint(As[cur][mA * ASTRIDE + ks + tig]);
                af[mt][1] = __float_as_uint(As[cur][(mA + 8) * ASTRIDE + ks + tig]);
                af[mt][2] = __float_as_uint(As[cur][mA * ASTRIDE + ks + tig + 4]);
                af[mt][3] = __float_as_uint(As[cur][(mA + 8) * ASTRIDE + ks + tig + 4]);
            }
            #pragma unroll
            for (int nt = 0; nt < NT; nt++) {
                int nB = wn + nt * 8 + grp;
                if (TRANSB) {
                    bf[nt][0] = __float_as_uint(Bs[cur][nB * ASTRIDE + ks + tig]);
                    bf[nt][1] = __float_as_uint(Bs[cur][nB * ASTRIDE + ks + tig + 4]);
                } else {
                    bf[nt][0] = __float_as_uint(Bs[cur][(ks + tig) * BSTR + nB]);
                    bf[nt][1] = __float_as_uint(Bs[cur][(ks + tig + 4) * BSTR + nB]);
                }
            }
            #pragma unroll
            for (int mt = 0; mt < 2; mt++)
                #pragma unroll
                for (int nt = 0; nt < NT; nt++) {
                    asm volatile(
                        "mma.sync.aligned.m16n8k8.row.col.f32.tf32.tf32.f32 "
                        "{%0,%1,%2,%3}, {%4,%5,%6,%7}, {%8,%9}, {%0,%1,%2,%3};"
                        : "+f"(acc[mt][nt][0]), "+f"(acc[mt][nt][1]),
                          "+f"(acc[mt][nt][2]), "+f"(acc[mt][nt][3])
                        : "r"(af[mt][0]), "r"(af[mt][1]), "r"(af[mt][2]), "r"(af[mt][3]),
                          "r"(bf[nt][0]), "r"(bf[nt][1]));
                }
        }
        if (!more) break;
        __syncthreads();
        cur ^= 1;
        k0 = k1;
    }

    // epilogue
    #pragma unroll
    for (int mt = 0; mt < 2; mt++) {
        #pragma unroll
        for (int half = 0; half < 2; half++) {
            int m = m0 + wm + mt * 16 + grp + half * 8;
            #pragma unroll
            for (int nt = 0; nt < NT; nt++) {
                int n = n0 + wn + nt * 8 + 2 * tig;
                float2 r;
                r.x = acc[mt][nt][half * 2 + 0] * alpha;
                r.y = acc[mt][nt][half * 2 + 1] * alpha;
                if (bias) {
                    r.x += bias[n];
                    r.y += bias[n + 1];
                }
                if (Res) {
                    const float2 rr = *(const float2*)(Res + (long long)m * ldc + n);
                    r.x += rr.x; r.y += rr.y;
                }
                if (RELU) {
                    r.x = fmaxf(r.x, 0.f);
                    r.y = fmaxf(r.y, 0.f);
                }
                if (TF32OUT) {
                    r.x = rna_tf32(r.x);
                    r.y = rna_tf32(r.y);
                }
                *(float2*)(C + (long long)m * ldc + n) = r;
            }
        }
    }
}

// ---------------- small kernels ----------------
__global__ void feats_kernel(const float* __restrict__ x, float* __restrict__ feats)
{
    long long i = (long long)blockIdx.x * blockDim.x + threadIdx.x;
    if (i >= (long long)NB * NN * CIN) return;
    int c = (int)(i & (CIN - 1));
    long long bn = i >> 6;
    int n = (int)(bn & (NN - 1));
    int b = (int)(bn >> 10);
    feats[i] = x[((long long)b * CIN + c) * NN + n];
}

__global__ void round_copy_kernel(const float* __restrict__ src, float* __restrict__ dst, int n)
{
    int i = blockIdx.x * blockDim.x + threadIdx.x;
    if (i < n) dst[i] = rna_tf32(src[i]);
}

// pack [L][384][1536] = [gcn | Wq | Wk | Wv], tf32-rounded
__global__ void pack_w_kernel(const float* __restrict__ gcn_W, const float* __restrict__ Wq,
                              const float* __restrict__ Wk, const float* __restrict__ Wv,
                              float* __restrict__ dst)
{
    int i = blockIdx.x * blockDim.x + threadIdx.x;
    if (i >= 3 * 384 * 1536) return;
    int l = i / (384 * 1536);
    int rem = i - l * (384 * 1536);
    int r = rem / 1536;
    int c = rem - r * 1536;
    int sel = c / 384, cc = c - sel * 384;
    const float* src = (sel == 0) ? gcn_W : (sel == 1) ? Wq : (sel == 2) ? Wk : Wv;
    dst[i] = rna_tf32(src[((long long)l * 384 + r) * 384 + cc]);
}

__global__ void pack_b_kernel(const float* __restrict__ gcn_b, const float* __restrict__ bq,
                              const float* __restrict__ bk, const float* __restrict__ bv,
                              float* __restrict__ dst)
{
    int i = blockIdx.x * blockDim.x + threadIdx.x;
    if (i >= 3 * 1536) return;
    int l = i / 1536;
    int c = i - l * 1536;
    int sel = c / 384, cc = c - sel * 384;
    const float* src = (sel == 0) ? gcn_b : (sel == 1) ? bq : (sel == 2) ? bk : bv;
    dst[i] = src[l * 384 + cc];
}

__device__ __forceinline__ void block_reduce2(float& s1, float& s2)
{
    __shared__ float b1[4], b2[4];
    #pragma unroll
    for (int o = 16; o > 0; o >>= 1) {
        s1 += __shfl_down_sync(0xffffffffu, s1, o);
        s2 += __shfl_down_sync(0xffffffffu, s2, o);
    }
    int w = threadIdx.x >> 5;
    if ((threadIdx.x & 31) == 0) { b1[w] = s1; b2[w] = s2; }
    __syncthreads();
    s1 = b1[0] + b1[1] + b1[2] + b1[3];
    s2 = b2[0] + b2[1] + b2[2] + b2[3];
}

__global__ void norm_kernel(const float* __restrict__ h0, float* __restrict__ nh)
{
    long long bn = blockIdx.x;
    int t = threadIdx.x; // 128
    const float* r = h0 + bn * HD;
    float v0 = r[t], v1 = r[t + 128], v2 = r[t + 256];
    float ss = v0 * v0 + v1 * v1 + v2 * v2, dummy = 0.f;
    block_reduce2(ss, dummy);
    float rinv = rsqrtf(ss);
    float* o = nh + bn * HD;
    o[t] = v0 * rinv; o[t + 128] = v1 * rinv; o[t + 256] = v2 * rinv;
}

__global__ void topk_warp_kernel(const float* __restrict__ sim, int* __restrict__ knn)
{
    int warp = blockIdx.x * (blockDim.x >> 5) + (threadIdx.x >> 5);
    if (warp >= NB * NN) return;
    int lane = threadIdx.x & 31;
    int n = warp & (NN - 1);
    const float* row = sim + (long long)warp * NN;
    float v[32];
    #pragma unroll
    for (int j = 0; j < 32; j++) {
        int m = j * 32 + lane;
        v[j] = (m == n) ? -3e38f : row[m];
    }
    unsigned taken = 0;
    int* o = knn + (long long)warp * KNN;
    for (int r = 0; r < KNN; r++) {
        float bv = -3e38f; int bj = 0;
        #pragma unroll
        for (int j = 0; j < 32; j++) {
            bool free_ = !((taken >> j) & 1u);
            if (free_ && v[j] > bv) { bv = v[j]; bj = j; }
        }
        int bidx = bj * 32 + lane;
        #pragma unroll
        for (int off = 16; off > 0; off >>= 1) {
            float ov = __shfl_xor_sync(0xffffffffu, bv, off);
            int   oi = __shfl_xor_sync(0xffffffffu, bidx, off);
            if (ov > bv || (ov == bv && oi < bidx)) { bv = ov; bidx = oi; }
        }
        if ((bidx & 31) == lane) taken |= 1u << (bidx >> 5);
        if (lane == 0) o[r] = bidx;
    }
}

// h_local = LN(hcur + (sum_{j in knn} xw[j] + xw[self]) / 17); xw strided LDX
__global__ void gcn_agg_ln(const float* __restrict__ hcur, const float* __restrict__ xw,
                           int ldx,
                           const int* __restrict__ knn,
                           const float* __restrict__ scale, const float* __restrict__ bias,
                           float* __restrict__ out)
{
    int bn = blockIdx.x;
    int b = bn >> 10;
    int t = threadIdx.x; // 128
    __shared__ int sidx[KNN];
    if (t < KNN) sidx[t] = knn[(long long)bn * KNN + t];
    __syncthreads();
    const float* xr = xw + (long long)bn * ldx;
    float a0 = xr[t], a1 = xr[t + 128], a2 = xr[t + 256];
    #pragma unroll 4
    for (int j = 0; j < KNN; j++) {
        const float* r = xw + ((long long)(b * NN) + sidx[j]) * ldx;
        a0 += r[t]; a1 += r[t + 128]; a2 += r[t + 256];
    }
    const float* h = hcur + (long long)bn * HD;
    const float inv17 = 1.f / 17.f;
    float v0 = h[t] + a0 * inv17;
    float v1 = h[t + 128] + a1 * inv17;
    float v2 = h[t + 256] + a2 * inv17;
    float s1 = v0 + v1 + v2;
    float s2 = v0 * v0 + v1 * v1 + v2 * v2;
    block_reduce2(s1, s2);
    float mu = s1 * (1.f / HD);
    float var = s2 * (1.f / HD) - mu * mu;
    float rstd = rsqrtf(var + 1e-5f);
    float* o = out + (long long)bn * HD;
    o[t]       = (v0 - mu) * rstd * scale[t]       + bias[t];
    o[t + 128] = (v1 - mu) * rstd * scale[t + 128] + bias[t + 128];
    o[t + 256] = (v2 - mu) * rstd * scale[t + 256] + bias[t + 256];
}

// out = (plus? plus : 0) + LN(a + (b? b : 0)); optional tf32 rounding of out
__global__ void add_ln_kernel(const float* __restrict__ a, const float* __restrict__ b,
                              const float* __restrict__ plus,
                              const float* __restrict__ scale, const float* __restrict__ bias,
                              float* __restrict__ out, int rnd)
{
    long long bn = blockIdx.x;
    int t = threadIdx.x; // 128
    const float* ar = a + bn * HD;
    float v0 = ar[t], v1 = ar[t + 128], v2 = ar[t + 256];
    if (b) {
        const float* br = b + bn * HD;
        v0 += br[t]; v1 += br[t + 128]; v2 += br[t + 256];
    }
    float s1 = v0 + v1 + v2;
    float s2 = v0 * v0 + v1 * v1 + v2 * v2;
    block_reduce2(s1, s2);
    float mu = s1 * (1.f / HD);
    float var = s2 * (1.f / HD) - mu * mu;
    float rstd = rsqrtf(var + 1e-5f);
    float y0 = (v0 - mu) * rstd * scale[t]       + bias[t];
    float y1 = (v1 - mu) * rstd * scale[t + 128] + bias[t + 128];
    float y2 = (v2 - mu) * rstd * scale[t + 256] + bias[t + 256];
    if (plus) {
        const float* pr = plus + bn * HD;
        y0 += pr[t]; y1 += pr[t + 128]; y2 += pr[t + 256];
    }
    if (rnd) { y0 = rna_tf32(y0); y1 = rna_tf32(y1); y2 = rna_tf32(y2); }
    float* o = out + bn * HD;
    o[t] = y0; o[t + 128] = y1; o[t + 256] = y2;
}

__global__ void softmax_kernel(float* __restrict__ sc)
{
    long long r = blockIdx.x;
    float* row = sc + r * (long long)NN;
    int t = threadIdx.x; // 256
    float x0 = row[t], x1 = row[t + 256], x2 = row[t + 512], x3 = row[t + 768];
    float m = fmaxf(fmaxf(x0, x1), fmaxf(x2, x3));
    __shared__ float bm[8], bs[8];
    #pragma unroll
    for (int o = 16; o > 0; o >>= 1) m = fmaxf(m, __shfl_down_sync(0xffffffffu, m, o));
    if ((t & 31) == 0) bm[t >> 5] = m;
    __syncthreads();
    float mm = bm[0];
    #pragma unroll
    for (int i = 1; i < 8; i++) mm = fmaxf(mm, bm[i]);
    float e0 = __expf(x0 - mm), e1 = __expf(x1 - mm), e2 = __expf(x2 - mm), e3 = __expf(x3 - mm);
    float s = e0 + e1 + e2 + e3;
    #pragma unroll
    for (int o = 16; o > 0; o >>= 1) s += __shfl_down_sync(0xffffffffu, s, o);
    if ((t & 31) == 0) bs[t >> 5] = s;
    __syncthreads();
    float ssum = bs[0] + bs[1] + bs[2] + bs[3] + bs[4] + bs[5] + bs[6] + bs[7];
    float inv = 1.f / ssum;
    row[t]       = rna_tf32(e0 * inv);
    row[t + 256] = rna_tf32(e1 * inv);
    row[t + 512] = rna_tf32(e2 * inv);
    row[t + 768] = rna_tf32(e3 * inv);
}

__global__ void pool_kernel(const float* __restrict__ h, float* __restrict__ pooled)
{
    int b = blockIdx.x;
    int t = threadIdx.x; // 384
    float s = 0.f;
    const float* base = h + (long long)b * NN * HD + t;
    for (int n = 0; n < NN; n++) s += base[(long long)n * HD];
    pooled[b * HD + t] = s * (1.f / NN);
}

__global__ void fin1_kernel(const float* __restrict__ pooled, const float* __restrict__ W,
                            const float* __restrict__ bias, float* __restrict__ z)
{
    int b = blockIdx.x;
    int j = threadIdx.x; // 384
    const float* p = pooled + b * HD;
    float s = bias[j];
    for (int k = 0; k < HD; k++) s = fmaf(p[k], W[k * HD + j], s);
    z[b * HD + j] = fmaxf(s, 0.f);
}

__global__ void fin2_kernel(const float* __restrict__ z, const float* __restrict__ W,
                            const float* __restrict__ bias, float* __restrict__ out)
{
    int b = blockIdx.x;
    int j = threadIdx.x; // 128
    const float* p = z + b * HD;
    float s = bias[j];
    for (int k = 0; k < HD; k++) s = fmaf(p[k], W[k * 128 + j], s);
    out[b * 128 + j] = s;
}

// ---------------- host-side GEMM dispatchers ----------------
static void gemm_f32(const float* A, const float* B, const float* bias, const float* Res, float* C,
                     int M, int Nn, int K, int lda, int ldb, int ldc,
                     long long sA, long long sAi, long long sB, long long sBi,
                     long long sC, long long sCi, int zi, int nz,
                     float alpha, bool transb, bool relu)
{
    dim3 grid(Nn / BN, M / BM, nz), block(256);
    if (transb) {
        if (relu) gemm_k<true, true ><<<grid, block>>>(A, B, bias, Res, C, M, Nn, K, lda, ldb, ldc, sA, sAi, sB, sBi, sC, sCi, zi, alpha);
        else      gemm_k<true, false><<<grid, block>>>(A, B, bias, Res, C, M, Nn, K, lda, ldb, ldc, sA, sAi, sB, sBi, sC, sCi, zi, alpha);
    } else {
        if (relu) gemm_k<false, true ><<<grid, block>>>(A, B, bias, Res, C, M, Nn, K, lda, ldb, ldc, sA, sAi, sB, sBi, sC, sCi, zi, alpha);
        else      gemm_k<false, false><<<grid, block>>>(A, B, bias, Res, C, M, Nn, K, lda, ldb, ldc, sA, sAi, sB, sBi, sC, sCi, zi, alpha);
    }
}

static void gemm_tf(const float* A, const float* B, const float* bias, const float* Res, float* C,
                    int M, int Nn, int K, int lda, int ldb, int ldc,
                    long long sA, long long sAi, long long sB, long long sBi,
                    long long sC, long long sCi, int zi, int nz,
                    float alpha, bool transb, bool relu, bool tf32out, int ntile)
{
    dim3 grid(Nn / ntile, M / 128, nz), block(256);
    #define DISP(TB, RL, TO, NTL) tf32gemm_k<TB, RL, TO, NTL><<<grid, block>>>(A, B, bias, Res, C, K, lda, ldb, ldc, sA, sAi, sB, sBi, sC, sCi, zi, alpha)
    if (ntile == 128) {
        if (transb) {
            if (relu)  { if (tf32out) DISP(true, true, true, 128);  else DISP(true, true, false, 128); }
            else       { if (tf32out) DISP(true, false, true, 128); else DISP(true, false, false, 128); }
        } else {
            if (relu)  { if (tf32out) DISP(false, true, true, 128);  else DISP(false, true, false, 128); }
            else       { if (tf32out) DISP(false, false, true, 128); else DISP(false, false, false, 128); }
        }
    } else {
        if (transb) {
            if (relu)  { if (tf32out) DISP(true, true, true, 64);  else DISP(true, true, false, 64); }
            else       { if (tf32out) DISP(true, false, true, 64); else DISP(true, false, false, 64); }
        } else {
            if (relu)  { if (tf32out) DISP(false, true, true, 64);  else DISP(false, true, false, 64); }
            else       { if (tf32out) DISP(false, false, true, 64); else DISP(false, false, false, 64); }
        }
    }
    #undef DISP
}

template<typename T> static T* sym_addr(const void* sym)
{
    void* p = nullptr;
    cudaGetSymbolAddress(&p, sym);
    return (T*)p;
}

extern "C" void kernel_launch(void* const* d_in, const int* in_sizes, int n_in,
                              void* d_out, int out_size)
{
    const float* x      = (const float*)d_in[0];
    const float* W_enc  = (const float*)d_in[1];
    const float* b_enc  = (const float*)d_in[2];
    const float* gcn_W  = (const float*)d_in[3];
    const float* gcn_b  = (const float*)d_in[4];
    const float* Wq     = (const float*)d_in[5];
    const float* bq     = (const float*)d_in[6];
    const float* Wk     = (const float*)d_in[7];
    const float* bk     = (const float*)d_in[8];
    const float* Wv     = (const float*)d_in[9];
    const float* bv     = (const float*)d_in[10];
    const float* Wo     = (const float*)d_in[11];
    const float* bo     = (const float*)d_in[12];
    const float* lnsc   = (const float*)d_in[13];
    const float* lnbi   = (const float*)d_in[14];
    const float* W1     = (const float*)d_in[15];
    const float* b1     = (const float*)d_in[16];
    const float* W2     = (const float*)d_in[17];
    const float* b2     = (const float*)d_in[18];
    const float* lin1_W = (const float*)d_in[19];
    const float* lin1_b = (const float*)d_in[20];
    const float* lin2_W = (const float*)d_in[21];
    const float* lin2_b = (const float*)d_in[22];
    float* outp = (float*)d_out;

    float* featsp = sym_addr<float>(g_feats);
    float* h0p    = sym_addr<float>(g_h0);
    float* h0rp   = sym_addr<float>(g_h0r);
    float* nhp    = sym_addr<float>(g_nh);
    float* simp   = sym_addr<float>(g_sim);
    int*   knnp   = sym_addr<int>(g_knn);
    float* hcurp  = sym_addr<float>(g_hcur);
    float* qkvgp  = sym_addr<float>(g_qkvg);
    float* hlocp  = sym_addr<float>(g_hloc);
    float* scp    = sym_addr<float>(g_sc);
    float* aop    = sym_addr<float>(g_ao);
    float* op     = sym_addr<float>(g_o);
    float* combp  = sym_addr<float>(g_comb);
    float* mlp1p  = sym_addr<float>(g_mlp1);
    float* ffp    = sym_addr<float>(g_ff);
    float* poolp  = sym_addr<float>(g_pool);
    float* zp     = sym_addr<float>(g_z);
    float* wpackp = sym_addr<float>(g_wpack);
    float* bpackp = sym_addr<float>(g_bpack);
    float* wrp    = sym_addr<float>(g_wr);

    const long long NH  = (long long)NN * HD;      // per-batch hidden stride
    const long long NH4 = (long long)NN * HD4;     // per-batch packed stride
    const long long SS  = (long long)NN * NN;      // per-head score stride
    const int WSQ = HD * HD;                       // 147456

    // ---- weight prep ----
    pack_w_kernel<<<(3 * 384 * 1536 + 255) / 256, 256>>>(gcn_W, Wq, Wk, Wv, wpackp);
    pack_b_kernel<<<(3 * 1536 + 255) / 256, 256>>>(gcn_b, bq, bk, bv, bpackp);
    round_copy_kernel<<<(3 * WSQ + 255) / 256, 256>>>(Wo, wrp + WR_WO, 3 * WSQ);
    round_copy_kernel<<<(3 * HD * 2 * HD + 255) / 256, 256>>>(W1, wrp + WR_W1, 3 * HD * 2 * HD);
    round_copy_kernel<<<(3 * 2 * HD * HD + 255) / 256, 256>>>(W2, wrp + WR_W2, 3 * 2 * HD * HD);

    // ---- encoder (exact fp32: feeds graph build) ----
    feats_kernel<<<(NB * NN * CIN + 255) / 256, 256>>>(x, featsp);
    gemm_f32(featsp, W_enc, b_enc, nullptr, h0p,
             NN, HD, CIN, CIN, HD, HD,
             (long long)NN * CIN, 0, 0, 0, NH, 0, 1, NB, 1.f, false, false);

    // ---- graph build (exact fp32 so kNN selection is stable) ----
    norm_kernel<<<NB * NN, 128>>>(h0p, nhp);
    gemm_f32(nhp, nhp, nullptr, nullptr, simp,
             NN, NN, HD, HD, HD, NN,
             NH, 0, NH, 0, SS, 0, 1, NB, 1.f, true, false);
    topk_warp_kernel<<<NB * NN / 8, 256>>>(simp, knnp);

    // rounded copy of h0 for the tf32 layer stack
    round_copy_kernel<<<(NB * NN * HD + 255) / 256, 256>>>(h0p, h0rp, NB * NN * HD);

    const float* hin = h0rp;
    for (int l = 0; l < NL; l++) {
        const float* scl = lnsc + (l * 3) * HD;
        const float* bil = lnbi + (l * 3) * HD;

        // fused projection: [gcn | q | k | v] in one N=1536 GEMM (tf32-rounded out)
        gemm_tf(hin, wpackp + (long long)l * HD * HD4, bpackp + l * HD4, nullptr, qkvgp,
                NN, HD4, HD, HD, HD4, HD4, NH, 0, 0, 0, NH4, 0, 1, NB,
                1.f, false, false, true, 128);

        // local GCN branch (xw = cols [0,384) of packed output)
        gcn_agg_ln<<<NB * NN, 128>>>(hin, qkvgp, HD4, knnp, scl, bil, hlocp);

        // scores[b,h] = q_h @ k_h^T / sqrt(128)
        gemm_tf(qkvgp + HD, qkvgp + 2 * HD, nullptr, nullptr, scp,
                NN, NN, DHE, HD4, HD4, NN,
                NH4, DHE, NH4, DHE, (long long)NHE * SS, SS, NHE, NB * NHE,
                0.08838834764831843f, true, false, false, 128);
        softmax_kernel<<<NB * NHE * NN, 256>>>(scp);
        // attn @ V  (N=128 per head -> BN=64 tiles)
        gemm_tf(scp, qkvgp + 3 * HD, nullptr, nullptr, aop,
                NN, DHE, NN, NN, HD4, HD,
                (long long)NHE * SS, SS, NH4, DHE, NH, DHE, NHE, NB * NHE,
                1.f, false, false, true, 64);
        gemm_tf(aop, wrp + WR_WO + (long long)l * WSQ, bo + l * HD, nullptr, op,
                NN, HD, HD, HD, HD, HD, NH, 0, 0, 0, NH, 0, 1, NB,
                1.f, false, false, false, 64);
        // comb = h_local + LN(hcur + o)   (rounded: feeds MLP GEMMs)
        add_ln_kernel<<<NB * NN, 128>>>(hin, op, hlocp, scl + HD, bil + HD, combp, 1);

        // FFN
        gemm_tf(combp, wrp + WR_W1 + (long long)l * HD * 2 * HD, b1 + l * 2 * HD, nullptr, mlp1p,
                NN, 2 * HD, HD, HD, 2 * HD, 2 * HD,
                NH, 0, 0, 0, (long long)NN * 2 * HD, 0, 1, NB, 1.f, false, true, true, 128);
        gemm_tf(mlp1p, wrp + WR_W2 + (long long)l * 2 * HD * HD, b2 + l * HD, combp, ffp,
                NN, HD, 2 * HD, 2 * HD, HD, HD,
                (long long)NN * 2 * HD, 0, 0, 0, NH, 0, 1, NB, 1.f, false, false, false, 64);
        add_ln_kernel<<<NB * NN, 128>>>(ffp, nullptr, nullptr, scl + 2 * HD, bil + 2 * HD, hcurp, 1);
        hin = hcurp;
    }

    // ---- head ----
    pool_kernel<<<NB, HD>>>(hin, poolp);
    fin1_kernel<<<NB, HD>>>(poolp, lin1_W, lin1_b, zp);
    fin2_kernel<<<NB, 128>>>(zp, lin2_W, lin2_b, outp);
}

// round 6
// speedup vs baseline: 2.9030x; 1.0801x over previous
#include <cuda_runtime.h>
#include <math.h>
#include <stdint.h>

// ---------------- problem constants ----------------
static const int NB   = 8;     // batch
static const int NN   = 1024;  // nodes (32*32)
static const int CIN  = 64;    // input channels
static const int HD   = 384;   // hidden
static const int NL   = 3;     // layers
static const int KNN  = 16;    // k
static const int NHE  = 3;     // heads
static const int DHE  = 128;   // head dim
static const int HD4  = 4 * HD; // 1536 packed width

// ---------------- device scratch (no allocs allowed) ----------------
__device__ float g_feats [NB*NN*CIN];
__device__ float g_h0    [NB*NN*HD];
__device__ float g_h0r   [NB*NN*HD];
__device__ float g_nh    [NB*NN*HD];
__device__ float g_sim   [NB*NN*NN];
__device__ int   g_knn   [NB*NN*KNN];
__device__ float g_hcur  [NB*NN*HD];
__device__ float g_qkvg  [NB*NN*4*HD];   // packed [gcn | q | k | v]
__device__ float g_hloc  [NB*NN*HD];
__device__ float g_ao    [NB*NN*HD];
__device__ float g_o     [NB*NN*HD];
__device__ float g_comb  [NB*NN*HD];
__device__ float g_mlp1  [NB*NN*2*HD];
__device__ float g_ff    [NB*NN*HD];
__device__ float g_pool  [NB*HD];
__device__ float g_z     [NB*HD];
// packed fused projection weights [L][384][1536] + biases [L][1536]
__device__ float g_wpack [3*384*1536];
__device__ float g_bpack [3*1536];
// rounded weights: WO, W1, W2
__device__ float g_wr    [2211840];
static const long long WR_WO  = 0;
static const long long WR_W1  = 442368;
static const long long WR_W2  = 1327104;

__device__ __forceinline__ float rna_tf32(float x)
{
    uint32_t r;
    asm("cvt.rna.tf32.f32 %0, %1;" : "=r"(r) : "f"(x));
    return __uint_as_float(r);
}

// ================= fp32 SIMT GEMM (exact path: encoder + cosine-sim) =======
#define BM 128
#define BN 128
#define BKK 8
#define SPAD 132

template<bool TRANSB, bool RELU>
__global__ void __launch_bounds__(256, 2)
gemm_k(const float* __restrict__ A, const float* __restrict__ B,
       const float* __restrict__ bias, const float* __restrict__ Res,
       float* __restrict__ C,
       int M, int Nn, int K, int lda, int ldb, int ldc,
       long long sA, long long sAi, long long sB, long long sBi,
       long long sC, long long sCi, int zi, float alpha)
{
    int bz = blockIdx.z;
    int zo = bz / zi, zin = bz % zi;
    A += zo * sA + zin * sAi;
    B += zo * sB + zin * sBi;
    C += zo * sC + zin * sCi;
    if (Res) Res += zo * sC + zin * sCi;

    int m0 = blockIdx.y * BM;
    int n0 = blockIdx.x * BN;

    __shared__ float As[2][BKK][SPAD];
    __shared__ float Bs[2][BKK][SPAD];

    int tid = threadIdx.x;
    int tx = tid & 15;
    int ty = tid >> 4;

    int a_m = tid >> 1;
    int a_k = (tid & 1) * 4;
    const float* Aload = A + (long long)(m0 + a_m) * lda + a_k;

    const float* Bload;
    int b_k = 0, b_n = 0;
    if (TRANSB) {
        Bload = B + (long long)(n0 + a_m) * ldb + a_k;
    } else {
        b_k = tid >> 5;
        b_n = (tid & 31) * 4;
        Bload = B + (long long)b_k * ldb + n0 + b_n;
    }

    float4 av = *(const float4*)Aload;
    float4 bv = *(const float4*)Bload;

    As[0][a_k + 0][a_m] = av.x;
    As[0][a_k + 1][a_m] = av.y;
    As[0][a_k + 2][a_m] = av.z;
    As[0][a_k + 3][a_m] = av.w;
    if (TRANSB) {
        Bs[0][a_k + 0][a_m] = bv.x;
        Bs[0][a_k + 1][a_m] = bv.y;
        Bs[0][a_k + 2][a_m] = bv.z;
        Bs[0][a_k + 3][a_m] = bv.w;
    } else {
        *(float4*)&Bs[0][b_k][b_n] = bv;
    }
    __syncthreads();

    float acc[8][8];
    #pragma unroll
    for (int i = 0; i < 8; i++)
        #pragma unroll
        for (int j = 0; j < 8; j++) acc[i][j] = 0.f;

    int cur = 0;
    for (int k0 = 0; ; ) {
        int k1 = k0 + BKK;
        bool more = (k1 < K);
        if (more) {
            av = *(const float4*)(Aload + k1);
            if (TRANSB) bv = *(const float4*)(Bload + k1);
            else        bv = *(const float4*)(Bload + (long long)k1 * ldb);
        }

        #pragma unroll
        for (int kk = 0; kk < BKK; kk++) {
            float4 a0 = *(const float4*)&As[cur][kk][ty * 4];
            float4 a1 = *(const float4*)&As[cur][kk][64 + ty * 4];
            float4 b0 = *(const float4*)&Bs[cur][kk][tx * 4];
            float4 b1 = *(const float4*)&Bs[cur][kk][64 + tx * 4];
            float a[8] = {a0.x, a0.y, a0.z, a0.w, a1.x, a1.y, a1.z, a1.w};
            float b[8] = {b0.x, b0.y, b0.z, b0.w, b1.x, b1.y, b1.z, b1.w};
            #pragma unroll
            for (int i = 0; i < 8; i++)
                #pragma unroll
                for (int j = 0; j < 8; j++)
                    acc[i][j] = fmaf(a[i], b[j], acc[i][j]);
        }
        if (!more) break;

        int nxt = cur ^ 1;
        As[nxt][a_k + 0][a_m] = av.x;
        As[nxt][a_k + 1][a_m] = av.y;
        As[nxt][a_k + 2][a_m] = av.z;
        As[nxt][a_k + 3][a_m] = av.w;
        if (TRANSB) {
            Bs[nxt][a_k + 0][a_m] = bv.x;
            Bs[nxt][a_k + 1][a_m] = bv.y;
            Bs[nxt][a_k + 2][a_m] = bv.z;
            Bs[nxt][a_k + 3][a_m] = bv.w;
        } else {
            *(float4*)&Bs[nxt][b_k][b_n] = bv;
        }
        __syncthreads();
        cur = nxt;
        k0 = k1;
    }

    #pragma unroll
    for (int ih = 0; ih < 2; ih++) {
        #pragma unroll
        for (int i = 0; i < 4; i++) {
            int m = m0 + ih * 64 + ty * 4 + i;
            #pragma unroll
            for (int jh = 0; jh < 2; jh++) {
                int n = n0 + jh * 64 + tx * 4;
                float4 r;
                r.x = acc[ih * 4 + i][jh * 4 + 0] * alpha;
                r.y = acc[ih * 4 + i][jh * 4 + 1] * alpha;
                r.z = acc[ih * 4 + i][jh * 4 + 2] * alpha;
                r.w = acc[ih * 4 + i][jh * 4 + 3] * alpha;
                if (bias) {
                    float4 bb = *(const float4*)(bias + n);
                    r.x += bb.x; r.y += bb.y; r.z += bb.z; r.w += bb.w;
                }
                if (Res) {
                    float4 rr = *(const float4*)(Res + (long long)m * ldc + n);
                    r.x += rr.x; r.y += rr.y; r.z += rr.z; r.w += rr.w;
                }
                if (RELU) {
                    r.x = fmaxf(r.x, 0.f); r.y = fmaxf(r.y, 0.f);
                    r.z = fmaxf(r.z, 0.f); r.w = fmaxf(r.w, 0.f);
                }
                *(float4*)(C + (long long)m * ldc + n) = r;
            }
        }
    }
}

// ================= tf32 tensor-core GEMM with cp.async ====================
#define ASTRIDE 20
#define BN128STR 136
#define BN64STR  68

__device__ __forceinline__ void cpa16(void* dst, const void* src)
{
    uint32_t s = (uint32_t)__cvta_generic_to_shared(dst);
    asm volatile("cp.async.cg.shared.global [%0], [%1], 16;" :: "r"(s), "l"(src));
}
template<int N> __device__ __forceinline__ void cpa_wait()
{
    asm volatile("cp.async.wait_group %0;" :: "n"(N));
}
__device__ __forceinline__ void cpa_commit()
{
    asm volatile("cp.async.commit_group;");
}
__device__ __forceinline__ void mma_tf32(float* d, const uint32_t* a, uint32_t b0, uint32_t b1)
{
    asm volatile(
        "mma.sync.aligned.m16n8k8.row.col.f32.tf32.tf32.f32 "
        "{%0,%1,%2,%3}, {%4,%5,%6,%7}, {%8,%9}, {%0,%1,%2,%3};"
        : "+f"(d[0]), "+f"(d[1]), "+f"(d[2]), "+f"(d[3])
        : "r"(a[0]), "r"(a[1]), "r"(a[2]), "r"(a[3]), "r"(b0), "r"(b1));
}

template<bool TRANSB, bool RELU, bool TF32OUT, int NTILE>
__global__ void __launch_bounds__(256, 2)
tf32gemm_k(const float* __restrict__ A, const float* __restrict__ B,
           const float* __restrict__ bias, const float* __restrict__ Res,
           float* __restrict__ C,
           int K, int lda, int ldb, int ldc,
           long long sA, long long sAi, long long sB, long long sBi,
           long long sC, long long sCi, int zi, float alpha)
{
    constexpr int NT = NTILE / 16;
    constexpr int BSTR = (NTILE == 128) ? BN128STR : BN64STR;

    int bz = blockIdx.z;
    int zo = bz / zi, zin = bz % zi;
    A += zo * sA + zin * sAi;
    B += zo * sB + zin * sBi;
    C += zo * sC + zin * sCi;
    if (Res) Res += zo * sC + zin * sCi;

    int m0 = blockIdx.y * 128;
    int n0 = blockIdx.x * NTILE;

    __shared__ __align__(16) float As[2][128 * ASTRIDE];
    constexpr int BSZ = TRANSB ? (NTILE * ASTRIDE) : (16 * BSTR);
    __shared__ __align__(16) float Bs[2][BSZ];

    int tid = threadIdx.x;
    int lane = tid & 31;
    int wid = tid >> 5;
    int wm = (wid & 3) * 32;
    int wn = (wid >> 2) * (NTILE / 2);
    int tig = lane & 3;
    int grp = lane >> 2;

    int ra = tid >> 2;
    int ca = (tid & 3) * 4;
    const float* Asrc0 = A + (long long)(m0 + ra) * lda + ca;
    const float* Asrc1 = A + (long long)(m0 + ra + 64) * lda + ca;
    int aoff0 = ra * ASTRIDE + ca;
    int aoff1 = (ra + 64) * ASTRIDE + ca;

    const float *Bsrc0 = nullptr, *Bsrc1 = nullptr;
    int boff0 = 0, boff1 = 0;
    if (TRANSB) {
        if (NTILE == 128) {
            Bsrc0 = B + (long long)(n0 + ra) * ldb + ca;
            Bsrc1 = B + (long long)(n0 + ra + 64) * ldb + ca;
            boff0 = aoff0;
            boff1 = aoff1;
        } else {
            Bsrc0 = B + (long long)(n0 + ra) * ldb + ca;
            boff0 = ra * ASTRIDE + ca;
        }
    } else {
        if (NTILE == 128) {
            int rb = tid >> 5;
            int cb = (tid & 31) * 4;
            Bsrc0 = B + (long long)rb * ldb + n0 + cb;
            Bsrc1 = B + (long long)(rb + 8) * ldb + n0 + cb;
            boff0 = rb * BSTR + cb;
            boff1 = (rb + 8) * BSTR + cb;
        } else {
            int rb = tid >> 4;
            int cb = (tid & 15) * 4;
            Bsrc0 = B + (long long)rb * ldb + n0 + cb;
            boff0 = rb * BSTR + cb;
        }
    }
    constexpr bool BTWO = (NTILE == 128);

    {
        cpa16(&As[0][aoff0], Asrc0);
        cpa16(&As[0][aoff1], Asrc1);
        cpa16(&Bs[0][boff0], Bsrc0);
        if (BTWO) cpa16(&Bs[0][boff1], Bsrc1);
        cpa_commit();
    }

    float acc[2][NT][4];
    #pragma unroll
    for (int mt = 0; mt < 2; mt++)
        #pragma unroll
        for (int nt = 0; nt < NT; nt++)
            #pragma unroll
            for (int r = 0; r < 4; r++) acc[mt][nt][r] = 0.f;

    int cur = 0;
    int k0 = 0;
    for (;;) {
        int k1 = k0 + 16;
        bool more = (k1 < K);
        if (more) {
            int nxt = cur ^ 1;
            cpa16(&As[nxt][aoff0], Asrc0 + k1);
            cpa16(&As[nxt][aoff1], Asrc1 + k1);
            if (TRANSB) {
                cpa16(&Bs[nxt][boff0], Bsrc0 + k1);
                if (BTWO) cpa16(&Bs[nxt][boff1], Bsrc1 + k1);
            } else {
                cpa16(&Bs[nxt][boff0], Bsrc0 + (long long)k1 * ldb);
                if (BTWO) cpa16(&Bs[nxt][boff1], Bsrc1 + (long long)k1 * ldb);
            }
            cpa_commit();
            cpa_wait<1>();
        } else {
            cpa_wait<0>();
        }
        __syncthreads();

        #pragma unroll
        for (int ks = 0; ks < 16; ks += 8) {
            uint32_t af[2][4], bf[NT][2];
            #pragma unroll
            for (int mt = 0; mt < 2; mt++) {
                int mA = wm + mt * 16 + grp;
                af[mt][0] = __float_as_uint(As[cur][mA * ASTRIDE + ks + tig]);
                af[mt][1] = __float_as_uint(As[cur][(mA + 8) * ASTRIDE + ks + tig]);
                af[mt][2] = __float_as_uint(As[cur][mA * ASTRIDE + ks + tig + 4]);
                af[mt][3] = __float_as_uint(As[cur][(mA + 8) * ASTRIDE + ks + tig + 4]);
            }
            #pragma unroll
            for (int nt = 0; nt < NT; nt++) {
                int nB = wn + nt * 8 + grp;
                if (TRANSB) {
                    bf[nt][0] = __float_as_uint(Bs[cur][nB * ASTRIDE + ks + tig]);
                    bf[nt][1] = __float_as_uint(Bs[cur][nB * ASTRIDE + ks + tig + 4]);
                } else {
                    bf[nt][0] = __float_as_uint(Bs[cur][(ks + tig) * BSTR + nB]);
                    bf[nt][1] = __float_as_uint(Bs[cur][(ks + tig + 4) * BSTR + nB]);
                }
            }
            #pragma unroll
            for (int mt = 0; mt < 2; mt++)
                #pragma unroll
                for (int nt = 0; nt < NT; nt++)
                    mma_tf32(acc[mt][nt], af[mt], bf[nt][0], bf[nt][1]);
        }
        if (!more) break;
        __syncthreads();
        cur ^= 1;
        k0 = k1;
    }

    #pragma unroll
    for (int mt = 0; mt < 2; mt++) {
        #pragma unroll
        for (int half = 0; half < 2; half++) {
            int m = m0 + wm + mt * 16 + grp + half * 8;
            #pragma unroll
            for (int nt = 0; nt < NT; nt++) {
                int n = n0 + wn + nt * 8 + 2 * tig;
                float2 r;
                r.x = acc[mt][nt][half * 2 + 0] * alpha;
                r.y = acc[mt][nt][half * 2 + 1] * alpha;
                if (bias) {
                    r.x += bias[n];
                    r.y += bias[n + 1];
                }
                if (Res) {
                    const float2 rr = *(const float2*)(Res + (long long)m * ldc + n);
                    r.x += rr.x; r.y += rr.y;
                }
                if (RELU) {
                    r.x = fmaxf(r.x, 0.f);
                    r.y = fmaxf(r.y, 0.f);
                }
                if (TF32OUT) {
                    r.x = rna_tf32(r.x);
                    r.y = rna_tf32(r.y);
                }
                *(float2*)(C + (long long)m * ldc + n) = r;
            }
        }
    }
}

// ================= fused flash attention (tf32 MMA, online softmax) ========
// grid (8 q-tiles, 24 b*h); 256 threads (8 warps, each = 16 q rows).
// smem: Qs[128][132] + Ks[2][32][132] + Vs[2][32][136] + Ps[128][36]
#define QSTR 132
#define KSTR 132
#define VSTR 136
#define PSTR 36
static const int FLASH_SMEM = (128*QSTR + 2*32*KSTR + 2*32*VSTR + 128*PSTR) * 4;

__global__ void __launch_bounds__(256, 1)
flash_attn_kernel(const float* __restrict__ qkv, float* __restrict__ ao)
{
    extern __shared__ __align__(16) float sm[];
    float* Qs = sm;                       // 128*132
    float* Ks = Qs + 128 * QSTR;          // 2*32*132
    float* Vs = Ks + 2 * 32 * KSTR;       // 2*32*136
    float* Ps = Vs + 2 * 32 * VSTR;       // 128*36

    int qt = blockIdx.x;                  // q tile
    int bh = blockIdx.y;
    int b = bh / NHE, h = bh - b * NHE;
    const float* qbase = qkv + (long long)b * NN * HD4 + (long long)qt * 128 * HD4 + HD + h * DHE;
    const float* kbase = qkv + (long long)b * NN * HD4 + 2 * HD + h * DHE;
    const float* vbase = qkv + (long long)b * NN * HD4 + 3 * HD + h * DHE;

    int tid = threadIdx.x;
    int lane = tid & 31, wid = tid >> 5;
    int tig = lane & 3, grp = lane >> 2;
    int wq = wid * 16;

    // prologue: Q (whole tile) + K/V tile 0
    #pragma unroll
    for (int c = 0; c < 16; c++) {
        int chunk = tid + c * 256;
        int row = chunk >> 5, col = (chunk & 31) * 4;
        cpa16(&Qs[row * QSTR + col], qbase + (long long)row * HD4 + col);
    }
    #pragma unroll
    for (int c = 0; c < 4; c++) {
        int chunk = tid + c * 256;
        int row = chunk >> 5, col = (chunk & 31) * 4;
        cpa16(&Ks[row * KSTR + col], kbase + (long long)row * HD4 + col);
        cpa16(&Vs[row * VSTR + col], vbase + (long long)row * HD4 + col);
    }
    cpa_commit();

    float Oacc[16][4];
    #pragma unroll
    for (int nt = 0; nt < 16; nt++)
        #pragma unroll
        for (int j = 0; j < 4; j++) Oacc[nt][j] = 0.f;
    float m0r = -1e30f, m1r = -1e30f;
    float l0 = 0.f, l1 = 0.f;
    const float alpha = 0.08838834764831843f;

    int cur = 0;
    for (int it = 0; it < 32; it++) {
        bool more = (it + 1 < 32);
        if (more) {
            int nxt = cur ^ 1;
            const float* kb = kbase + (long long)(it + 1) * 32 * HD4;
            const float* vb = vbase + (long long)(it + 1) * 32 * HD4;
            #pragma unroll
            for (int c = 0; c < 4; c++) {
                int chunk = tid + c * 256;
                int row = chunk >> 5, col = (chunk & 31) * 4;
                cpa16(&Ks[nxt * 32 * KSTR + row * KSTR + col], kb + (long long)row * HD4 + col);
                cpa16(&Vs[nxt * 32 * VSTR + row * VSTR + col], vb + (long long)row * HD4 + col);
            }
            cpa_commit();
            cpa_wait<1>();
        } else {
            cpa_wait<0>();
        }
        __syncthreads();

        const float* Kc = Ks + cur * 32 * KSTR;
        const float* Vc = Vs + cur * 32 * VSTR;

        // S = Q @ K^T  (warp: 16 q rows x 32 keys)
        float s[4][4];
        #pragma unroll
        for (int nt = 0; nt < 4; nt++)
            #pragma unroll
            for (int j = 0; j < 4; j++) s[nt][j] = 0.f;
        #pragma unroll
        for (int kc = 0; kc < 16; kc++) {
            uint32_t af[4];
            af[0] = __float_as_uint(Qs[(wq + grp) * QSTR + kc * 8 + tig]);
            af[1] = __float_as_uint(Qs[(wq + grp + 8) * QSTR + kc * 8 + tig]);
            af[2] = __float_as_uint(Qs[(wq + grp) * QSTR + kc * 8 + tig + 4]);
            af[3] = __float_as_uint(Qs[(wq + grp + 8) * QSTR + kc * 8 + tig + 4]);
            #pragma unroll
            for (int nt = 0; nt < 4; nt++) {
                uint32_t b0 = __float_as_uint(Kc[(nt * 8 + grp) * KSTR + kc * 8 + tig]);
                uint32_t b1 = __float_as_uint(Kc[(nt * 8 + grp) * KSTR + kc * 8 + tig + 4]);
                mma_tf32(s[nt], af, b0, b1);
            }
        }

        // online softmax update
        float t0 = -1e30f, t1 = -1e30f;
        #pragma unroll
        for (int nt = 0; nt < 4; nt++) {
            s[nt][0] *= alpha; s[nt][1] *= alpha;
            s[nt][2] *= alpha; s[nt][3] *= alpha;
            t0 = fmaxf(t0, fmaxf(s[nt][0], s[nt][1]));
            t1 = fmaxf(t1, fmaxf(s[nt][2], s[nt][3]));
        }
        t0 = fmaxf(t0, __shfl_xor_sync(0xffffffffu, t0, 1));
        t0 = fmaxf(t0, __shfl_xor_sync(0xffffffffu, t0, 2));
        t1 = fmaxf(t1, __shfl_xor_sync(0xffffffffu, t1, 1));
        t1 = fmaxf(t1, __shfl_xor_sync(0xffffffffu, t1, 2));
        float mn0 = fmaxf(m0r, t0), mn1 = fmaxf(m1r, t1);
        float f0 = __expf(m0r - mn0), f1 = __expf(m1r - mn1);
        float ps0 = 0.f, ps1 = 0.f;
        #pragma unroll
        for (int nt = 0; nt < 4; nt++) {
            float p0 = __expf(s[nt][0] - mn0);
            float p1 = __expf(s[nt][1] - mn0);
            float p2 = __expf(s[nt][2] - mn1);
            float p3 = __expf(s[nt][3] - mn1);
            ps0 += p0 + p1;
            ps1 += p2 + p3;
            float2 lo = { rna_tf32(p0), rna_tf32(p1) };
            float2 hi = { rna_tf32(p2), rna_tf32(p3) };
            *(float2*)&Ps[(wq + grp) * PSTR + nt * 8 + 2 * tig] = lo;
            *(float2*)&Ps[(wq + grp + 8) * PSTR + nt * 8 + 2 * tig] = hi;
        }
        ps0 += __shfl_xor_sync(0xffffffffu, ps0, 1);
        ps0 += __shfl_xor_sync(0xffffffffu, ps0, 2);
        ps1 += __shfl_xor_sync(0xffffffffu, ps1, 1);
        ps1 += __shfl_xor_sync(0xffffffffu, ps1, 2);
        l0 = l0 * f0 + ps0;
        l1 = l1 * f1 + ps1;
        m0r = mn0; m1r = mn1;
        #pragma unroll
        for (int nt = 0; nt < 16; nt++) {
            Oacc[nt][0] *= f0; Oacc[nt][1] *= f0;
            Oacc[nt][2] *= f1; Oacc[nt][3] *= f1;
        }
        __syncwarp();

        // O += P @ V  (warp reads only its own P rows)
        #pragma unroll
        for (int kc = 0; kc < 4; kc++) {
            uint32_t af[4];
            af[0] = __float_as_uint(Ps[(wq + grp) * PSTR + kc * 8 + tig]);
            af[1] = __float_as_uint(Ps[(wq + grp + 8) * PSTR + kc * 8 + tig]);
            af[2] = __float_as_uint(Ps[(wq + grp) * PSTR + kc * 8 + tig + 4]);
            af[3] = __float_as_uint(Ps[(wq + grp + 8) * PSTR + kc * 8 + tig + 4]);
            #pragma unroll
            for (int nt = 0; nt < 16; nt++) {
                uint32_t b0 = __float_as_uint(Vc[(kc * 8 + tig) * VSTR + nt * 8 + grp]);
                uint32_t b1 = __float_as_uint(Vc[(kc * 8 + tig + 4) * VSTR + nt * 8 + grp]);
                mma_tf32(Oacc[nt], af, b0, b1);
            }
        }
        if (!more) break;
        __syncthreads();
        cur ^= 1;
    }

    // normalize + store (tf32-rounded: feeds Wo GEMM)
    float inv0 = 1.f / l0, inv1 = 1.f / l1;
    int r0 = qt * 128 + wq + grp;
    float* o0 = ao + (long long)b * NN * HD + (long long)r0 * HD + h * DHE;
    float* o1 = o0 + 8 * HD;
    #pragma unroll
    for (int nt = 0; nt < 16; nt++) {
        int col = nt * 8 + 2 * tig;
        float2 va = { rna_tf32(Oacc[nt][0] * inv0), rna_tf32(Oacc[nt][1] * inv0) };
        float2 vb = { rna_tf32(Oacc[nt][2] * inv1), rna_tf32(Oacc[nt][3] * inv1) };
        *(float2*)(o0 + col) = va;
        *(float2*)(o1 + col) = vb;
    }
}

// ---------------- small kernels ----------------
__global__ void feats_kernel(const float* __restrict__ x, float* __restrict__ feats)
{
    long long i = (long long)blockIdx.x * blockDim.x + threadIdx.x;
    if (i >= (long long)NB * NN * CIN) return;
    int c = (int)(i & (CIN - 1));
    long long bn = i >> 6;
    int n = (int)(bn & (NN - 1));
    int b = (int)(bn >> 10);
    feats[i] = x[((long long)b * CIN + c) * NN + n];
}

// one-shot weight prep: pack proj weights/biases + round Wo/W1/W2
__global__ void prep_kernel(const float* __restrict__ gcn_W, const float* __restrict__ Wq,
                            const float* __restrict__ Wk, const float* __restrict__ Wv,
                            const float* __restrict__ gcn_b, const float* __restrict__ bq,
                            const float* __restrict__ bk, const float* __restrict__ bv,
                            const float* __restrict__ Wo, const float* __restrict__ W1,
                            const float* __restrict__ W2,
                            float* __restrict__ wpack, float* __restrict__ bpack,
                            float* __restrict__ wr)
{
    int i = blockIdx.x * blockDim.x + threadIdx.x;
    const int NWP = 3 * 384 * 1536;   // 1769472
    const int NBP = 3 * 1536;         // 4608
    const int NWO = 442368;
    const int NW1 = 884736;
    if (i < NWP) {
        int l = i / (384 * 1536);
        int rem = i - l * (384 * 1536);
        int r = rem / 1536;
        int c = rem - r * 1536;
        int sel = c / 384, cc = c - sel * 384;
        const float* src = (sel == 0) ? gcn_W : (sel == 1) ? Wq : (sel == 2) ? Wk : Wv;
        wpack[i] = rna_tf32(src[((long long)l * 384 + r) * 384 + cc]);
        return;
    }
    int j = i - NWP;
    if (j < NBP) {
        int l = j / 1536;
        int c = j - l * 1536;
        int sel = c / 384, cc = c - sel * 384;
        const float* src = (sel == 0) ? gcn_b : (sel == 1) ? bq : (sel == 2) ? bk : bv;
        bpack[j] = src[l * 384 + cc];
        return;
    }
    j -= NBP;
    if (j < NWO) { wr[WR_WO + j] = rna_tf32(Wo[j]); return; }
    j -= NWO;
    if (j < NW1) { wr[WR_W1 + j] = rna_tf32(W1[j]); return; }
    j -= NW1;
    if (j < NW1) { wr[WR_W2 + j] = rna_tf32(W2[j]); return; }
}

__device__ __forceinline__ void block_reduce2(float& s1, float& s2)
{
    __shared__ float b1[4], b2[4];
    #pragma unroll
    for (int o = 16; o > 0; o >>= 1) {
        s1 += __shfl_down_sync(0xffffffffu, s1, o);
        s2 += __shfl_down_sync(0xffffffffu, s2, o);
    }
    int w = threadIdx.x >> 5;
    if ((threadIdx.x & 31) == 0) { b1[w] = s1; b2[w] = s2; }
    __syncthreads();
    s1 = b1[0] + b1[1] + b1[2] + b1[3];
    s2 = b2[0] + b2[1] + b2[2] + b2[3];
}

// nh = h0/|h0|  and  h0r = rna(h0)
__global__ void norm_kernel(const float* __restrict__ h0, float* __restrict__ nh,
                            float* __restrict__ h0r)
{
    long long bn = blockIdx.x;
    int t = threadIdx.x; // 128
    const float* r = h0 + bn * HD;
    float v0 = r[t], v1 = r[t + 128], v2 = r[t + 256];
    float ss = v0 * v0 + v1 * v1 + v2 * v2, dummy = 0.f;
    block_reduce2(ss, dummy);
    float rinv = rsqrtf(ss);
    float* o = nh + bn * HD;
    o[t] = v0 * rinv; o[t + 128] = v1 * rinv; o[t + 256] = v2 * rinv;
    float* o2 = h0r + bn * HD;
    o2[t] = rna_tf32(v0); o2[t + 128] = rna_tf32(v1); o2[t + 256] = rna_tf32(v2);
}

__global__ void topk_warp_kernel(const float* __restrict__ sim, int* __restrict__ knn)
{
    int warp = blockIdx.x * (blockDim.x >> 5) + (threadIdx.x >> 5);
    if (warp >= NB * NN) return;
    int lane = threadIdx.x & 31;
    int n = warp & (NN - 1);
    const float* row = sim + (long long)warp * NN;
    float v[32];
    #pragma unroll
    for (int j = 0; j < 32; j++) {
        int m = j * 32 + lane;
        v[j] = (m == n) ? -3e38f : row[m];
    }
    unsigned taken = 0;
    int* o = knn + (long long)warp * KNN;
    for (int r = 0; r < KNN; r++) {
        float bv = -3e38f; int bj = 0;
        #pragma unroll
        for (int j = 0; j < 32; j++) {
            bool free_ = !((taken >> j) & 1u);
            if (free_ && v[j] > bv) { bv = v[j]; bj = j; }
        }
        int bidx = bj * 32 + lane;
        #pragma unroll
        for (int off = 16; off > 0; off >>= 1) {
            float ov = __shfl_xor_sync(0xffffffffu, bv, off);
            int   oi = __shfl_xor_sync(0xffffffffu, bidx, off);
            if (ov > bv || (ov == bv && oi < bidx)) { bv = ov; bidx = oi; }
        }
        if ((bidx & 31) == lane) taken |= 1u << (bidx >> 5);
        if (lane == 0) o[r] = bidx;
    }
}

__global__ void gcn_agg_ln(const float* __restrict__ hcur, const float* __restrict__ xw,
                           int ldx,
                           const int* __restrict__ knn,
                           const float* __restrict__ scale, const float* __restrict__ bias,
                           float* __restrict__ out)
{
    int bn = blockIdx.x;
    int b = bn >> 10;
    int t = threadIdx.x; // 128
    __shared__ int sidx[KNN];
    if (t < KNN) sidx[t] = knn[(long long)bn * KNN + t];
    __syncthreads();
    const float* xr = xw + (long long)bn * ldx;
    float a0 = xr[t], a1 = xr[t + 128], a2 = xr[t + 256];
    #pragma unroll 4
    for (int j = 0; j < KNN; j++) {
        const float* r = xw + ((long long)(b * NN) + sidx[j]) * ldx;
        a0 += r[t]; a1 += r[t + 128]; a2 += r[t + 256];
    }
    const float* h = hcur + (long long)bn * HD;
    const float inv17 = 1.f / 17.f;
    float v0 = h[t] + a0 * inv17;
    float v1 = h[t + 128] + a1 * inv17;
    float v2 = h[t + 256] + a2 * inv17;
    float s1 = v0 + v1 + v2;
    float s2 = v0 * v0 + v1 * v1 + v2 * v2;
    block_reduce2(s1, s2);
    float mu = s1 * (1.f / HD);
    float var = s2 * (1.f / HD) - mu * mu;
    float rstd = rsqrtf(var + 1e-5f);
    float* o = out + (long long)bn * HD;
    o[t]       = (v0 - mu) * rstd * scale[t]       + bias[t];
    o[t + 128] = (v1 - mu) * rstd * scale[t + 128] + bias[t + 128];
    o[t + 256] = (v2 - mu) * rstd * scale[t + 256] + bias[t + 256];
}

__global__ void add_ln_kernel(const float* __restrict__ a, const float* __restrict__ b,
                              const float* __restrict__ plus,
                              const float* __restrict__ scale, const float* __restrict__ bias,
                              float* __restrict__ out, int rnd)
{
    long long bn = blockIdx.x;
    int t = threadIdx.x; // 128
    const float* ar = a + bn * HD;
    float v0 = ar[t], v1 = ar[t + 128], v2 = ar[t + 256];
    if (b) {
        const float* br = b + bn * HD;
        v0 += br[t]; v1 += br[t + 128]; v2 += br[t + 256];
    }
    float s1 = v0 + v1 + v2;
    float s2 = v0 * v0 + v1 * v1 + v2 * v2;
    block_reduce2(s1, s2);
    float mu = s1 * (1.f / HD);
    float var = s2 * (1.f / HD) - mu * mu;
    float rstd = rsqrtf(var + 1e-5f);
    float y0 = (v0 - mu) * rstd * scale[t]       + bias[t];
    float y1 = (v1 - mu) * rstd * scale[t + 128] + bias[t + 128];
    float y2 = (v2 - mu) * rstd * scale[t + 256] + bias[t + 256];
    if (plus) {
        const float* pr = plus + bn * HD;
        y0 += pr[t]; y1 += pr[t + 128]; y2 += pr[t + 256];
    }
    if (rnd) { y0 = rna_tf32(y0); y1 = rna_tf32(y1); y2 = rna_tf32(y2); }
    float* o = out + bn * HD;
    o[t] = y0; o[t + 128] = y1; o[t + 256] = y2;
}

__global__ void pool_kernel(const float* __restrict__ h, float* __restrict__ pooled)
{
    int b = blockIdx.x;
    int t = threadIdx.x; // 384
    float s = 0.f;
    const float* base = h + (long long)b * NN * HD + t;
    for (int n = 0; n < NN; n++) s += base[(long long)n * HD];
    pooled[b * HD + t] = s * (1.f / NN);
}

__global__ void fin1_kernel(const float* __restrict__ pooled, const float* __restrict__ W,
                            const float* __restrict__ bias, float* __restrict__ z)
{
    int b = blockIdx.x;
    int j = threadIdx.x; // 384
    const float* p = pooled + b * HD;
    float s = bias[j];
    for (int k = 0; k < HD; k++) s = fmaf(p[k], W[k * HD + j], s);
    z[b * HD + j] = fmaxf(s, 0.f);
}

__global__ void fin2_kernel(const float* __restrict__ z, const float* __restrict__ W,
                            const float* __restrict__ bias, float* __restrict__ out)
{
    int b = blockIdx.x;
    int j = threadIdx.x; // 128
    const float* p = z + b * HD;
    float s = bias[j];
    for (int k = 0; k < HD; k++) s = fmaf(p[k], W[k * 128 + j], s);
    out[b * 128 + j] = s;
}

// ---------------- host-side GEMM dispatchers ----------------
static void gemm_f32(const float* A, const float* B, const float* bias, const float* Res, float* C,
                     int M, int Nn, int K, int lda, int ldb, int ldc,
                     long long sA, long long sAi, long long sB, long long sBi,
                     long long sC, long long sCi, int zi, int nz,
                     float alpha, bool transb, bool relu)
{
    dim3 grid(Nn / BN, M / BM, nz), block(256);
    if (transb) {
        if (relu) gemm_k<true, true ><<<grid, block>>>(A, B, bias, Res, C, M, Nn, K, lda, ldb, ldc, sA, sAi, sB, sBi, sC, sCi, zi, alpha);
        else      gemm_k<true, false><<<grid, block>>>(A, B, bias, Res, C, M, Nn, K, lda, ldb, ldc, sA, sAi, sB, sBi, sC, sCi, zi, alpha);
    } else {
        if (relu) gemm_k<false, true ><<<grid, block>>>(A, B, bias, Res, C, M, Nn, K, lda, ldb, ldc, sA, sAi, sB, sBi, sC, sCi, zi, alpha);
        else      gemm_k<false, false><<<grid, block>>>(A, B, bias, Res, C, M, Nn, K, lda, ldb, ldc, sA, sAi, sB, sBi, sC, sCi, zi, alpha);
    }
}

static void gemm_tf(const float* A, const float* B, const float* bias, const float* Res, float* C,
                    int M, int Nn, int K, int lda, int ldb, int ldc,
                    long long sA, long long sAi, long long sB, long long sBi,
                    long long sC, long long sCi, int zi, int nz,
                    float alpha, bool transb, bool relu, bool tf32out, int ntile)
{
    dim3 grid(Nn / ntile, M / 128, nz), block(256);
    #define DISP(TB, RL, TO, NTL) tf32gemm_k<TB, RL, TO, NTL><<<grid, block>>>(A, B, bias, Res, C, K, lda, ldb, ldc, sA, sAi, sB, sBi, sC, sCi, zi, alpha)
    if (ntile == 128) {
        if (transb) {
            if (relu)  { if (tf32out) DISP(true, true, true, 128);  else DISP(true, true, false, 128); }
            else       { if (tf32out) DISP(true, false, true, 128); else DISP(true, false, false, 128); }
        } else {
            if (relu)  { if (tf32out) DISP(false, true, true, 128);  else DISP(false, true, false, 128); }
            else       { if (tf32out) DISP(false, false, true, 128); else DISP(false, false, false, 128); }
        }
    } else {
        if (transb) {
            if (relu)  { if (tf32out) DISP(true, true, true, 64);  else DISP(true, true, false, 64); }
            else       { if (tf32out) DISP(true, false, true, 64); else DISP(true, false, false, 64); }
        } else {
            if (relu)  { if (tf32out) DISP(false, true, true, 64);  else DISP(false, true, false, 64); }
            else       { if (tf32out) DISP(false, false, true, 64); else DISP(false, false, false, 64); }
        }
    }
    #undef DISP
}

template<typename T> static T* sym_addr(const void* sym)
{
    void* p = nullptr;
    cudaGetSymbolAddress(&p, sym);
    return (T*)p;
}

extern "C" void kernel_launch(void* const* d_in, const int* in_sizes, int n_in,
                              void* d_out, int out_size)
{
    const float* x      = (const float*)d_in[0];
    const float* W_enc  = (const float*)d_in[1];
    const float* b_enc  = (const float*)d_in[2];
    const float* gcn_W  = (const float*)d_in[3];
    const float* gcn_b  = (const float*)d_in[4];
    const float* Wq     = (const float*)d_in[5];
    const float* bq     = (const float*)d_in[6];
    const float* Wk     = (const float*)d_in[7];
    const float* bk     = (const float*)d_in[8];
    const float* Wv     = (const float*)d_in[9];
    const float* bv     = (const float*)d_in[10];
    const float* Wo     = (const float*)d_in[11];
    const float* bo     = (const float*)d_in[12];
    const float* lnsc   = (const float*)d_in[13];
    const float* lnbi   = (const float*)d_in[14];
    const float* W1     = (const float*)d_in[15];
    const float* b1     = (const float*)d_in[16];
    const float* W2     = (const float*)d_in[17];
    const float* b2     = (const float*)d_in[18];
    const float* lin1_W = (const float*)d_in[19];
    const float* lin1_b = (const float*)d_in[20];
    const float* lin2_W = (const float*)d_in[21];
    const float* lin2_b = (const float*)d_in[22];
    float* outp = (float*)d_out;

    float* featsp = sym_addr<float>(g_feats);
    float* h0p    = sym_addr<float>(g_h0);
    float* h0rp   = sym_addr<float>(g_h0r);
    float* nhp    = sym_addr<float>(g_nh);
    float* simp   = sym_addr<float>(g_sim);
    int*   knnp   = sym_addr<int>(g_knn);
    float* hcurp  = sym_addr<float>(g_hcur);
    float* qkvgp  = sym_addr<float>(g_qkvg);
    float* hlocp  = sym_addr<float>(g_hloc);
    float* aop    = sym_addr<float>(g_ao);
    float* op     = sym_addr<float>(g_o);
    float* combp  = sym_addr<float>(g_comb);
    float* mlp1p  = sym_addr<float>(g_mlp1);
    float* ffp    = sym_addr<float>(g_ff);
    float* poolp  = sym_addr<float>(g_pool);
    float* zp     = sym_addr<float>(g_z);
    float* wpackp = sym_addr<float>(g_wpack);
    float* bpackp = sym_addr<float>(g_bpack);
    float* wrp    = sym_addr<float>(g_wr);

    cudaFuncSetAttribute(flash_attn_kernel, cudaFuncAttributeMaxDynamicSharedMemorySize, FLASH_SMEM);

    const long long NH  = (long long)NN * HD;
    const long long NH4 = (long long)NN * HD4;
    const int WSQ = HD * HD;

    // #1 weight prep (single launch)
    {
        int total = 3 * 384 * 1536 + 3 * 1536 + 442368 + 884736 + 884736;
        prep_kernel<<<(total + 255) / 256, 256>>>(gcn_W, Wq, Wk, Wv, gcn_b, bq, bk, bv,
                                                  Wo, W1, W2, wpackp, bpackp, wrp);
    }
    // #2 feats, #3 encoder (fp32 exact)
    feats_kernel<<<(NB * NN * CIN + 255) / 256, 256>>>(x, featsp);
    gemm_f32(featsp, W_enc, b_enc, nullptr, h0p,
             NN, HD, CIN, CIN, HD, HD,
             (long long)NN * CIN, 0, 0, 0, NH, 0, 1, NB, 1.f, false, false);
    // #4 norm (+ rounded h0), #5 sim (fp32 exact)
    norm_kernel<<<NB * NN, 128>>>(h0p, nhp, h0rp);
    gemm_f32(nhp, nhp, nullptr, nullptr, simp,
             NN, NN, HD, HD, HD, NN,
             NH, 0, NH, 0, (long long)NN * NN, 0, 1, NB, 1.f, true, false);
    // #6 fused projection for layer 0 (profiled launch)
    gemm_tf(h0rp, wpackp, bpackp, nullptr, qkvgp,
            NN, HD4, HD, HD, HD4, HD4, NH, 0, 0, 0, NH4, 0, 1, NB,
            1.f, false, false, true, 128);
    // #7 top-k
    topk_warp_kernel<<<NB * NN / 8, 256>>>(simp, knnp);

    const float* hin = h0rp;
    for (int l = 0; l < NL; l++) {
        const float* scl = lnsc + (l * 3) * HD;
        const float* bil = lnbi + (l * 3) * HD;

        if (l > 0) {
            gemm_tf(hin, wpackp + (long long)l * HD * HD4, bpackp + l * HD4, nullptr, qkvgp,
                    NN, HD4, HD, HD, HD4, HD4, NH, 0, 0, 0, NH4, 0, 1, NB,
                    1.f, false, false, true, 128);
        }

        // local GCN branch (xw = cols [0,384) of packed output)
        gcn_agg_ln<<<NB * NN, 128>>>(hin, qkvgp, HD4, knnp, scl, bil, hlocp);

        // fused attention: scores + softmax + PV in one kernel
        flash_attn_kernel<<<dim3(NN / 128, NB * NHE), 256, FLASH_SMEM>>>(qkvgp, aop);

        gemm_tf(aop, wrp + WR_WO + (long long)l * WSQ, bo + l * HD, nullptr, op,
                NN, HD, HD, HD, HD, HD, NH, 0, 0, 0, NH, 0, 1, NB,
                1.f, false, false, false, 64);
        // comb = h_local + LN(hcur + o)   (rounded: feeds MLP GEMMs)
        add_ln_kernel<<<NB * NN, 128>>>(hin, op, hlocp, scl + HD, bil + HD, combp, 1);

        // FFN
        gemm_tf(combp, wrp + WR_W1 + (long long)l * HD * 2 * HD, b1 + l * 2 * HD, nullptr, mlp1p,
                NN, 2 * HD, HD, HD, 2 * HD, 2 * HD,
                NH, 0, 0, 0, (long long)NN * 2 * HD, 0, 1, NB, 1.f, false, true, true, 128);
        gemm_tf(mlp1p, wrp + WR_W2 + (long long)l * 2 * HD * HD, b2 + l * HD, combp, ffp,
                NN, HD, 2 * HD, 2 * HD, HD, HD,
                (long long)NN * 2 * HD, 0, 0, 0, NH, 0, 1, NB, 1.f, false, false, false, 64);
        add_ln_kernel<<<NB * NN, 128>>>(ffp, nullptr, nullptr, scl + 2 * HD, bil + 2 * HD, hcurp, 1);
        hin = hcurp;
    }

    // ---- head ----
    pool_kernel<<<NB, HD>>>(hin, poolp);
    fin1_kernel<<<NB, HD>>>(poolp, lin1_W, lin1_b, zp);
    fin2_kernel<<<NB, 128>>>(zp, lin2_W, lin2_b, outp);
}

// round 7
// speedup vs baseline: 3.2354x; 1.1145x over previous
#include <cuda_runtime.h>
#include <math.h>
#include <stdint.h>

// ---------------- problem constants ----------------
static const int NB   = 8;     // batch
static const int NN   = 1024;  // nodes (32*32)
static const int CIN  = 64;    // input channels
static const int HD   = 384;   // hidden
static const int NL   = 3;     // layers
static const int KNN  = 16;    // k
static const int NHE  = 3;     // heads
static const int DHE  = 128;   // head dim
static const int HD4  = 4 * HD; // 1536 packed width

// ---------------- device scratch (no allocs allowed) ----------------
__device__ float g_feats [NB*NN*CIN];
__device__ float g_h0    [NB*NN*HD];
__device__ float g_h0r   [NB*NN*HD];
__device__ float g_nh    [NB*NN*HD];
__device__ float g_sim   [NB*NN*NN];
__device__ int   g_knn   [NB*NN*KNN];
__device__ float g_hcur  [NB*NN*HD];
__device__ float g_qkvg  [NB*NN*4*HD];   // packed [gcn | q | k | v]
__device__ float g_hloc  [NB*NN*HD];
__device__ float g_ao    [NB*NN*HD];
__device__ float g_o     [NB*NN*HD];
__device__ float g_comb  [NB*NN*HD];
__device__ float g_mlp1  [NB*NN*2*HD];
__device__ float g_ff    [NB*NN*HD];
__device__ float g_pool  [NB*HD];
__device__ float g_z     [NB*HD];
// packed fused projection weights [L][384][1536] + biases [L][1536]
__device__ float g_wpack [3*384*1536];
__device__ float g_bpack [3*1536];
// rounded weights: WO, W1, W2
__device__ float g_wr    [2211840];
static const long long WR_WO  = 0;
static const long long WR_W1  = 442368;
static const long long WR_W2  = 1327104;

__device__ __forceinline__ float rna_tf32(float x)
{
    uint32_t r;
    asm("cvt.rna.tf32.f32 %0, %1;" : "=r"(r) : "f"(x));
    return __uint_as_float(r);
}

// ================= fp32 SIMT GEMM (exact path: encoder + cosine-sim) =======
#define BM 128
#define BN 128
#define BKK 8
#define SPAD 132

template<bool TRANSB, bool RELU>
__global__ void __launch_bounds__(256, 2)
gemm_k(const float* __restrict__ A, const float* __restrict__ B,
       const float* __restrict__ bias, const float* __restrict__ Res,
       float* __restrict__ C,
       int M, int Nn, int K, int lda, int ldb, int ldc,
       long long sA, long long sAi, long long sB, long long sBi,
       long long sC, long long sCi, int zi, float alpha)
{
    int bz = blockIdx.z;
    int zo = bz / zi, zin = bz % zi;
    A += zo * sA + zin * sAi;
    B += zo * sB + zin * sBi;
    C += zo * sC + zin * sCi;
    if (Res) Res += zo * sC + zin * sCi;

    int m0 = blockIdx.y * BM;
    int n0 = blockIdx.x * BN;

    __shared__ float As[2][BKK][SPAD];
    __shared__ float Bs[2][BKK][SPAD];

    int tid = threadIdx.x;
    int tx = tid & 15;
    int ty = tid >> 4;

    int a_m = tid >> 1;
    int a_k = (tid & 1) * 4;
    const float* Aload = A + (long long)(m0 + a_m) * lda + a_k;

    const float* Bload;
    int b_k = 0, b_n = 0;
    if (TRANSB) {
        Bload = B + (long long)(n0 + a_m) * ldb + a_k;
    } else {
        b_k = tid >> 5;
        b_n = (tid & 31) * 4;
        Bload = B + (long long)b_k * ldb + n0 + b_n;
    }

    float4 av = *(const float4*)Aload;
    float4 bv = *(const float4*)Bload;

    As[0][a_k + 0][a_m] = av.x;
    As[0][a_k + 1][a_m] = av.y;
    As[0][a_k + 2][a_m] = av.z;
    As[0][a_k + 3][a_m] = av.w;
    if (TRANSB) {
        Bs[0][a_k + 0][a_m] = bv.x;
        Bs[0][a_k + 1][a_m] = bv.y;
        Bs[0][a_k + 2][a_m] = bv.z;
        Bs[0][a_k + 3][a_m] = bv.w;
    } else {
        *(float4*)&Bs[0][b_k][b_n] = bv;
    }
    __syncthreads();

    float acc[8][8];
    #pragma unroll
    for (int i = 0; i < 8; i++)
        #pragma unroll
        for (int j = 0; j < 8; j++) acc[i][j] = 0.f;

    int cur = 0;
    for (int k0 = 0; ; ) {
        int k1 = k0 + BKK;
        bool more = (k1 < K);
        if (more) {
            av = *(const float4*)(Aload + k1);
            if (TRANSB) bv = *(const float4*)(Bload + k1);
            else        bv = *(const float4*)(Bload + (long long)k1 * ldb);
        }

        #pragma unroll
        for (int kk = 0; kk < BKK; kk++) {
            float4 a0 = *(const float4*)&As[cur][kk][ty * 4];
            float4 a1 = *(const float4*)&As[cur][kk][64 + ty * 4];
            float4 b0 = *(const float4*)&Bs[cur][kk][tx * 4];
            float4 b1 = *(const float4*)&Bs[cur][kk][64 + tx * 4];
            float a[8] = {a0.x, a0.y, a0.z, a0.w, a1.x, a1.y, a1.z, a1.w};
            float b[8] = {b0.x, b0.y, b0.z, b0.w, b1.x, b1.y, b1.z, b1.w};
            #pragma unroll
            for (int i = 0; i < 8; i++)
                #pragma unroll
                for (int j = 0; j < 8; j++)
                    acc[i][j] = fmaf(a[i], b[j], acc[i][j]);
        }
        if (!more) break;

        int nxt = cur ^ 1;
        As[nxt][a_k + 0][a_m] = av.x;
        As[nxt][a_k + 1][a_m] = av.y;
        As[nxt][a_k + 2][a_m] = av.z;
        As[nxt][a_k + 3][a_m] = av.w;
        if (TRANSB) {
            Bs[nxt][a_k + 0][a_m] = bv.x;
            Bs[nxt][a_k + 1][a_m] = bv.y;
            Bs[nxt][a_k + 2][a_m] = bv.z;
            Bs[nxt][a_k + 3][a_m] = bv.w;
        } else {
            *(float4*)&Bs[nxt][b_k][b_n] = bv;
        }
        __syncthreads();
        cur = nxt;
        k0 = k1;
    }

    #pragma unroll
    for (int ih = 0; ih < 2; ih++) {
        #pragma unroll
        for (int i = 0; i < 4; i++) {
            int m = m0 + ih * 64 + ty * 4 + i;
            #pragma unroll
            for (int jh = 0; jh < 2; jh++) {
                int n = n0 + jh * 64 + tx * 4;
                float4 r;
                r.x = acc[ih * 4 + i][jh * 4 + 0] * alpha;
                r.y = acc[ih * 4 + i][jh * 4 + 1] * alpha;
                r.z = acc[ih * 4 + i][jh * 4 + 2] * alpha;
                r.w = acc[ih * 4 + i][jh * 4 + 3] * alpha;
                if (bias) {
                    float4 bb = *(const float4*)(bias + n);
                    r.x += bb.x; r.y += bb.y; r.z += bb.z; r.w += bb.w;
                }
                if (Res) {
                    float4 rr = *(const float4*)(Res + (long long)m * ldc + n);
                    r.x += rr.x; r.y += rr.y; r.z += rr.z; r.w += rr.w;
                }
                if (RELU) {
                    r.x = fmaxf(r.x, 0.f); r.y = fmaxf(r.y, 0.f);
                    r.z = fmaxf(r.z, 0.f); r.w = fmaxf(r.w, 0.f);
                }
                *(float4*)(C + (long long)m * ldc + n) = r;
            }
        }
    }
}

// ================= tf32 tensor-core GEMM, 3-stage cp.async ================
#define ASTRIDE 20
#define BN128STR 136
#define BN64STR  68

__device__ __forceinline__ void cpa16(void* dst, const void* src)
{
    uint32_t s = (uint32_t)__cvta_generic_to_shared(dst);
    asm volatile("cp.async.cg.shared.global [%0], [%1], 16;" :: "r"(s), "l"(src));
}
template<int N> __device__ __forceinline__ void cpa_wait()
{
    asm volatile("cp.async.wait_group %0;" :: "n"(N));
}
__device__ __forceinline__ void cpa_commit()
{
    asm volatile("cp.async.commit_group;");
}
__device__ __forceinline__ void mma_tf32(float* d, const uint32_t* a, uint32_t b0, uint32_t b1)
{
    asm volatile(
        "mma.sync.aligned.m16n8k8.row.col.f32.tf32.tf32.f32 "
        "{%0,%1,%2,%3}, {%4,%5,%6,%7}, {%8,%9}, {%0,%1,%2,%3};"
        : "+f"(d[0]), "+f"(d[1]), "+f"(d[2]), "+f"(d[3])
        : "r"(a[0]), "r"(a[1]), "r"(a[2]), "r"(a[3]), "r"(b0), "r"(b1));
}

template<bool TRANSB, bool RELU, bool TF32OUT, int NTILE>
__global__ void __launch_bounds__(256, 2)
tf32gemm_k(const float* __restrict__ A, const float* __restrict__ B,
           const float* __restrict__ bias, const float* __restrict__ Res,
           float* __restrict__ C,
           int K, int lda, int ldb, int ldc,
           long long sA, long long sAi, long long sB, long long sBi,
           long long sC, long long sCi, int zi, float alpha)
{
    constexpr int NT = NTILE / 16;
    constexpr int BSTR = (NTILE == 128) ? BN128STR : BN64STR;
    constexpr int ASZ = 128 * ASTRIDE;
    constexpr int BSZ = TRANSB ? (NTILE * ASTRIDE) : (16 * BSTR);

    extern __shared__ __align__(16) float dsm[];
    float* As = dsm;               // 3 * ASZ
    float* Bs = dsm + 3 * ASZ;     // 3 * BSZ

    int bz = blockIdx.z;
    int zo = bz / zi, zin = bz % zi;
    A += zo * sA + zin * sAi;
    B += zo * sB + zin * sBi;
    C += zo * sC + zin * sCi;
    if (Res) Res += zo * sC + zin * sCi;

    int m0 = blockIdx.y * 128;
    int n0 = blockIdx.x * NTILE;

    int tid = threadIdx.x;
    int lane = tid & 31;
    int wid = tid >> 5;
    int wm = (wid & 3) * 32;
    int wn = (wid >> 2) * (NTILE / 2);
    int tig = lane & 3;
    int grp = lane >> 2;

    int ra = tid >> 2;
    int ca = (tid & 3) * 4;
    const float* Asrc0 = A + (long long)(m0 + ra) * lda + ca;
    const float* Asrc1 = A + (long long)(m0 + ra + 64) * lda + ca;
    int aoff0 = ra * ASTRIDE + ca;
    int aoff1 = (ra + 64) * ASTRIDE + ca;

    const float *Bsrc0 = nullptr, *Bsrc1 = nullptr;
    int boff0 = 0, boff1 = 0;
    if (TRANSB) {
        if (NTILE == 128) {
            Bsrc0 = B + (long long)(n0 + ra) * ldb + ca;
            Bsrc1 = B + (long long)(n0 + ra + 64) * ldb + ca;
            boff0 = aoff0;
            boff1 = aoff1;
        } else {
            Bsrc0 = B + (long long)(n0 + ra) * ldb + ca;
            boff0 = ra * ASTRIDE + ca;
        }
    } else {
        if (NTILE == 128) {
            int rb = tid >> 5;
            int cb = (tid & 31) * 4;
            Bsrc0 = B + (long long)rb * ldb + n0 + cb;
            Bsrc1 = B + (long long)(rb + 8) * ldb + n0 + cb;
            boff0 = rb * BSTR + cb;
            boff1 = (rb + 8) * BSTR + cb;
        } else {
            int rb = tid >> 4;
            int cb = (tid & 15) * 4;
            Bsrc0 = B + (long long)rb * ldb + n0 + cb;
            boff0 = rb * BSTR + cb;
        }
    }
    constexpr bool BTWO = (NTILE == 128);

    const int kIters = K >> 4;

    // prologue: prefetch iter 0 -> buf0, iter 1 -> buf1
    {
        cpa16(&As[aoff0], Asrc0);
        cpa16(&As[aoff1], Asrc1);
        cpa16(&Bs[boff0], Bsrc0);
        if (BTWO) cpa16(&Bs[boff1], Bsrc1);
        cpa_commit();
        if (kIters > 1) {
            cpa16(&As[ASZ + aoff0], Asrc0 + 16);
            cpa16(&As[ASZ + aoff1], Asrc1 + 16);
            if (TRANSB) {
                cpa16(&Bs[BSZ + boff0], Bsrc0 + 16);
                if (BTWO) cpa16(&Bs[BSZ + boff1], Bsrc1 + 16);
            } else {
                cpa16(&Bs[BSZ + boff0], Bsrc0 + (long long)16 * ldb);
                if (BTWO) cpa16(&Bs[BSZ + boff1], Bsrc1 + (long long)16 * ldb);
            }
            cpa_commit();
        }
    }

    float acc[2][NT][4];
    #pragma unroll
    for (int mt = 0; mt < 2; mt++)
        #pragma unroll
        for (int nt = 0; nt < NT; nt++)
            #pragma unroll
            for (int r = 0; r < 4; r++) acc[mt][nt][r] = 0.f;

    int bufm = 0;   // buffer index of current iter (cycles 0,1,2)
    for (int it = 0; it < kIters; it++) {
        if (it + 1 < kIters) cpa_wait<1>(); else cpa_wait<0>();
        __syncthreads();

        // prefetch iter it+2 into buffer (it+2)%3 (== buffer of it-1, safe after sync)
        if (it + 2 < kIters) {
            int pb = bufm + 2; if (pb >= 3) pb -= 3;
            int kf = (it + 2) << 4;
            cpa16(&As[pb * ASZ + aoff0], Asrc0 + kf);
            cpa16(&As[pb * ASZ + aoff1], Asrc1 + kf);
            if (TRANSB) {
                cpa16(&Bs[pb * BSZ + boff0], Bsrc0 + kf);
                if (BTWO) cpa16(&Bs[pb * BSZ + boff1], Bsrc1 + kf);
            } else {
                cpa16(&Bs[pb * BSZ + boff0], Bsrc0 + (long long)kf * ldb);
                if (BTWO) cpa16(&Bs[pb * BSZ + boff1], Bsrc1 + (long long)kf * ldb);
            }
            cpa_commit();
        }

        const float* Ac = As + bufm * ASZ;
        const float* Bc = Bs + bufm * BSZ;
        #pragma unroll
        for (int ks = 0; ks < 16; ks += 8) {
            uint32_t af[2][4], bf[NT][2];
            #pragma unroll
            for (int mt = 0; mt < 2; mt++) {
                int mA = wm + mt * 16 + grp;
                af[mt][0] = __float_as_uint(Ac[mA * ASTRIDE + ks + tig]);
                af[mt][1] = __float_as_uint(Ac[(mA + 8) * ASTRIDE + ks + tig]);
                af[mt][2] = __float_as_uint(Ac[mA * ASTRIDE + ks + tig + 4]);
                af[mt][3] = __float_as_uint(Ac[(mA + 8) * ASTRIDE + ks + tig + 4]);
            }
            #pragma unroll
            for (int nt = 0; nt < NT; nt++) {
                int nB = wn + nt * 8 + grp;
                if (TRANSB) {
                    bf[nt][0] = __float_as_uint(Bc[nB * ASTRIDE + ks + tig]);
                    bf[nt][1] = __float_as_uint(Bc[nB * ASTRIDE + ks + tig + 4]);
                } else {
                    bf[nt][0] = __float_as_uint(Bc[(ks + tig) * BSTR + nB]);
                    bf[nt][1] = __float_as_uint(Bc[(ks + tig + 4) * BSTR + nB]);
                }
            }
            #pragma unroll
            for (int mt = 0; mt < 2; mt++)
                #pragma unroll
                for (int nt = 0; nt < NT; nt++)
                    mma_tf32(acc[mt][nt], af[mt], bf[nt][0], bf[nt][1]);
        }
        bufm++; if (bufm >= 3) bufm = 0;
    }

    #pragma unroll
    for (int mt = 0; mt < 2; mt++) {
        #pragma unroll
        for (int half = 0; half < 2; half++) {
            int m = m0 + wm + mt * 16 + grp + half * 8;
            #pragma unroll
            for (int nt = 0; nt < NT; nt++) {
                int n = n0 + wn + nt * 8 + 2 * tig;
                float2 r;
                r.x = acc[mt][nt][half * 2 + 0] * alpha;
                r.y = acc[mt][nt][half * 2 + 1] * alpha;
                if (bias) {
                    r.x += bias[n];
                    r.y += bias[n + 1];
                }
                if (Res) {
                    const float2 rr = *(const float2*)(Res + (long long)m * ldc + n);
                    r.x += rr.x; r.y += rr.y;
                }
                if (RELU) {
                    r.x = fmaxf(r.x, 0.f);
                    r.y = fmaxf(r.y, 0.f);
                }
                if (TF32OUT) {
                    r.x = rna_tf32(r.x);
                    r.y = rna_tf32(r.y);
                }
                *(float2*)(C + (long long)m * ldc + n) = r;
            }
        }
    }
}

// ================= fused flash attention (tf32 MMA, online softmax) ========
#define QSTR 132
#define KSTR 132
#define VSTR 136
#define PSTR 36
static const int FLASH_SMEM = (128*QSTR + 2*32*KSTR + 2*32*VSTR + 128*PSTR) * 4;

__global__ void __launch_bounds__(256, 1)
flash_attn_kernel(const float* __restrict__ qkv, float* __restrict__ ao)
{
    extern __shared__ __align__(16) float sm[];
    float* Qs = sm;
    float* Ks = Qs + 128 * QSTR;
    float* Vs = Ks + 2 * 32 * KSTR;
    float* Ps = Vs + 2 * 32 * VSTR;

    int qt = blockIdx.x;
    int bh = blockIdx.y;
    int b = bh / NHE, h = bh - b * NHE;
    const float* qbase = qkv + (long long)b * NN * HD4 + (long long)qt * 128 * HD4 + HD + h * DHE;
    const float* kbase = qkv + (long long)b * NN * HD4 + 2 * HD + h * DHE;
    const float* vbase = qkv + (long long)b * NN * HD4 + 3 * HD + h * DHE;

    int tid = threadIdx.x;
    int lane = tid & 31, wid = tid >> 5;
    int tig = lane & 3, grp = lane >> 2;
    int wq = wid * 16;

    #pragma unroll
    for (int c = 0; c < 16; c++) {
        int chunk = tid + c * 256;
        int row = chunk >> 5, col = (chunk & 31) * 4;
        cpa16(&Qs[row * QSTR + col], qbase + (long long)row * HD4 + col);
    }
    #pragma unroll
    for (int c = 0; c < 4; c++) {
        int chunk = tid + c * 256;
        int row = chunk >> 5, col = (chunk & 31) * 4;
        cpa16(&Ks[row * KSTR + col], kbase + (long long)row * HD4 + col);
        cpa16(&Vs[row * VSTR + col], vbase + (long long)row * HD4 + col);
    }
    cpa_commit();

    float Oacc[16][4];
    #pragma unroll
    for (int nt = 0; nt < 16; nt++)
        #pragma unroll
        for (int j = 0; j < 4; j++) Oacc[nt][j] = 0.f;
    float m0r = -1e30f, m1r = -1e30f;
    float l0 = 0.f, l1 = 0.f;
    const float alpha = 0.08838834764831843f;

    int cur = 0;
    for (int it = 0; it < 32; it++) {
        bool more = (it + 1 < 32);
        if (more) {
            int nxt = cur ^ 1;
            const float* kb = kbase + (long long)(it + 1) * 32 * HD4;
            const float* vb = vbase + (long long)(it + 1) * 32 * HD4;
            #pragma unroll
            for (int c = 0; c < 4; c++) {
                int chunk = tid + c * 256;
                int row = chunk >> 5, col = (chunk & 31) * 4;
                cpa16(&Ks[nxt * 32 * KSTR + row * KSTR + col], kb + (long long)row * HD4 + col);
                cpa16(&Vs[nxt * 32 * VSTR + row * VSTR + col], vb + (long long)row * HD4 + col);
            }
            cpa_commit();
            cpa_wait<1>();
        } else {
            cpa_wait<0>();
        }
        __syncthreads();

        const float* Kc = Ks + cur * 32 * KSTR;
        const float* Vc = Vs + cur * 32 * VSTR;

        float s[4][4];
        #pragma unroll
        for (int nt = 0; nt < 4; nt++)
            #pragma unroll
            for (int j = 0; j < 4; j++) s[nt][j] = 0.f;
        #pragma unroll
        for (int kc = 0; kc < 16; kc++) {
            uint32_t af[4];
            af[0] = __float_as_uint(Qs[(wq + grp) * QSTR + kc * 8 + tig]);
            af[1] = __float_as_uint(Qs[(wq + grp + 8) * QSTR + kc * 8 + tig]);
            af[2] = __float_as_uint(Qs[(wq + grp) * QSTR + kc * 8 + tig + 4]);
            af[3] = __float_as_uint(Qs[(wq + grp + 8) * QSTR + kc * 8 + tig + 4]);
            #pragma unroll
            for (int nt = 0; nt < 4; nt++) {
                uint32_t b0 = __float_as_uint(Kc[(nt * 8 + grp) * KSTR + kc * 8 + tig]);
                uint32_t b1 = __float_as_uint(Kc[(nt * 8 + grp) * KSTR + kc * 8 + tig + 4]);
                mma_tf32(s[nt], af, b0, b1);
            }
        }

        float t0 = -1e30f, t1 = -1e30f;
        #pragma unroll
        for (int nt = 0; nt < 4; nt++) {
            s[nt][0] *= alpha; s[nt][1] *= alpha;
            s[nt][2] *= alpha; s[nt][3] *= alpha;
            t0 = fmaxf(t0, fmaxf(s[nt][0], s[nt][1]));
            t1 = fmaxf(t1, fmaxf(s[nt][2], s[nt][3]));
        }
        t0 = fmaxf(t0, __shfl_xor_sync(0xffffffffu, t0, 1));
        t0 = fmaxf(t0, __shfl_xor_sync(0xffffffffu, t0, 2));
        t1 = fmaxf(t1, __shfl_xor_sync(0xffffffffu, t1, 1));
        t1 = fmaxf(t1, __shfl_xor_sync(0xffffffffu, t1, 2));
        float mn0 = fmaxf(m0r, t0), mn1 = fmaxf(m1r, t1);
        float f0 = __expf(m0r - mn0), f1 = __expf(m1r - mn1);
        float ps0 = 0.f, ps1 = 0.f;
        #pragma unroll
        for (int nt = 0; nt < 4; nt++) {
            float p0 = __expf(s[nt][0] - mn0);
            float p1 = __expf(s[nt][1] - mn0);
            float p2 = __expf(s[nt][2] - mn1);
            float p3 = __expf(s[nt][3] - mn1);
            ps0 += p0 + p1;
            ps1 += p2 + p3;
            float2 lo = { rna_tf32(p0), rna_tf32(p1) };
            float2 hi = { rna_tf32(p2), rna_tf32(p3) };
            *(float2*)&Ps[(wq + grp) * PSTR + nt * 8 + 2 * tig] = lo;
            *(float2*)&Ps[(wq + grp + 8) * PSTR + nt * 8 + 2 * tig] = hi;
        }
        ps0 += __shfl_xor_sync(0xffffffffu, ps0, 1);
        ps0 += __shfl_xor_sync(0xffffffffu, ps0, 2);
        ps1 += __shfl_xor_sync(0xffffffffu, ps1, 1);
        ps1 += __shfl_xor_sync(0xffffffffu, ps1, 2);
        l0 = l0 * f0 + ps0;
        l1 = l1 * f1 + ps1;
        m0r = mn0; m1r = mn1;
        #pragma unroll
        for (int nt = 0; nt < 16; nt++) {
            Oacc[nt][0] *= f0; Oacc[nt][1] *= f0;
            Oacc[nt][2] *= f1; Oacc[nt][3] *= f1;
        }
        __syncwarp();

        #pragma unroll
        for (int kc = 0; kc < 4; kc++) {
            uint32_t af[4];
            af[0] = __float_as_uint(Ps[(wq + grp) * PSTR + kc * 8 + tig]);
            af[1] = __float_as_uint(Ps[(wq + grp + 8) * PSTR + kc * 8 + tig]);
            af[2] = __float_as_uint(Ps[(wq + grp) * PSTR + kc * 8 + tig + 4]);
            af[3] = __float_as_uint(Ps[(wq + grp + 8) * PSTR + kc * 8 + tig + 4]);
            #pragma unroll
            for (int nt = 0; nt < 16; nt++) {
                uint32_t b0 = __float_as_uint(Vc[(kc * 8 + tig) * VSTR + nt * 8 + grp]);
                uint32_t b1 = __float_as_uint(Vc[(kc * 8 + tig + 4) * VSTR + nt * 8 + grp]);
                mma_tf32(Oacc[nt], af, b0, b1);
            }
        }
        if (!more) break;
        __syncthreads();
        cur ^= 1;
    }

    float inv0 = 1.f / l0, inv1 = 1.f / l1;
    int r0 = qt * 128 + wq + grp;
    float* o0 = ao + (long long)b * NN * HD + (long long)r0 * HD + h * DHE;
    float* o1 = o0 + 8 * HD;
    #pragma unroll
    for (int nt = 0; nt < 16; nt++) {
        int col = nt * 8 + 2 * tig;
        float2 va = { rna_tf32(Oacc[nt][0] * inv0), rna_tf32(Oacc[nt][1] * inv0) };
        float2 vb = { rna_tf32(Oacc[nt][2] * inv1), rna_tf32(Oacc[nt][3] * inv1) };
        *(float2*)(o0 + col) = va;
        *(float2*)(o1 + col) = vb;
    }
}

// ---------------- small kernels ----------------
__global__ void feats_kernel(const float* __restrict__ x, float* __restrict__ feats)
{
    long long i = (long long)blockIdx.x * blockDim.x + threadIdx.x;
    if (i >= (long long)NB * NN * CIN) return;
    int c = (int)(i & (CIN - 1));
    long long bn = i >> 6;
    int n = (int)(bn & (NN - 1));
    int b = (int)(bn >> 10);
    feats[i] = x[((long long)b * CIN + c) * NN + n];
}

__global__ void prep_kernel(const float* __restrict__ gcn_W, const float* __restrict__ Wq,
                            const float* __restrict__ Wk, const float* __restrict__ Wv,
                            const float* __restrict__ gcn_b, const float* __restrict__ bq,
                            const float* __restrict__ bk, const float* __restrict__ bv,
                            const float* __restrict__ Wo, const float* __restrict__ W1,
                            const float* __restrict__ W2,
                            float* __restrict__ wpack, float* __restrict__ bpack,
                            float* __restrict__ wr)
{
    int i = blockIdx.x * blockDim.x + threadIdx.x;
    const int NWP = 3 * 384 * 1536;
    const int NBP = 3 * 1536;
    const int NWO = 442368;
    const int NW1 = 884736;
    if (i < NWP) {
        int l = i / (384 * 1536);
        int rem = i - l * (384 * 1536);
        int r = rem / 1536;
        int c = rem - r * 1536;
        int sel = c / 384, cc = c - sel * 384;
        const float* src = (sel == 0) ? gcn_W : (sel == 1) ? Wq : (sel == 2) ? Wk : Wv;
        wpack[i] = rna_tf32(src[((long long)l * 384 + r) * 384 + cc]);
        return;
    }
    int j = i - NWP;
    if (j < NBP) {
        int l = j / 1536;
        int c = j - l * 1536;
        int sel = c / 384, cc = c - sel * 384;
        const float* src = (sel == 0) ? gcn_b : (sel == 1) ? bq : (sel == 2) ? bk : bv;
        bpack[j] = src[l * 384 + cc];
        return;
    }
    j -= NBP;
    if (j < NWO) { wr[WR_WO + j] = rna_tf32(Wo[j]); return; }
    j -= NWO;
    if (j < NW1) { wr[WR_W1 + j] = rna_tf32(W1[j]); return; }
    j -= NW1;
    if (j < NW1) { wr[WR_W2 + j] = rna_tf32(W2[j]); return; }
}

__device__ __forceinline__ void block_reduce2(float& s1, float& s2)
{
    __shared__ float b1[4], b2[4];
    #pragma unroll
    for (int o = 16; o > 0; o >>= 1) {
        s1 += __shfl_down_sync(0xffffffffu, s1, o);
        s2 += __shfl_down_sync(0xffffffffu, s2, o);
    }
    int w = threadIdx.x >> 5;
    if ((threadIdx.x & 31) == 0) { b1[w] = s1; b2[w] = s2; }
    __syncthreads();
    s1 = b1[0] + b1[1] + b1[2] + b1[3];
    s2 = b2[0] + b2[1] + b2[2] + b2[3];
}

__global__ void norm_kernel(const float* __restrict__ h0, float* __restrict__ nh,
                            float* __restrict__ h0r)
{
    long long bn = blockIdx.x;
    int t = threadIdx.x; // 128
    const float* r = h0 + bn * HD;
    float v0 = r[t], v1 = r[t + 128], v2 = r[t + 256];
    float ss = v0 * v0 + v1 * v1 + v2 * v2, dummy = 0.f;
    block_reduce2(ss, dummy);
    float rinv = rsqrtf(ss);
    float* o = nh + bn * HD;
    o[t] = v0 * rinv; o[t + 128] = v1 * rinv; o[t + 256] = v2 * rinv;
    float* o2 = h0r + bn * HD;
    o2[t] = rna_tf32(v0); o2[t + 128] = rna_tf32(v1); o2[t + 256] = rna_tf32(v2);
}

__global__ void topk_warp_kernel(const float* __restrict__ sim, int* __restrict__ knn)
{
    int warp = blockIdx.x * (blockDim.x >> 5) + (threadIdx.x >> 5);
    if (warp >= NB * NN) return;
    int lane = threadIdx.x & 31;
    int n = warp & (NN - 1);
    const float* row = sim + (long long)warp * NN;
    float v[32];
    #pragma unroll
    for (int j = 0; j < 32; j++) {
        int m = j * 32 + lane;
        v[j] = (m == n) ? -3e38f : row[m];
    }
    unsigned taken = 0;
    int* o = knn + (long long)warp * KNN;
    for (int r = 0; r < KNN; r++) {
        float bv = -3e38f; int bj = 0;
        #pragma unroll
        for (int j = 0; j < 32; j++) {
            bool free_ = !((taken >> j) & 1u);
            if (free_ && v[j] > bv) { bv = v[j]; bj = j; }
        }
        int bidx = bj * 32 + lane;
        #pragma unroll
        for (int off = 16; off > 0; off >>= 1) {
            float ov = __shfl_xor_sync(0xffffffffu, bv, off);
            int   oi = __shfl_xor_sync(0xffffffffu, bidx, off);
            if (ov > bv || (ov == bv && oi < bidx)) { bv = ov; bidx = oi; }
        }
        if ((bidx & 31) == lane) taken |= 1u << (bidx >> 5);
        if (lane == 0) o[r] = bidx;
    }
}

__global__ void gcn_agg_ln(const float* __restrict__ hcur, const float* __restrict__ xw,
                           int ldx,
                           const int* __restrict__ knn,
                           const float* __restrict__ scale, const float* __restrict__ bias,
                           float* __restrict__ out)
{
    int bn = blockIdx.x;
    int b = bn >> 10;
    int t = threadIdx.x; // 128
    __shared__ int sidx[KNN];
    if (t < KNN) sidx[t] = knn[(long long)bn * KNN + t];
    __syncthreads();
    const float* xr = xw + (long long)bn * ldx;
    float a0 = xr[t], a1 = xr[t + 128], a2 = xr[t + 256];
    #pragma unroll 4
    for (int j = 0; j < KNN; j++) {
        const float* r = xw + ((long long)(b * NN) + sidx[j]) * ldx;
        a0 += r[t]; a1 += r[t + 128]; a2 += r[t + 256];
    }
    const float* h = hcur + (long long)bn * HD;
    const float inv17 = 1.f / 17.f;
    float v0 = h[t] + a0 * inv17;
    float v1 = h[t + 128] + a1 * inv17;
    float v2 = h[t + 256] + a2 * inv17;
    float s1 = v0 + v1 + v2;
    float s2 = v0 * v0 + v1 * v1 + v2 * v2;
    block_reduce2(s1, s2);
    float mu = s1 * (1.f / HD);
    float var = s2 * (1.f / HD) - mu * mu;
    float rstd = rsqrtf(var + 1e-5f);
    float* o = out + (long long)bn * HD;
    o[t]       = (v0 - mu) * rstd * scale[t]       + bias[t];
    o[t + 128] = (v1 - mu) * rstd * scale[t + 128] + bias[t + 128];
    o[t + 256] = (v2 - mu) * rstd * scale[t + 256] + bias[t + 256];
}

__global__ void add_ln_kernel(const float* __restrict__ a, const float* __restrict__ b,
                              const float* __restrict__ plus,
                              const float* __restrict__ scale, const float* __restrict__ bias,
                              float* __restrict__ out, int rnd)
{
    long long bn = blockIdx.x;
    int t = threadIdx.x; // 128
    const float* ar = a + bn * HD;
    float v0 = ar[t], v1 = ar[t + 128], v2 = ar[t + 256];
    if (b) {
        const float* br = b + bn * HD;
        v0 += br[t]; v1 += br[t + 128]; v2 += br[t + 256];
    }
    float s1 = v0 + v1 + v2;
    float s2 = v0 * v0 + v1 * v1 + v2 * v2;
    block_reduce2(s1, s2);
    float mu = s1 * (1.f / HD);
    float var = s2 * (1.f / HD) - mu * mu;
    float rstd = rsqrtf(var + 1e-5f);
    float y0 = (v0 - mu) * rstd * scale[t]       + bias[t];
    float y1 = (v1 - mu) * rstd * scale[t + 128] + bias[t + 128];
    float y2 = (v2 - mu) * rstd * scale[t + 256] + bias[t + 256];
    if (plus) {
        const float* pr = plus + bn * HD;
        y0 += pr[t]; y1 += pr[t + 128]; y2 += pr[t + 256];
    }
    if (rnd) { y0 = rna_tf32(y0); y1 = rna_tf32(y1); y2 = rna_tf32(y2); }
    float* o = out + bn * HD;
    o[t] = y0; o[t + 128] = y1; o[t + 256] = y2;
}

__global__ void pool_kernel(const float* __restrict__ h, float* __restrict__ pooled)
{
    int b = blockIdx.x;
    int t = threadIdx.x; // 384
    float s = 0.f;
    const float* base = h + (long long)b * NN * HD + t;
    for (int n = 0; n < NN; n++) s += base[(long long)n * HD];
    pooled[b * HD + t] = s * (1.f / NN);
}

__global__ void fin1_kernel(const float* __restrict__ pooled, const float* __restrict__ W,
                            const float* __restrict__ bias, float* __restrict__ z)
{
    int b = blockIdx.x;
    int j = threadIdx.x; // 384
    const float* p = pooled + b * HD;
    float s = bias[j];
    for (int k = 0; k < HD; k++) s = fmaf(p[k], W[k * HD + j], s);
    z[b * HD + j] = fmaxf(s, 0.f);
}

__global__ void fin2_kernel(const float* __restrict__ z, const float* __restrict__ W,
                            const float* __restrict__ bias, float* __restrict__ out)
{
    int b = blockIdx.x;
    int j = threadIdx.x; // 128
    const float* p = z + b * HD;
    float s = bias[j];
    for (int k = 0; k < HD; k++) s = fmaf(p[k], W[k * 128 + j], s);
    out[b * 128 + j] = s;
}

// ---------------- host-side GEMM dispatchers ----------------
static void gemm_f32(const float* A, const float* B, const float* bias, const float* Res, float* C,
                     int M, int Nn, int K, int lda, int ldb, int ldc,
                     long long sA, long long sAi, long long sB, long long sBi,
                     long long sC, long long sCi, int zi, int nz,
                     float alpha, bool transb, bool relu, cudaStream_t st = 0)
{
    dim3 grid(Nn / BN, M / BM, nz), block(256);
    if (transb) {
        if (relu) gemm_k<true, true ><<<grid, block, 0, st>>>(A, B, bias, Res, C, M, Nn, K, lda, ldb, ldc, sA, sAi, sB, sBi, sC, sCi, zi, alpha);
        else      gemm_k<true, false><<<grid, block, 0, st>>>(A, B, bias, Res, C, M, Nn, K, lda, ldb, ldc, sA, sAi, sB, sBi, sC, sCi, zi, alpha);
    } else {
        if (relu) gemm_k<false, true ><<<grid, block, 0, st>>>(A, B, bias, Res, C, M, Nn, K, lda, ldb, ldc, sA, sAi, sB, sBi, sC, sCi, zi, alpha);
        else      gemm_k<false, false><<<grid, block, 0, st>>>(A, B, bias, Res, C, M, Nn, K, lda, ldb, ldc, sA, sAi, sB, sBi, sC, sCi, zi, alpha);
    }
}

static void gemm_tf(const float* A, const float* B, const float* bias, const float* Res, float* C,
                    int M, int Nn, int K, int lda, int ldb, int ldc,
                    long long sA, long long sAi, long long sB, long long sBi,
                    long long sC, long long sCi, int zi, int nz,
                    float alpha, bool transb, bool relu, bool tf32out, int ntile,
                    cudaStream_t st = 0)
{
    dim3 grid(Nn / ntile, M / 128, nz), block(256);
    #define DISP(TB, RL, TO, NTL) do { \
        constexpr int BSZc = TB ? (NTL * ASTRIDE) : (16 * ((NTL == 128) ? BN128STR : BN64STR)); \
        int smemb = (3 * 128 * ASTRIDE + 3 * BSZc) * 4; \
        cudaFuncSetAttribute(tf32gemm_k<TB, RL, TO, NTL>, cudaFuncAttributeMaxDynamicSharedMemorySize, smemb); \
        tf32gemm_k<TB, RL, TO, NTL><<<grid, block, smemb, st>>>(A, B, bias, Res, C, K, lda, ldb, ldc, sA, sAi, sB, sBi, sC, sCi, zi, alpha); \
    } while (0)
    if (ntile == 128) {
        if (transb) {
            if (relu)  { if (tf32out) DISP(true, true, true, 128);  else DISP(true, true, false, 128); }
            else       { if (tf32out) DISP(true, false, true, 128); else DISP(true, false, false, 128); }
        } else {
            if (relu)  { if (tf32out) DISP(false, true, true, 128);  else DISP(false, true, false, 128); }
            else       { if (tf32out) DISP(false, false, true, 128); else DISP(false, false, false, 128); }
        }
    } else {
        if (transb) {
            if (relu)  { if (tf32out) DISP(true, true, true, 64);  else DISP(true, true, false, 64); }
            else       { if (tf32out) DISP(true, false, true, 64); else DISP(true, false, false, 64); }
        } else {
            if (relu)  { if (tf32out) DISP(false, true, true, 64);  else DISP(false, true, false, 64); }
            else       { if (tf32out) DISP(false, false, true, 64); else DISP(false, false, false, 64); }
        }
    }
    #undef DISP
}

template<typename T> static T* sym_addr(const void* sym)
{
    void* p = nullptr;
    cudaGetSymbolAddress(&p, sym);
    return (T*)p;
}

extern "C" void kernel_launch(void* const* d_in, const int* in_sizes, int n_in,
                              void* d_out, int out_size)
{
    const float* x      = (const float*)d_in[0];
    const float* W_enc  = (const float*)d_in[1];
    const float* b_enc  = (const float*)d_in[2];
    const float* gcn_W  = (const float*)d_in[3];
    const float* gcn_b  = (const float*)d_in[4];
    const float* Wq     = (const float*)d_in[5];
    const float* bq     = (const float*)d_in[6];
    const float* Wk     = (const float*)d_in[7];
    const float* bk     = (const float*)d_in[8];
    const float* Wv     = (const float*)d_in[9];
    const float* bv     = (const float*)d_in[10];
    const float* Wo     = (const float*)d_in[11];
    const float* bo     = (const float*)d_in[12];
    const float* lnsc   = (const float*)d_in[13];
    const float* lnbi   = (const float*)d_in[14];
    const float* W1     = (const float*)d_in[15];
    const float* b1     = (const float*)d_in[16];
    const float* W2     = (const float*)d_in[17];
    const float* b2     = (const float*)d_in[18];
    const float* lin1_W = (const float*)d_in[19];
    const float* lin1_b = (const float*)d_in[20];
    const float* lin2_W = (const float*)d_in[21];
    const float* lin2_b = (const float*)d_in[22];
    float* outp = (float*)d_out;

    float* featsp = sym_addr<float>(g_feats);
    float* h0p    = sym_addr<float>(g_h0);
    float* h0rp   = sym_addr<float>(g_h0r);
    float* nhp    = sym_addr<float>(g_nh);
    float* simp   = sym_addr<float>(g_sim);
    int*   knnp   = sym_addr<int>(g_knn);
    float* hcurp  = sym_addr<float>(g_hcur);
    float* qkvgp  = sym_addr<float>(g_qkvg);
    float* hlocp  = sym_addr<float>(g_hloc);
    float* aop    = sym_addr<float>(g_ao);
    float* op     = sym_addr<float>(g_o);
    float* combp  = sym_addr<float>(g_comb);
    float* mlp1p  = sym_addr<float>(g_mlp1);
    float* ffp    = sym_addr<float>(g_ff);
    float* poolp  = sym_addr<float>(g_pool);
    float* zp     = sym_addr<float>(g_z);
    float* wpackp = sym_addr<float>(g_wpack);
    float* bpackp = sym_addr<float>(g_bpack);
    float* wrp    = sym_addr<float>(g_wr);

    cudaFuncSetAttribute(flash_attn_kernel, cudaFuncAttributeMaxDynamicSharedMemorySize, FLASH_SMEM);

    const long long NH  = (long long)NN * HD;
    const long long NH4 = (long long)NN * HD4;
    const int WSQ = HD * HD;

    // side stream + events (fork-join pattern; capture-legal)
    cudaStream_t sB;
    cudaStreamCreateWithFlags(&sB, cudaStreamNonBlocking);
    cudaEvent_t evFork, evProj, evWo[NL], evFork2[NL];
    cudaEventCreateWithFlags(&evFork, cudaEventDisableTiming);
    cudaEventCreateWithFlags(&evProj, cudaEventDisableTiming);
    for (int l = 0; l < NL; l++) {
        cudaEventCreateWithFlags(&evWo[l], cudaEventDisableTiming);
        cudaEventCreateWithFlags(&evFork2[l], cudaEventDisableTiming);
    }

    // prep + encoder + norm on main stream
    {
        int total = 3 * 384 * 1536 + 3 * 1536 + 442368 + 884736 + 884736;
        prep_kernel<<<(total + 255) / 256, 256>>>(gcn_W, Wq, Wk, Wv, gcn_b, bq, bk, bv,
                                                  Wo, W1, W2, wpackp, bpackp, wrp);
    }
    feats_kernel<<<(NB * NN * CIN + 255) / 256, 256>>>(x, featsp);
    gemm_f32(featsp, W_enc, b_enc, nullptr, h0p,
             NN, HD, CIN, CIN, HD, HD,
             (long long)NN * CIN, 0, 0, 0, NH, 0, 1, NB, 1.f, false, false);
    norm_kernel<<<NB * NN, 128>>>(h0p, nhp, h0rp);

    // fork: sB runs layer-0 tensor chain (proj0 -> flash0 -> Wo0)
    cudaEventRecord(evFork, 0);
    cudaStreamWaitEvent(sB, evFork, 0);
    gemm_tf(h0rp, wpackp, bpackp, nullptr, qkvgp,
            NN, HD4, HD, HD, HD4, HD4, NH, 0, 0, 0, NH4, 0, 1, NB,
            1.f, false, false, true, 128, sB);
    cudaEventRecord(evProj, sB);
    flash_attn_kernel<<<dim3(NN / 128, NB * NHE), 256, FLASH_SMEM, sB>>>(qkvgp, aop);
    gemm_tf(aop, wrp + WR_WO, bo, nullptr, op,
            NN, HD, HD, HD, HD, HD, NH, 0, 0, 0, NH, 0, 1, NB,
            1.f, false, false, false, 64, sB);
    cudaEventRecord(evWo[0], sB);

    // main stream: graph build (fma-pipe work) concurrent with sB
    gemm_f32(nhp, nhp, nullptr, nullptr, simp,
             NN, NN, HD, HD, HD, NN,
             NH, 0, NH, 0, (long long)NN * NN, 0, 1, NB, 1.f, true, false);
    topk_warp_kernel<<<NB * NN / 8, 256>>>(simp, knnp);

    const float* hin = h0rp;
    for (int l = 0; l < NL; l++) {
        const float* scl = lnsc + (l * 3) * HD;
        const float* bil = lnbi + (l * 3) * HD;

        if (l > 0) {
            // proj on main stream, then fork flash+Wo onto sB
            gemm_tf(hin, wpackp + (long long)l * HD * HD4, bpackp + l * HD4, nullptr, qkvgp,
                    NN, HD4, HD, HD, HD4, HD4, NH, 0, 0, 0, NH4, 0, 1, NB,
                    1.f, false, false, true, 128);
            cudaEventRecord(evFork2[l], 0);
            cudaStreamWaitEvent(sB, evFork2[l], 0);
            flash_attn_kernel<<<dim3(NN / 128, NB * NHE), 256, FLASH_SMEM, sB>>>(qkvgp, aop);
            gemm_tf(aop, wrp + WR_WO + (long long)l * WSQ, bo + l * HD, nullptr, op,
                    NN, HD, HD, HD, HD, HD, NH, 0, 0, 0, NH, 0, 1, NB,
                    1.f, false, false, false, 64, sB);
            cudaEventRecord(evWo[l], sB);
        } else {
            // layer 0: gcn needs proj0 (from sB) + topk (main)
            cudaStreamWaitEvent(0, evProj, 0);
        }

        // gcn branch on main stream (overlaps flash/Wo on sB)
        gcn_agg_ln<<<NB * NN, 128>>>(hin, qkvgp, HD4, knnp, scl, bil, hlocp);

        // join: add_ln needs Wo output
        cudaStreamWaitEvent(0, evWo[l], 0);
        add_ln_kernel<<<NB * NN, 128>>>(hin, op, hlocp, scl + HD, bil + HD, combp, 1);

        // FFN
        gemm_tf(combp, wrp + WR_W1 + (long long)l * HD * 2 * HD, b1 + l * 2 * HD, nullptr, mlp1p,
                NN, 2 * HD, HD, HD, 2 * HD, 2 * HD,
                NH, 0, 0, 0, (long long)NN * 2 * HD, 0, 1, NB, 1.f, false, true, true, 128);
        gemm_tf(mlp1p, wrp + WR_W2 + (long long)l * 2 * HD * HD, b2 + l * HD, combp, ffp,
                NN, HD, 2 * HD, 2 * HD, HD, HD,
                (long long)NN * 2 * HD, 0, 0, 0, NH, 0, 1, NB, 1.f, false, false, false, 64);
        add_ln_kernel<<<NB * NN, 128>>>(ffp, nullptr, nullptr, scl + 2 * HD, bil + 2 * HD, hcurp, 1);
        hin = hcurp;
    }

    // ---- head ----
    pool_kernel<<<NB, HD>>>(hin, poolp);
    fin1_kernel<<<NB, HD>>>(poolp, lin1_W, lin1_b, zp);
    fin2_kernel<<<NB, 128>>>(zp, lin2_W, lin2_b, outp);

    cudaEventDestroy(evFork);
    cudaEventDestroy(evProj);
    for (int l = 0; l < NL; l++) {
        cudaEventDestroy(evWo[l]);
        cudaEventDestroy(evFork2[l]);
    }
    cudaStreamDestroy(sB);
}

// round 8
// speedup vs baseline: 3.2571x; 1.0067x over previous
#include <cuda_runtime.h>
#include <math.h>
#include <stdint.h>

// ---------------- problem constants ----------------
static const int NB   = 8;     // batch
static const int NN   = 1024;  // nodes (32*32)
static const int CIN  = 64;    // input channels
static const int HD   = 384;   // hidden
static const int NL   = 3;     // layers
static const int KNN  = 16;    // k
static const int NHE  = 3;     // heads
static const int DHE  = 128;   // head dim
static const int HD4  = 4 * HD; // 1536 packed width

// ---------------- device scratch (no allocs allowed) ----------------
__device__ float g_feats [NB*NN*CIN];
__device__ float g_h0    [NB*NN*HD];
__device__ float g_h0r   [NB*NN*HD];
__device__ float g_nh    [NB*NN*HD];
__device__ float g_sim   [NB*NN*NN];
__device__ int   g_knn   [NB*NN*KNN];
__device__ float g_hcur  [NB*NN*HD];
__device__ float g_qkvg  [NB*NN*4*HD];   // packed [gcn | q | k | v]
__device__ float g_hloc  [NB*NN*HD];
__device__ float g_ao    [NB*NN*HD];
__device__ float g_o     [NB*NN*HD];
__device__ float g_comb  [NB*NN*HD];
__device__ float g_mlp1  [NB*NN*2*HD];
__device__ float g_ff    [NB*NN*HD];
__device__ float g_pool  [NB*HD];
__device__ float g_z     [NB*HD];
// packed fused projection weights [L][384][1536] + biases [L][1536]
__device__ float g_wpack [3*384*1536];
__device__ float g_bpack [3*1536];
// rounded weights: WO, W1, W2
__device__ float g_wr    [2211840];
static const long long WR_WO  = 0;
static const long long WR_W1  = 442368;
static const long long WR_W2  = 1327104;

__device__ __forceinline__ float rna_tf32(float x)
{
    uint32_t r;
    asm("cvt.rna.tf32.f32 %0, %1;" : "=r"(r) : "f"(x));
    return __uint_as_float(r);
}

// ================= fp32 SIMT GEMM (exact path: encoder) ====================
#define BM 128
#define BN 128
#define BKK 8
#define SPAD 132

template<bool TRANSB, bool RELU>
__global__ void __launch_bounds__(256, 2)
gemm_k(const float* __restrict__ A, const float* __restrict__ B,
       const float* __restrict__ bias, const float* __restrict__ Res,
       float* __restrict__ C,
       int M, int Nn, int K, int lda, int ldb, int ldc,
       long long sA, long long sAi, long long sB, long long sBi,
       long long sC, long long sCi, int zi, float alpha)
{
    int bz = blockIdx.z;
    int zo = bz / zi, zin = bz % zi;
    A += zo * sA + zin * sAi;
    B += zo * sB + zin * sBi;
    C += zo * sC + zin * sCi;
    if (Res) Res += zo * sC + zin * sCi;

    int m0 = blockIdx.y * BM;
    int n0 = blockIdx.x * BN;

    __shared__ float As[2][BKK][SPAD];
    __shared__ float Bs[2][BKK][SPAD];

    int tid = threadIdx.x;
    int tx = tid & 15;
    int ty = tid >> 4;

    int a_m = tid >> 1;
    int a_k = (tid & 1) * 4;
    const float* Aload = A + (long long)(m0 + a_m) * lda + a_k;

    const float* Bload;
    int b_k = 0, b_n = 0;
    if (TRANSB) {
        Bload = B + (long long)(n0 + a_m) * ldb + a_k;
    } else {
        b_k = tid >> 5;
        b_n = (tid & 31) * 4;
        Bload = B + (long long)b_k * ldb + n0 + b_n;
    }

    float4 av = *(const float4*)Aload;
    float4 bv = *(const float4*)Bload;

    As[0][a_k + 0][a_m] = av.x;
    As[0][a_k + 1][a_m] = av.y;
    As[0][a_k + 2][a_m] = av.z;
    As[0][a_k + 3][a_m] = av.w;
    if (TRANSB) {
        Bs[0][a_k + 0][a_m] = bv.x;
        Bs[0][a_k + 1][a_m] = bv.y;
        Bs[0][a_k + 2][a_m] = bv.z;
        Bs[0][a_k + 3][a_m] = bv.w;
    } else {
        *(float4*)&Bs[0][b_k][b_n] = bv;
    }
    __syncthreads();

    float acc[8][8];
    #pragma unroll
    for (int i = 0; i < 8; i++)
        #pragma unroll
        for (int j = 0; j < 8; j++) acc[i][j] = 0.f;

    int cur = 0;
    for (int k0 = 0; ; ) {
        int k1 = k0 + BKK;
        bool more = (k1 < K);
        if (more) {
            av = *(const float4*)(Aload + k1);
            if (TRANSB) bv = *(const float4*)(Bload + k1);
            else        bv = *(const float4*)(Bload + (long long)k1 * ldb);
        }

        #pragma unroll
        for (int kk = 0; kk < BKK; kk++) {
            float4 a0 = *(const float4*)&As[cur][kk][ty * 4];
            float4 a1 = *(const float4*)&As[cur][kk][64 + ty * 4];
            float4 b0 = *(const float4*)&Bs[cur][kk][tx * 4];
            float4 b1 = *(const float4*)&Bs[cur][kk][64 + tx * 4];
            float a[8] = {a0.x, a0.y, a0.z, a0.w, a1.x, a1.y, a1.z, a1.w};
            float b[8] = {b0.x, b0.y, b0.z, b0.w, b1.x, b1.y, b1.z, b1.w};
            #pragma unroll
            for (int i = 0; i < 8; i++)
                #pragma unroll
                for (int j = 0; j < 8; j++)
                    acc[i][j] = fmaf(a[i], b[j], acc[i][j]);
        }
        if (!more) break;

        int nxt = cur ^ 1;
        As[nxt][a_k + 0][a_m] = av.x;
        As[nxt][a_k + 1][a_m] = av.y;
        As[nxt][a_k + 2][a_m] = av.z;
        As[nxt][a_k + 3][a_m] = av.w;
        if (TRANSB) {
            Bs[nxt][a_k + 0][a_m] = bv.x;
            Bs[nxt][a_k + 1][a_m] = bv.y;
            Bs[nxt][a_k + 2][a_m] = bv.z;
            Bs[nxt][a_k + 3][a_m] = bv.w;
        } else {
            *(float4*)&Bs[nxt][b_k][b_n] = bv;
        }
        __syncthreads();
        cur = nxt;
        k0 = k1;
    }

    #pragma unroll
    for (int ih = 0; ih < 2; ih++) {
        #pragma unroll
        for (int i = 0; i < 4; i++) {
            int m = m0 + ih * 64 + ty * 4 + i;
            #pragma unroll
            for (int jh = 0; jh < 2; jh++) {
                int n = n0 + jh * 64 + tx * 4;
                float4 r;
                r.x = acc[ih * 4 + i][jh * 4 + 0] * alpha;
                r.y = acc[ih * 4 + i][jh * 4 + 1] * alpha;
                r.z = acc[ih * 4 + i][jh * 4 + 2] * alpha;
                r.w = acc[ih * 4 + i][jh * 4 + 3] * alpha;
                if (bias) {
                    float4 bb = *(const float4*)(bias + n);
                    r.x += bb.x; r.y += bb.y; r.z += bb.z; r.w += bb.w;
                }
                if (Res) {
                    float4 rr = *(const float4*)(Res + (long long)m * ldc + n);
                    r.x += rr.x; r.y += rr.y; r.z += rr.z; r.w += rr.w;
                }
                if (RELU) {
                    r.x = fmaxf(r.x, 0.f); r.y = fmaxf(r.y, 0.f);
                    r.z = fmaxf(r.z, 0.f); r.w = fmaxf(r.w, 0.f);
                }
                *(float4*)(C + (long long)m * ldc + n) = r;
            }
        }
    }
}

// ================= symmetric cosine-sim GEMM (fp32 exact) ==================
// sim = nh @ nh^T : compute lower-triangle 128x128 block pairs only; mirror
// off-diagonal tiles with transposed stores. Bit-identical values to full GEMM.
__global__ void __launch_bounds__(256, 2)
sim_gemm_k(const float* __restrict__ nh, float* __restrict__ sim)
{
    int t = blockIdx.x;              // 0..35 pair index
    int bi = 0;
    while ((bi + 1) * (bi + 2) / 2 <= t) bi++;
    int bj = t - bi * (bi + 1) / 2;  // bj <= bi
    int z = blockIdx.z;

    const float* A = nh + (long long)z * NN * HD;
    float* C = sim + (long long)z * NN * NN;
    int m0 = bi * 128;
    int n0 = bj * 128;

    __shared__ float As[2][BKK][SPAD];
    __shared__ float Bs[2][BKK][SPAD];

    int tid = threadIdx.x;
    int tx = tid & 15;
    int ty = tid >> 4;

    int a_m = tid >> 1;
    int a_k = (tid & 1) * 4;
    const float* Aload = A + (long long)(m0 + a_m) * HD + a_k;
    const float* Bload = A + (long long)(n0 + a_m) * HD + a_k;

    float4 av = *(const float4*)Aload;
    float4 bv = *(const float4*)Bload;

    As[0][a_k + 0][a_m] = av.x;
    As[0][a_k + 1][a_m] = av.y;
    As[0][a_k + 2][a_m] = av.z;
    As[0][a_k + 3][a_m] = av.w;
    Bs[0][a_k + 0][a_m] = bv.x;
    Bs[0][a_k + 1][a_m] = bv.y;
    Bs[0][a_k + 2][a_m] = bv.z;
    Bs[0][a_k + 3][a_m] = bv.w;
    __syncthreads();

    float acc[8][8];
    #pragma unroll
    for (int i = 0; i < 8; i++)
        #pragma unroll
        for (int j = 0; j < 8; j++) acc[i][j] = 0.f;

    int cur = 0;
    for (int k0 = 0; ; ) {
        int k1 = k0 + BKK;
        bool more = (k1 < HD);
        if (more) {
            av = *(const float4*)(Aload + k1);
            bv = *(const float4*)(Bload + k1);
        }
        #pragma unroll
        for (int kk = 0; kk < BKK; kk++) {
            float4 a0 = *(const float4*)&As[cur][kk][ty * 4];
            float4 a1 = *(const float4*)&As[cur][kk][64 + ty * 4];
            float4 b0 = *(const float4*)&Bs[cur][kk][tx * 4];
            float4 b1 = *(const float4*)&Bs[cur][kk][64 + tx * 4];
            float a[8] = {a0.x, a0.y, a0.z, a0.w, a1.x, a1.y, a1.z, a1.w};
            float b[8] = {b0.x, b0.y, b0.z, b0.w, b1.x, b1.y, b1.z, b1.w};
            #pragma unroll
            for (int i = 0; i < 8; i++)
                #pragma unroll
                for (int j = 0; j < 8; j++)
                    acc[i][j] = fmaf(a[i], b[j], acc[i][j]);
        }
        if (!more) break;

        int nxt = cur ^ 1;
        As[nxt][a_k + 0][a_m] = av.x;
        As[nxt][a_k + 1][a_m] = av.y;
        As[nxt][a_k + 2][a_m] = av.z;
        As[nxt][a_k + 3][a_m] = av.w;
        Bs[nxt][a_k + 0][a_m] = bv.x;
        Bs[nxt][a_k + 1][a_m] = bv.y;
        Bs[nxt][a_k + 2][a_m] = bv.z;
        Bs[nxt][a_k + 3][a_m] = bv.w;
        __syncthreads();
        cur = nxt;
        k0 = k1;
    }

    bool mirror = (bi != bj);
    #pragma unroll
    for (int ih = 0; ih < 2; ih++) {
        #pragma unroll
        for (int i = 0; i < 4; i++) {
            int m = m0 + ih * 64 + ty * 4 + i;
            #pragma unroll
            for (int jh = 0; jh < 2; jh++) {
                int n = n0 + jh * 64 + tx * 4;
                float4 r;
                r.x = acc[ih * 4 + i][jh * 4 + 0];
                r.y = acc[ih * 4 + i][jh * 4 + 1];
                r.z = acc[ih * 4 + i][jh * 4 + 2];
                r.w = acc[ih * 4 + i][jh * 4 + 3];
                *(float4*)(C + (long long)m * NN + n) = r;
                if (mirror) {
                    C[(long long)(n + 0) * NN + m] = r.x;
                    C[(long long)(n + 1) * NN + m] = r.y;
                    C[(long long)(n + 2) * NN + m] = r.z;
                    C[(long long)(n + 3) * NN + m] = r.w;
                }
            }
        }
    }
}

// ================= tf32 tensor-core GEMM, 3-stage cp.async ================
#define ASTRIDE 20
#define BN128STR 136
#define BN64STR  68

__device__ __forceinline__ void cpa16(void* dst, const void* src)
{
    uint32_t s = (uint32_t)__cvta_generic_to_shared(dst);
    asm volatile("cp.async.cg.shared.global [%0], [%1], 16;" :: "r"(s), "l"(src));
}
template<int N> __device__ __forceinline__ void cpa_wait()
{
    asm volatile("cp.async.wait_group %0;" :: "n"(N));
}
__device__ __forceinline__ void cpa_commit()
{
    asm volatile("cp.async.commit_group;");
}
__device__ __forceinline__ void mma_tf32(float* d, const uint32_t* a, uint32_t b0, uint32_t b1)
{
    asm volatile(
        "mma.sync.aligned.m16n8k8.row.col.f32.tf32.tf32.f32 "
        "{%0,%1,%2,%3}, {%4,%5,%6,%7}, {%8,%9}, {%0,%1,%2,%3};"
        : "+f"(d[0]), "+f"(d[1]), "+f"(d[2]), "+f"(d[3])
        : "r"(a[0]), "r"(a[1]), "r"(a[2]), "r"(a[3]), "r"(b0), "r"(b1));
}

template<bool TRANSB, bool RELU, bool TF32OUT, int NTILE>
__global__ void __launch_bounds__(256, 2)
tf32gemm_k(const float* __restrict__ A, const float* __restrict__ B,
           const float* __restrict__ bias, const float* __restrict__ Res,
           float* __restrict__ C,
           int K, int lda, int ldb, int ldc,
           long long sA, long long sAi, long long sB, long long sBi,
           long long sC, long long sCi, int zi, float alpha)
{
    constexpr int NT = NTILE / 16;
    constexpr int BSTR = (NTILE == 128) ? BN128STR : BN64STR;
    constexpr int ASZ = 128 * ASTRIDE;
    constexpr int BSZ = TRANSB ? (NTILE * ASTRIDE) : (16 * BSTR);

    extern __shared__ __align__(16) float dsm[];
    float* As = dsm;               // 3 * ASZ
    float* Bs = dsm + 3 * ASZ;     // 3 * BSZ

    int bz = blockIdx.z;
    int zo = bz / zi, zin = bz % zi;
    A += zo * sA + zin * sAi;
    B += zo * sB + zin * sBi;
    C += zo * sC + zin * sCi;
    if (Res) Res += zo * sC + zin * sCi;

    int m0 = blockIdx.y * 128;
    int n0 = blockIdx.x * NTILE;

    int tid = threadIdx.x;
    int lane = tid & 31;
    int wid = tid >> 5;
    int wm = (wid & 3) * 32;
    int wn = (wid >> 2) * (NTILE / 2);
    int tig = lane & 3;
    int grp = lane >> 2;

    int ra = tid >> 2;
    int ca = (tid & 3) * 4;
    const float* Asrc0 = A + (long long)(m0 + ra) * lda + ca;
    const float* Asrc1 = A + (long long)(m0 + ra + 64) * lda + ca;
    int aoff0 = ra * ASTRIDE + ca;
    int aoff1 = (ra + 64) * ASTRIDE + ca;

    const float *Bsrc0 = nullptr, *Bsrc1 = nullptr;
    int boff0 = 0, boff1 = 0;
    if (TRANSB) {
        if (NTILE == 128) {
            Bsrc0 = B + (long long)(n0 + ra) * ldb + ca;
            Bsrc1 = B + (long long)(n0 + ra + 64) * ldb + ca;
            boff0 = aoff0;
            boff1 = aoff1;
        } else {
            Bsrc0 = B + (long long)(n0 + ra) * ldb + ca;
            boff0 = ra * ASTRIDE + ca;
        }
    } else {
        if (NTILE == 128) {
            int rb = tid >> 5;
            int cb = (tid & 31) * 4;
            Bsrc0 = B + (long long)rb * ldb + n0 + cb;
            Bsrc1 = B + (long long)(rb + 8) * ldb + n0 + cb;
            boff0 = rb * BSTR + cb;
            boff1 = (rb + 8) * BSTR + cb;
        } else {
            int rb = tid >> 4;
            int cb = (tid & 15) * 4;
            Bsrc0 = B + (long long)rb * ldb + n0 + cb;
            boff0 = rb * BSTR + cb;
        }
    }
    constexpr bool BTWO = (NTILE == 128);

    const int kIters = K >> 4;

    {
        cpa16(&As[aoff0], Asrc0);
        cpa16(&As[aoff1], Asrc1);
        cpa16(&Bs[boff0], Bsrc0);
        if (BTWO) cpa16(&Bs[boff1], Bsrc1);
        cpa_commit();
        if (kIters > 1) {
            cpa16(&As[ASZ + aoff0], Asrc0 + 16);
            cpa16(&As[ASZ + aoff1], Asrc1 + 16);
            if (TRANSB) {
                cpa16(&Bs[BSZ + boff0], Bsrc0 + 16);
                if (BTWO) cpa16(&Bs[BSZ + boff1], Bsrc1 + 16);
            } else {
                cpa16(&Bs[BSZ + boff0], Bsrc0 + (long long)16 * ldb);
                if (BTWO) cpa16(&Bs[BSZ + boff1], Bsrc1 + (long long)16 * ldb);
            }
            cpa_commit();
        }
    }

    float acc[2][NT][4];
    #pragma unroll
    for (int mt = 0; mt < 2; mt++)
        #pragma unroll
        for (int nt = 0; nt < NT; nt++)
            #pragma unroll
            for (int r = 0; r < 4; r++) acc[mt][nt][r] = 0.f;

    int bufm = 0;
    for (int it = 0; it < kIters; it++) {
        if (it + 1 < kIters) cpa_wait<1>(); else cpa_wait<0>();
        __syncthreads();

        if (it + 2 < kIters) {
            int pb = bufm + 2; if (pb >= 3) pb -= 3;
            int kf = (it + 2) << 4;
            cpa16(&As[pb * ASZ + aoff0], Asrc0 + kf);
            cpa16(&As[pb * ASZ + aoff1], Asrc1 + kf);
            if (TRANSB) {
                cpa16(&Bs[pb * BSZ + boff0], Bsrc0 + kf);
                if (BTWO) cpa16(&Bs[pb * BSZ + boff1], Bsrc1 + kf);
            } else {
                cpa16(&Bs[pb * BSZ + boff0], Bsrc0 + (long long)kf * ldb);
                if (BTWO) cpa16(&Bs[pb * BSZ + boff1], Bsrc1 + (long long)kf * ldb);
            }
            cpa_commit();
        }

        const float* Ac = As + bufm * ASZ;
        const float* Bc = Bs + bufm * BSZ;
        #pragma unroll
        for (int ks = 0; ks < 16; ks += 8) {
            uint32_t af[2][4], bf[NT][2];
            #pragma unroll
            for (int mt = 0; mt < 2; mt++) {
                int mA = wm + mt * 16 + grp;
                af[mt][0] = __float_as_uint(Ac[mA * ASTRIDE + ks + tig]);
                af[mt][1] = __float_as_uint(Ac[(mA + 8) * ASTRIDE + ks + tig]);
                af[mt][2] = __float_as_uint(Ac[mA * ASTRIDE + ks + tig + 4]);
                af[mt][3] = __float_as_uint(Ac[(mA + 8) * ASTRIDE + ks + tig + 4]);
            }
            #pragma unroll
            for (int nt = 0; nt < NT; nt++) {
                int nB = wn + nt * 8 + grp;
                if (TRANSB) {
                    bf[nt][0] = __float_as_uint(Bc[nB * ASTRIDE + ks + tig]);
                    bf[nt][1] = __float_as_uint(Bc[nB * ASTRIDE + ks + tig + 4]);
                } else {
                    bf[nt][0] = __float_as_uint(Bc[(ks + tig) * BSTR + nB]);
                    bf[nt][1] = __float_as_uint(Bc[(ks + tig + 4) * BSTR + nB]);
                }
            }
            #pragma unroll
            for (int mt = 0; mt < 2; mt++)
                #pragma unroll
                for (int nt = 0; nt < NT; nt++)
                    mma_tf32(acc[mt][nt], af[mt], bf[nt][0], bf[nt][1]);
        }
        bufm++; if (bufm >= 3) bufm = 0;
    }

    #pragma unroll
    for (int mt = 0; mt < 2; mt++) {
        #pragma unroll
        for (int half = 0; half < 2; half++) {
            int m = m0 + wm + mt * 16 + grp + half * 8;
            #pragma unroll
            for (int nt = 0; nt < NT; nt++) {
                int n = n0 + wn + nt * 8 + 2 * tig;
                float2 r;
                r.x = acc[mt][nt][half * 2 + 0] * alpha;
                r.y = acc[mt][nt][half * 2 + 1] * alpha;
                if (bias) {
                    r.x += bias[n];
                    r.y += bias[n + 1];
                }
                if (Res) {
                    const float2 rr = *(const float2*)(Res + (long long)m * ldc + n);
                    r.x += rr.x; r.y += rr.y;
                }
                if (RELU) {
                    r.x = fmaxf(r.x, 0.f);
                    r.y = fmaxf(r.y, 0.f);
                }
                if (TF32OUT) {
                    r.x = rna_tf32(r.x);
                    r.y = rna_tf32(r.y);
                }
                *(float2*)(C + (long long)m * ldc + n) = r;
            }
        }
    }
}

// ================= fused flash attention (tf32 MMA, online softmax) ========
#define QSTR 132
#define KSTR 132
#define VSTR 136
#define PSTR 36
static const int FLASH_SMEM = (128*QSTR + 2*32*KSTR + 2*32*VSTR + 128*PSTR) * 4;

__global__ void __launch_bounds__(256, 1)
flash_attn_kernel(const float* __restrict__ qkv, float* __restrict__ ao)
{
    extern __shared__ __align__(16) float sm[];
    float* Qs = sm;
    float* Ks = Qs + 128 * QSTR;
    float* Vs = Ks + 2 * 32 * KSTR;
    float* Ps = Vs + 2 * 32 * VSTR;

    int qt = blockIdx.x;
    int bh = blockIdx.y;
    int b = bh / NHE, h = bh - b * NHE;
    const float* qbase = qkv + (long long)b * NN * HD4 + (long long)qt * 128 * HD4 + HD + h * DHE;
    const float* kbase = qkv + (long long)b * NN * HD4 + 2 * HD + h * DHE;
    const float* vbase = qkv + (long long)b * NN * HD4 + 3 * HD + h * DHE;

    int tid = threadIdx.x;
    int lane = tid & 31, wid = tid >> 5;
    int tig = lane & 3, grp = lane >> 2;
    int wq = wid * 16;

    #pragma unroll
    for (int c = 0; c < 16; c++) {
        int chunk = tid + c * 256;
        int row = chunk >> 5, col = (chunk & 31) * 4;
        cpa16(&Qs[row * QSTR + col], qbase + (long long)row * HD4 + col);
    }
    #pragma unroll
    for (int c = 0; c < 4; c++) {
        int chunk = tid + c * 256;
        int row = chunk >> 5, col = (chunk & 31) * 4;
        cpa16(&Ks[row * KSTR + col], kbase + (long long)row * HD4 + col);
        cpa16(&Vs[row * VSTR + col], vbase + (long long)row * HD4 + col);
    }
    cpa_commit();

    float Oacc[16][4];
    #pragma unroll
    for (int nt = 0; nt < 16; nt++)
        #pragma unroll
        for (int j = 0; j < 4; j++) Oacc[nt][j] = 0.f;
    float m0r = -1e30f, m1r = -1e30f;
    float l0 = 0.f, l1 = 0.f;
    const float alpha = 0.08838834764831843f;

    int cur = 0;
    for (int it = 0; it < 32; it++) {
        bool more = (it + 1 < 32);
        if (more) {
            int nxt = cur ^ 1;
            const float* kb = kbase + (long long)(it + 1) * 32 * HD4;
            const float* vb = vbase + (long long)(it + 1) * 32 * HD4;
            #pragma unroll
            for (int c = 0; c < 4; c++) {
                int chunk = tid + c * 256;
                int row = chunk >> 5, col = (chunk & 31) * 4;
                cpa16(&Ks[nxt * 32 * KSTR + row * KSTR + col], kb + (long long)row * HD4 + col);
                cpa16(&Vs[nxt * 32 * VSTR + row * VSTR + col], vb + (long long)row * HD4 + col);
            }
            cpa_commit();
            cpa_wait<1>();
        } else {
            cpa_wait<0>();
        }
        __syncthreads();

        const float* Kc = Ks + cur * 32 * KSTR;
        const float* Vc = Vs + cur * 32 * VSTR;

        float s[4][4];
        #pragma unroll
        for (int nt = 0; nt < 4; nt++)
            #pragma unroll
            for (int j = 0; j < 4; j++) s[nt][j] = 0.f;
        #pragma unroll
        for (int kc = 0; kc < 16; kc++) {
            uint32_t af[4];
            af[0] = __float_as_uint(Qs[(wq + grp) * QSTR + kc * 8 + tig]);
            af[1] = __float_as_uint(Qs[(wq + grp + 8) * QSTR + kc * 8 + tig]);
            af[2] = __float_as_uint(Qs[(wq + grp) * QSTR + kc * 8 + tig + 4]);
            af[3] = __float_as_uint(Qs[(wq + grp + 8) * QSTR + kc * 8 + tig + 4]);
            #pragma unroll
            for (int nt = 0; nt < 4; nt++) {
                uint32_t b0 = __float_as_uint(Kc[(nt * 8 + grp) * KSTR + kc * 8 + tig]);
                uint32_t b1 = __float_as_uint(Kc[(nt * 8 + grp) * KSTR + kc * 8 + tig + 4]);
                mma_tf32(s[nt], af, b0, b1);
            }
        }

        float t0 = -1e30f, t1 = -1e30f;
        #pragma unroll
        for (int nt = 0; nt < 4; nt++) {
            s[nt][0] *= alpha; s[nt][1] *= alpha;
            s[nt][2] *= alpha; s[nt][3] *= alpha;
            t0 = fmaxf(t0, fmaxf(s[nt][0], s[nt][1]));
            t1 = fmaxf(t1, fmaxf(s[nt][2], s[nt][3]));
        }
        t0 = fmaxf(t0, __shfl_xor_sync(0xffffffffu, t0, 1));
        t0 = fmaxf(t0, __shfl_xor_sync(0xffffffffu, t0, 2));
        t1 = fmaxf(t1, __shfl_xor_sync(0xffffffffu, t1, 1));
        t1 = fmaxf(t1, __shfl_xor_sync(0xffffffffu, t1, 2));
        float mn0 = fmaxf(m0r, t0), mn1 = fmaxf(m1r, t1);
        float f0 = __expf(m0r - mn0), f1 = __expf(m1r - mn1);
        float ps0 = 0.f, ps1 = 0.f;
        #pragma unroll
        for (int nt = 0; nt < 4; nt++) {
            float p0 = __expf(s[nt][0] - mn0);
            float p1 = __expf(s[nt][1] - mn0);
            float p2 = __expf(s[nt][2] - mn1);
            float p3 = __expf(s[nt][3] - mn1);
            ps0 += p0 + p1;
            ps1 += p2 + p3;
            float2 lo = { rna_tf32(p0), rna_tf32(p1) };
            float2 hi = { rna_tf32(p2), rna_tf32(p3) };
            *(float2*)&Ps[(wq + grp) * PSTR + nt * 8 + 2 * tig] = lo;
            *(float2*)&Ps[(wq + grp + 8) * PSTR + nt * 8 + 2 * tig] = hi;
        }
        ps0 += __shfl_xor_sync(0xffffffffu, ps0, 1);
        ps0 += __shfl_xor_sync(0xffffffffu, ps0, 2);
        ps1 += __shfl_xor_sync(0xffffffffu, ps1, 1);
        ps1 += __shfl_xor_sync(0xffffffffu, ps1, 2);
        l0 = l0 * f0 + ps0;
        l1 = l1 * f1 + ps1;
        m0r = mn0; m1r = mn1;
        #pragma unroll
        for (int nt = 0; nt < 16; nt++) {
            Oacc[nt][0] *= f0; Oacc[nt][1] *= f0;
            Oacc[nt][2] *= f1; Oacc[nt][3] *= f1;
        }
        __syncwarp();

        #pragma unroll
        for (int kc = 0; kc < 4; kc++) {
            uint32_t af[4];
            af[0] = __float_as_uint(Ps[(wq + grp) * PSTR + kc * 8 + tig]);
            af[1] = __float_as_uint(Ps[(wq + grp + 8) * PSTR + kc * 8 + tig]);
            af[2] = __float_as_uint(Ps[(wq + grp) * PSTR + kc * 8 + tig + 4]);
            af[3] = __float_as_uint(Ps[(wq + grp + 8) * PSTR + kc * 8 + tig + 4]);
            #pragma unroll
            for (int nt = 0; nt < 16; nt++) {
                uint32_t b0 = __float_as_uint(Vc[(kc * 8 + tig) * VSTR + nt * 8 + grp]);
                uint32_t b1 = __float_as_uint(Vc[(kc * 8 + tig + 4) * VSTR + nt * 8 + grp]);
                mma_tf32(Oacc[nt], af, b0, b1);
            }
        }
        if (!more) break;
        __syncthreads();
        cur ^= 1;
    }

    float inv0 = 1.f / l0, inv1 = 1.f / l1;
    int r0 = qt * 128 + wq + grp;
    float* o0 = ao + (long long)b * NN * HD + (long long)r0 * HD + h * DHE;
    float* o1 = o0 + 8 * HD;
    #pragma unroll
    for (int nt = 0; nt < 16; nt++) {
        int col = nt * 8 + 2 * tig;
        float2 va = { rna_tf32(Oacc[nt][0] * inv0), rna_tf32(Oacc[nt][1] * inv0) };
        float2 vb = { rna_tf32(Oacc[nt][2] * inv1), rna_tf32(Oacc[nt][3] * inv1) };
        *(float2*)(o0 + col) = va;
        *(float2*)(o1 + col) = vb;
    }
}

// ---------------- small kernels ----------------
__global__ void feats_kernel(const float* __restrict__ x, float* __restrict__ feats)
{
    long long i = (long long)blockIdx.x * blockDim.x + threadIdx.x;
    if (i >= (long long)NB * NN * CIN) return;
    int c = (int)(i & (CIN - 1));
    long long bn = i >> 6;
    int n = (int)(bn & (NN - 1));
    int b = (int)(bn >> 10);
    feats[i] = x[((long long)b * CIN + c) * NN + n];
}

__global__ void prep_kernel(const float* __restrict__ gcn_W, const float* __restrict__ Wq,
                            const float* __restrict__ Wk, const float* __restrict__ Wv,
                            const float* __restrict__ gcn_b, const float* __restrict__ bq,
                            const float* __restrict__ bk, const float* __restrict__ bv,
                            const float* __restrict__ Wo, const float* __restrict__ W1,
                            const float* __restrict__ W2,
                            float* __restrict__ wpack, float* __restrict__ bpack,
                            float* __restrict__ wr)
{
    int i = blockIdx.x * blockDim.x + threadIdx.x;
    const int NWP = 3 * 384 * 1536;
    const int NBP = 3 * 1536;
    const int NWO = 442368;
    const int NW1 = 884736;
    if (i < NWP) {
        int l = i / (384 * 1536);
        int rem = i - l * (384 * 1536);
        int r = rem / 1536;
        int c = rem - r * 1536;
        int sel = c / 384, cc = c - sel * 384;
        const float* src = (sel == 0) ? gcn_W : (sel == 1) ? Wq : (sel == 2) ? Wk : Wv;
        wpack[i] = rna_tf32(src[((long long)l * 384 + r) * 384 + cc]);
        return;
    }
    int j = i - NWP;
    if (j < NBP) {
        int l = j / 1536;
        int c = j - l * 1536;
        int sel = c / 384, cc = c - sel * 384;
        const float* src = (sel == 0) ? gcn_b : (sel == 1) ? bq : (sel == 2) ? bk : bv;
        bpack[j] = src[l * 384 + cc];
        return;
    }
    j -= NBP;
    if (j < NWO) { wr[WR_WO + j] = rna_tf32(Wo[j]); return; }
    j -= NWO;
    if (j < NW1) { wr[WR_W1 + j] = rna_tf32(W1[j]); return; }
    j -= NW1;
    if (j < NW1) { wr[WR_W2 + j] = rna_tf32(W2[j]); return; }
}

__device__ __forceinline__ void block_reduce2(float& s1, float& s2)
{
    __shared__ float b1[4], b2[4];
    #pragma unroll
    for (int o = 16; o > 0; o >>= 1) {
        s1 += __shfl_down_sync(0xffffffffu, s1, o);
        s2 += __shfl_down_sync(0xffffffffu, s2, o);
    }
    int w = threadIdx.x >> 5;
    if ((threadIdx.x & 31) == 0) { b1[w] = s1; b2[w] = s2; }
    __syncthreads();
    s1 = b1[0] + b1[1] + b1[2] + b1[3];
    s2 = b2[0] + b2[1] + b2[2] + b2[3];
}

__global__ void norm_kernel(const float* __restrict__ h0, float* __restrict__ nh,
                            float* __restrict__ h0r)
{
    long long bn = blockIdx.x;
    int t = threadIdx.x; // 128
    const float* r = h0 + bn * HD;
    float v0 = r[t], v1 = r[t + 128], v2 = r[t + 256];
    float ss = v0 * v0 + v1 * v1 + v2 * v2, dummy = 0.f;
    block_reduce2(ss, dummy);
    float rinv = rsqrtf(ss);
    float* o = nh + bn * HD;
    o[t] = v0 * rinv; o[t + 128] = v1 * rinv; o[t + 256] = v2 * rinv;
    float* o2 = h0r + bn * HD;
    o2[t] = rna_tf32(v0); o2[t + 128] = rna_tf32(v1); o2[t + 256] = rna_tf32(v2);
}

__global__ void topk_warp_kernel(const float* __restrict__ sim, int* __restrict__ knn)
{
    int warp = blockIdx.x * (blockDim.x >> 5) + (threadIdx.x >> 5);
    if (warp >= NB * NN) return;
    int lane = threadIdx.x & 31;
    int n = warp & (NN - 1);
    const float* row = sim + (long long)warp * NN;
    float v[32];
    #pragma unroll
    for (int j = 0; j < 32; j++) {
        int m = j * 32 + lane;
        v[j] = (m == n) ? -3e38f : row[m];
    }
    unsigned taken = 0;
    int* o = knn + (long long)warp * KNN;
    for (int r = 0; r < KNN; r++) {
        float bv = -3e38f; int bj = 0;
        #pragma unroll
        for (int j = 0; j < 32; j++) {
            bool free_ = !((taken >> j) & 1u);
            if (free_ && v[j] > bv) { bv = v[j]; bj = j; }
        }
        int bidx = bj * 32 + lane;
        #pragma unroll
        for (int off = 16; off > 0; off >>= 1) {
            float ov = __shfl_xor_sync(0xffffffffu, bv, off);
            int   oi = __shfl_xor_sync(0xffffffffu, bidx, off);
            if (ov > bv || (ov == bv && oi < bidx)) { bv = ov; bidx = oi; }
        }
        if ((bidx & 31) == lane) taken |= 1u << (bidx >> 5);
        if (lane == 0) o[r] = bidx;
    }
}

__global__ void gcn_agg_ln(const float* __restrict__ hcur, const float* __restrict__ xw,
                           int ldx,
                           const int* __restrict__ knn,
                           const float* __restrict__ scale, const float* __restrict__ bias,
                           float* __restrict__ out)
{
    int bn = blockIdx.x;
    int b = bn >> 10;
    int t = threadIdx.x; // 128
    __shared__ int sidx[KNN];
    if (t < KNN) sidx[t] = knn[(long long)bn * KNN + t];
    __syncthreads();
    const float* xr = xw + (long long)bn * ldx;
    float a0 = xr[t], a1 = xr[t + 128], a2 = xr[t + 256];
    #pragma unroll 4
    for (int j = 0; j < KNN; j++) {
        const float* r = xw + ((long long)(b * NN) + sidx[j]) * ldx;
        a0 += r[t]; a1 += r[t + 128]; a2 += r[t + 256];
    }
    const float* h = hcur + (long long)bn * HD;
    const float inv17 = 1.f / 17.f;
    float v0 = h[t] + a0 * inv17;
    float v1 = h[t + 128] + a1 * inv17;
    float v2 = h[t + 256] + a2 * inv17;
    float s1 = v0 + v1 + v2;
    float s2 = v0 * v0 + v1 * v1 + v2 * v2;
    block_reduce2(s1, s2);
    float mu = s1 * (1.f / HD);
    float var = s2 * (1.f / HD) - mu * mu;
    float rstd = rsqrtf(var + 1e-5f);
    float* o = out + (long long)bn * HD;
    o[t]       = (v0 - mu) * rstd * scale[t]       + bias[t];
    o[t + 128] = (v1 - mu) * rstd * scale[t + 128] + bias[t + 128];
    o[t + 256] = (v2 - mu) * rstd * scale[t + 256] + bias[t + 256];
}

__global__ void add_ln_kernel(const float* __restrict__ a, const float* __restrict__ b,
                              const float* __restrict__ plus,
                              const float* __restrict__ scale, const float* __restrict__ bias,
                              float* __restrict__ out, int rnd)
{
    long long bn = blockIdx.x;
    int t = threadIdx.x; // 128
    const float* ar = a + bn * HD;
    float v0 = ar[t], v1 = ar[t + 128], v2 = ar[t + 256];
    if (b) {
        const float* br = b + bn * HD;
        v0 += br[t]; v1 += br[t + 128]; v2 += br[t + 256];
    }
    float s1 = v0 + v1 + v2;
    float s2 = v0 * v0 + v1 * v1 + v2 * v2;
    block_reduce2(s1, s2);
    float mu = s1 * (1.f / HD);
    float var = s2 * (1.f / HD) - mu * mu;
    float rstd = rsqrtf(var + 1e-5f);
    float y0 = (v0 - mu) * rstd * scale[t]       + bias[t];
    float y1 = (v1 - mu) * rstd * scale[t + 128] + bias[t + 128];
    float y2 = (v2 - mu) * rstd * scale[t + 256] + bias[t + 256];
    if (plus) {
        const float* pr = plus + bn * HD;
        y0 += pr[t]; y1 += pr[t + 128]; y2 += pr[t + 256];
    }
    if (rnd) { y0 = rna_tf32(y0); y1 = rna_tf32(y1); y2 = rna_tf32(y2); }
    float* o = out + bn * HD;
    o[t] = y0; o[t + 128] = y1; o[t + 256] = y2;
}

__global__ void pool_kernel(const float* __restrict__ h, float* __restrict__ pooled)
{
    int b = blockIdx.x;
    int t = threadIdx.x; // 384
    float s = 0.f;
    const float* base = h + (long long)b * NN * HD + t;
    for (int n = 0; n < NN; n++) s += base[(long long)n * HD];
    pooled[b * HD + t] = s * (1.f / NN);
}

__global__ void fin1_kernel(const float* __restrict__ pooled, const float* __restrict__ W,
                            const float* __restrict__ bias, float* __restrict__ z)
{
    int b = blockIdx.x;
    int j = threadIdx.x; // 384
    const float* p = pooled + b * HD;
    float s = bias[j];
    for (int k = 0; k < HD; k++) s = fmaf(p[k], W[k * HD + j], s);
    z[b * HD + j] = fmaxf(s, 0.f);
}

__global__ void fin2_kernel(const float* __restrict__ z, const float* __restrict__ W,
                            const float* __restrict__ bias, float* __restrict__ out)
{
    int b = blockIdx.x;
    int j = threadIdx.x; // 128
    const float* p = z + b * HD;
    float s = bias[j];
    for (int k = 0; k < HD; k++) s = fmaf(p[k], W[k * 128 + j], s);
    out[b * 128 + j] = s;
}

// ---------------- host-side GEMM dispatchers ----------------
static void gemm_f32(const float* A, const float* B, const float* bias, const float* Res, float* C,
                     int M, int Nn, int K, int lda, int ldb, int ldc,
                     long long sA, long long sAi, long long sB, long long sBi,
                     long long sC, long long sCi, int zi, int nz,
                     float alpha, bool transb, bool relu, cudaStream_t st = 0)
{
    dim3 grid(Nn / BN, M / BM, nz), block(256);
    if (transb) {
        if (relu) gemm_k<true, true ><<<grid, block, 0, st>>>(A, B, bias, Res, C, M, Nn, K, lda, ldb, ldc, sA, sAi, sB, sBi, sC, sCi, zi, alpha);
        else      gemm_k<true, false><<<grid, block, 0, st>>>(A, B, bias, Res, C, M, Nn, K, lda, ldb, ldc, sA, sAi, sB, sBi, sC, sCi, zi, alpha);
    } else {
        if (relu) gemm_k<false, true ><<<grid, block, 0, st>>>(A, B, bias, Res, C, M, Nn, K, lda, ldb, ldc, sA, sAi, sB, sBi, sC, sCi, zi, alpha);
        else      gemm_k<false, false><<<grid, block, 0, st>>>(A, B, bias, Res, C, M, Nn, K, lda, ldb, ldc, sA, sAi, sB, sBi, sC, sCi, zi, alpha);
    }
}

static void gemm_tf(const float* A, const float* B, const float* bias, const float* Res, float* C,
                    int M, int Nn, int K, int lda, int ldb, int ldc,
                    long long sA, long long sAi, long long sB, long long sBi,
                    long long sC, long long sCi, int zi, int nz,
                    float alpha, bool transb, bool relu, bool tf32out, int ntile,
                    cudaStream_t st = 0)
{
    dim3 grid(Nn / ntile, M / 128, nz), block(256);
    #define DISP(TB, RL, TO, NTL) do { \
        constexpr int BSZc = TB ? (NTL * ASTRIDE) : (16 * ((NTL == 128) ? BN128STR : BN64STR)); \
        int smemb = (3 * 128 * ASTRIDE + 3 * BSZc) * 4; \
        cudaFuncSetAttribute(tf32gemm_k<TB, RL, TO, NTL>, cudaFuncAttributeMaxDynamicSharedMemorySize, smemb); \
        tf32gemm_k<TB, RL, TO, NTL><<<grid, block, smemb, st>>>(A, B, bias, Res, C, K, lda, ldb, ldc, sA, sAi, sB, sBi, sC, sCi, zi, alpha); \
    } while (0)
    if (ntile == 128) {
        if (transb) {
            if (relu)  { if (tf32out) DISP(true, true, true, 128);  else DISP(true, true, false, 128); }
            else       { if (tf32out) DISP(true, false, true, 128); else DISP(true, false, false, 128); }
        } else {
            if (relu)  { if (tf32out) DISP(false, true, true, 128);  else DISP(false, true, false, 128); }
            else       { if (tf32out) DISP(false, false, true, 128); else DISP(false, false, false, 128); }
        }
    } else {
        if (transb) {
            if (relu)  { if (tf32out) DISP(true, true, true, 64);  else DISP(true, true, false, 64); }
            else       { if (tf32out) DISP(true, false, true, 64); else DISP(true, false, false, 64); }
        } else {
            if (relu)  { if (tf32out) DISP(false, true, true, 64);  else DISP(false, true, false, 64); }
            else       { if (tf32out) DISP(false, false, true, 64); else DISP(false, false, false, 64); }
        }
    }
    #undef DISP
}

template<typename T> static T* sym_addr(const void* sym)
{
    void* p = nullptr;
    cudaGetSymbolAddress(&p, sym);
    return (T*)p;
}

extern "C" void kernel_launch(void* const* d_in, const int* in_sizes, int n_in,
                              void* d_out, int out_size)
{
    const float* x      = (const float*)d_in[0];
    const float* W_enc  = (const float*)d_in[1];
    const float* b_enc  = (const float*)d_in[2];
    const float* gcn_W  = (const float*)d_in[3];
    const float* gcn_b  = (const float*)d_in[4];
    const float* Wq     = (const float*)d_in[5];
    const float* bq     = (const float*)d_in[6];
    const float* Wk     = (const float*)d_in[7];
    const float* bk     = (const float*)d_in[8];
    const float* Wv     = (const float*)d_in[9];
    const float* bv     = (const float*)d_in[10];
    const float* Wo     = (const float*)d_in[11];
    const float* bo     = (const float*)d_in[12];
    const float* lnsc   = (const float*)d_in[13];
    const float* lnbi   = (const float*)d_in[14];
    const float* W1     = (const float*)d_in[15];
    const float* b1     = (const float*)d_in[16];
    const float* W2     = (const float*)d_in[17];
    const float* b2     = (const float*)d_in[18];
    const float* lin1_W = (const float*)d_in[19];
    const float* lin1_b = (const float*)d_in[20];
    const float* lin2_W = (const float*)d_in[21];
    const float* lin2_b = (const float*)d_in[22];
    float* outp = (float*)d_out;

    float* featsp = sym_addr<float>(g_feats);
    float* h0p    = sym_addr<float>(g_h0);
    float* h0rp   = sym_addr<float>(g_h0r);
    float* nhp    = sym_addr<float>(g_nh);
    float* simp   = sym_addr<float>(g_sim);
    int*   knnp   = sym_addr<int>(g_knn);
    float* hcurp  = sym_addr<float>(g_hcur);
    float* qkvgp  = sym_addr<float>(g_qkvg);
    float* hlocp  = sym_addr<float>(g_hloc);
    float* aop    = sym_addr<float>(g_ao);
    float* op     = sym_addr<float>(g_o);
    float* combp  = sym_addr<float>(g_comb);
    float* mlp1p  = sym_addr<float>(g_mlp1);
    float* ffp    = sym_addr<float>(g_ff);
    float* poolp  = sym_addr<float>(g_pool);
    float* zp     = sym_addr<float>(g_z);
    float* wpackp = sym_addr<float>(g_wpack);
    float* bpackp = sym_addr<float>(g_bpack);
    float* wrp    = sym_addr<float>(g_wr);

    cudaFuncSetAttribute(flash_attn_kernel, cudaFuncAttributeMaxDynamicSharedMemorySize, FLASH_SMEM);

    const long long NH  = (long long)NN * HD;
    const long long NH4 = (long long)NN * HD4;
    const int WSQ = HD * HD;

    // side stream + events (fork-join pattern; capture-legal)
    cudaStream_t sB;
    cudaStreamCreateWithFlags(&sB, cudaStreamNonBlocking);
    cudaEvent_t evStart, evNorm, evProj, evWo[NL], evFork2[NL];
    cudaEventCreateWithFlags(&evStart, cudaEventDisableTiming);
    cudaEventCreateWithFlags(&evNorm, cudaEventDisableTiming);
    cudaEventCreateWithFlags(&evProj, cudaEventDisableTiming);
    for (int l = 0; l < NL; l++) {
        cudaEventCreateWithFlags(&evWo[l], cudaEventDisableTiming);
        cudaEventCreateWithFlags(&evFork2[l], cudaEventDisableTiming);
    }

    // sB: weight prep runs concurrently with feats/encoder/norm on main
    cudaEventRecord(evStart, 0);
    cudaStreamWaitEvent(sB, evStart, 0);
    {
        int total = 3 * 384 * 1536 + 3 * 1536 + 442368 + 884736 + 884736;
        prep_kernel<<<(total + 255) / 256, 256, 0, sB>>>(gcn_W, Wq, Wk, Wv, gcn_b, bq, bk, bv,
                                                         Wo, W1, W2, wpackp, bpackp, wrp);
    }

    // main: feats -> encoder -> norm
    feats_kernel<<<(NB * NN * CIN + 255) / 256, 256>>>(x, featsp);
    gemm_f32(featsp, W_enc, b_enc, nullptr, h0p,
             NN, HD, CIN, CIN, HD, HD,
             (long long)NN * CIN, 0, 0, 0, NH, 0, 1, NB, 1.f, false, false);
    norm_kernel<<<NB * NN, 128>>>(h0p, nhp, h0rp);
    cudaEventRecord(evNorm, 0);

    // sB: layer-0 tensor chain (proj0 -> flash0 -> Wo0), needs norm + prep
    cudaStreamWaitEvent(sB, evNorm, 0);
    gemm_tf(h0rp, wpackp, bpackp, nullptr, qkvgp,
            NN, HD4, HD, HD, HD4, HD4, NH, 0, 0, 0, NH4, 0, 1, NB,
            1.f, false, false, true, 128, sB);
    cudaEventRecord(evProj, sB);
    flash_attn_kernel<<<dim3(NN / 128, NB * NHE), 256, FLASH_SMEM, sB>>>(qkvgp, aop);
    gemm_tf(aop, wrp + WR_WO, bo, nullptr, op,
            NN, HD, HD, HD, HD, HD, NH, 0, 0, 0, NH, 0, 1, NB,
            1.f, false, false, false, 64, sB);
    cudaEventRecord(evWo[0], sB);

    // main: symmetric sim + topk (fma-pipe work) concurrent with sB
    sim_gemm_k<<<dim3(36, 1, NB), 256>>>(nhp, simp);
    topk_warp_kernel<<<NB * NN / 8, 256>>>(simp, knnp);

    const float* hin = h0rp;
    for (int l = 0; l < NL; l++) {
        const float* scl = lnsc + (l * 3) * HD;
        const float* bil = lnbi + (l * 3) * HD;

        if (l > 0) {
            gemm_tf(hin, wpackp + (long long)l * HD * HD4, bpackp + l * HD4, nullptr, qkvgp,
                    NN, HD4, HD, HD, HD4, HD4, NH, 0, 0, 0, NH4, 0, 1, NB,
                    1.f, false, false, true, 128);
            cudaEventRecord(evFork2[l], 0);
            cudaStreamWaitEvent(sB, evFork2[l], 0);
            flash_attn_kernel<<<dim3(NN / 128, NB * NHE), 256, FLASH_SMEM, sB>>>(qkvgp, aop);
            gemm_tf(aop, wrp + WR_WO + (long long)l * WSQ, bo + l * HD, nullptr, op,
                    NN, HD, HD, HD, HD, HD, NH, 0, 0, 0, NH, 0, 1, NB,
                    1.f, false, false, false, 64, sB);
            cudaEventRecord(evWo[l], sB);
        } else {
            cudaStreamWaitEvent(0, evProj, 0);
        }

        // gcn branch on main stream (overlaps flash/Wo on sB)
        gcn_agg_ln<<<NB * NN, 128>>>(hin, qkvgp, HD4, knnp, scl, bil, hlocp);

        // join: add_ln needs Wo output
        cudaStreamWaitEvent(0, evWo[l], 0);
        add_ln_kernel<<<NB * NN, 128>>>(hin, op, hlocp, scl + HD, bil + HD, combp, 1);

        // FFN
        gemm_tf(combp, wrp + WR_W1 + (long long)l * HD * 2 * HD, b1 + l * 2 * HD, nullptr, mlp1p,
                NN, 2 * HD, HD, HD, 2 * HD, 2 * HD,
                NH, 0, 0, 0, (long long)NN * 2 * HD, 0, 1, NB, 1.f, false, true, true, 128);
        gemm_tf(mlp1p, wrp + WR_W2 + (long long)l * 2 * HD * HD, b2 + l * HD, combp, ffp,
                NN, HD, 2 * HD, 2 * HD, HD, HD,
                (long long)NN * 2 * HD, 0, 0, 0, NH, 0, 1, NB, 1.f, false, false, false, 64);
        add_ln_kernel<<<NB * NN, 128>>>(ffp, nullptr, nullptr, scl + 2 * HD, bil + 2 * HD, hcurp, 1);
        hin = hcurp;
    }

    // ---- head ----
    pool_kernel<<<NB, HD>>>(hin, poolp);
    fin1_kernel<<<NB, HD>>>(poolp, lin1_W, lin1_b, zp);
    fin2_kernel<<<NB, 128>>>(zp, lin2_W, lin2_b, outp);

    cudaEventDestroy(evStart);
    cudaEventDestroy(evNorm);
    cudaEventDestroy(evProj);
    for (int l = 0; l < NL; l++) {
        cudaEventDestroy(evWo[l]);
        cudaEventDestroy(evFork2[l]);
    }
    cudaStreamDestroy(sB);
}

// round 10
// speedup vs baseline: 3.6459x; 1.1194x over previous
#include <cuda_runtime.h>
#include <math.h>
#include <stdint.h>

// ---------------- problem constants ----------------
static const int NB   = 8;     // batch
static const int NN   = 1024;  // nodes (32*32)
static const int CIN  = 64;    // input channels
static const int HD   = 384;   // hidden
static const int NL   = 3;     // layers
static const int KNN  = 16;    // k
static const int NHE  = 3;     // heads
static const int DHE  = 128;   // head dim
static const int HD4  = 4 * HD; // 1536 packed width
static const int HB   = 4;     // batches per half-pipeline

// ---------------- device scratch (no allocs allowed) ----------------
__device__ float g_feats [NB*NN*CIN];
__device__ float g_h0    [NB*NN*HD];
__device__ float g_h0r   [NB*NN*HD];
__device__ float g_nh    [NB*NN*HD];
__device__ float g_sim   [NB*NN*NN];
__device__ int   g_knn   [NB*NN*KNN];
__device__ float g_hcur  [NB*NN*HD];
__device__ float g_qkvg  [NB*NN*4*HD];   // packed [gcn | q | k | v]
__device__ float g_hloc  [NB*NN*HD];
__device__ float g_ao    [NB*NN*HD];
__device__ float g_o     [NB*NN*HD];
__device__ float g_comb  [NB*NN*HD];
__device__ float g_mlp1  [NB*NN*2*HD];
__device__ float g_ff    [NB*NN*HD];
__device__ float g_pool  [NB*HD];
__device__ float g_z     [NB*HD];
// packed fused projection weights [L][384][1536] + biases [L][1536]
__device__ float g_wpack [3*384*1536];
__device__ float g_bpack [3*1536];
// rounded weights: WO, W1, W2
__device__ float g_wr    [2211840];
static const long long WR_WO  = 0;
static const long long WR_W1  = 442368;
static const long long WR_W2  = 1327104;

__device__ __forceinline__ float rna_tf32(float x)
{
    uint32_t r;
    asm("cvt.rna.tf32.f32 %0, %1;" : "=r"(r) : "f"(x));
    return __uint_as_float(r);
}

// ================= fp32 SIMT GEMM (exact path: encoder) ====================
#define BM 128
#define BN 128
#define BKK 8
#define SPAD 132

template<bool TRANSB, bool RELU>
__global__ void __launch_bounds__(256, 2)
gemm_k(const float* __restrict__ A, const float* __restrict__ B,
       const float* __restrict__ bias, const float* __restrict__ Res,
       float* __restrict__ C,
       int M, int Nn, int K, int lda, int ldb, int ldc,
       long long sA, long long sAi, long long sB, long long sBi,
       long long sC, long long sCi, int zi, float alpha)
{
    int bz = blockIdx.z;
    int zo = bz / zi, zin = bz % zi;
    A += zo * sA + zin * sAi;
    B += zo * sB + zin * sBi;
    C += zo * sC + zin * sCi;
    if (Res) Res += zo * sC + zin * sCi;

    int m0 = blockIdx.y * BM;
    int n0 = blockIdx.x * BN;

    __shared__ float As[2][BKK][SPAD];
    __shared__ float Bs[2][BKK][SPAD];

    int tid = threadIdx.x;
    int tx = tid & 15;
    int ty = tid >> 4;

    int a_m = tid >> 1;
    int a_k = (tid & 1) * 4;
    const float* Aload = A + (long long)(m0 + a_m) * lda + a_k;

    const float* Bload;
    int b_k = 0, b_n = 0;
    if (TRANSB) {
        Bload = B + (long long)(n0 + a_m) * ldb + a_k;
    } else {
        b_k = tid >> 5;
        b_n = (tid & 31) * 4;
        Bload = B + (long long)b_k * ldb + n0 + b_n;
    }

    float4 av = *(const float4*)Aload;
    float4 bv = *(const float4*)Bload;

    As[0][a_k + 0][a_m] = av.x;
    As[0][a_k + 1][a_m] = av.y;
    As[0][a_k + 2][a_m] = av.z;
    As[0][a_k + 3][a_m] = av.w;
    if (TRANSB) {
        Bs[0][a_k + 0][a_m] = bv.x;
        Bs[0][a_k + 1][a_m] = bv.y;
        Bs[0][a_k + 2][a_m] = bv.z;
        Bs[0][a_k + 3][a_m] = bv.w;
    } else {
        *(float4*)&Bs[0][b_k][b_n] = bv;
    }
    __syncthreads();

    float acc[8][8];
    #pragma unroll
    for (int i = 0; i < 8; i++)
        #pragma unroll
        for (int j = 0; j < 8; j++) acc[i][j] = 0.f;

    int cur = 0;
    for (int k0 = 0; ; ) {
        int k1 = k0 + BKK;
        bool more = (k1 < K);
        if (more) {
            av = *(const float4*)(Aload + k1);
            if (TRANSB) bv = *(const float4*)(Bload + k1);
            else        bv = *(const float4*)(Bload + (long long)k1 * ldb);
        }

        #pragma unroll
        for (int kk = 0; kk < BKK; kk++) {
            float4 a0 = *(const float4*)&As[cur][kk][ty * 4];
            float4 a1 = *(const float4*)&As[cur][kk][64 + ty * 4];
            float4 b0 = *(const float4*)&Bs[cur][kk][tx * 4];
            float4 b1 = *(const float4*)&Bs[cur][kk][64 + tx * 4];
            float a[8] = {a0.x, a0.y, a0.z, a0.w, a1.x, a1.y, a1.z, a1.w};
            float b[8] = {b0.x, b0.y, b0.z, b0.w, b1.x, b1.y, b1.z, b1.w};
            #pragma unroll
            for (int i = 0; i < 8; i++)
                #pragma unroll
                for (int j = 0; j < 8; j++)
                    acc[i][j] = fmaf(a[i], b[j], acc[i][j]);
        }
        if (!more) break;

        int nxt = cur ^ 1;
        As[nxt][a_k + 0][a_m] = av.x;
        As[nxt][a_k + 1][a_m] = av.y;
        As[nxt][a_k + 2][a_m] = av.z;
        As[nxt][a_k + 3][a_m] = av.w;
        if (TRANSB) {
            Bs[nxt][a_k + 0][a_m] = bv.x;
            Bs[nxt][a_k + 1][a_m] = bv.y;
            Bs[nxt][a_k + 2][a_m] = bv.z;
            Bs[nxt][a_k + 3][a_m] = bv.w;
        } else {
            *(float4*)&Bs[nxt][b_k][b_n] = bv;
        }
        __syncthreads();
        cur = nxt;
        k0 = k1;
    }

    #pragma unroll
    for (int ih = 0; ih < 2; ih++) {
        #pragma unroll
        for (int i = 0; i < 4; i++) {
            int m = m0 + ih * 64 + ty * 4 + i;
            #pragma unroll
            for (int jh = 0; jh < 2; jh++) {
                int n = n0 + jh * 64 + tx * 4;
                float4 r;
                r.x = acc[ih * 4 + i][jh * 4 + 0] * alpha;
                r.y = acc[ih * 4 + i][jh * 4 + 1] * alpha;
                r.z = acc[ih * 4 + i][jh * 4 + 2] * alpha;
                r.w = acc[ih * 4 + i][jh * 4 + 3] * alpha;
                if (bias) {
                    float4 bb = *(const float4*)(bias + n);
                    r.x += bb.x; r.y += bb.y; r.z += bb.z; r.w += bb.w;
                }
                if (Res) {
                    float4 rr = *(const float4*)(Res + (long long)m * ldc + n);
                    r.x += rr.x; r.y += rr.y; r.z += rr.z; r.w += rr.w;
                }
                if (RELU) {
                    r.x = fmaxf(r.x, 0.f); r.y = fmaxf(r.y, 0.f);
                    r.z = fmaxf(r.z, 0.f); r.w = fmaxf(r.w, 0.f);
                }
                *(float4*)(C + (long long)m * ldc + n) = r;
            }
        }
    }
}

// ================= symmetric cosine-sim GEMM (fp32 exact) ==================
__global__ void __launch_bounds__(256, 2)
sim_gemm_k(const float* __restrict__ nh, float* __restrict__ sim)
{
    int t = blockIdx.x;              // 0..35 pair index
    int bi = 0;
    while ((bi + 1) * (bi + 2) / 2 <= t) bi++;
    int bj = t - bi * (bi + 1) / 2;  // bj <= bi
    int z = blockIdx.z;

    const float* A = nh + (long long)z * NN * HD;
    float* C = sim + (long long)z * NN * NN;
    int m0 = bi * 128;
    int n0 = bj * 128;

    __shared__ float As[2][BKK][SPAD];
    __shared__ float Bs[2][BKK][SPAD];

    int tid = threadIdx.x;
    int tx = tid & 15;
    int ty = tid >> 4;

    int a_m = tid >> 1;
    int a_k = (tid & 1) * 4;
    const float* Aload = A + (long long)(m0 + a_m) * HD + a_k;
    const float* Bload = A + (long long)(n0 + a_m) * HD + a_k;

    float4 av = *(const float4*)Aload;
    float4 bv = *(const float4*)Bload;

    As[0][a_k + 0][a_m] = av.x;
    As[0][a_k + 1][a_m] = av.y;
    As[0][a_k + 2][a_m] = av.z;
    As[0][a_k + 3][a_m] = av.w;
    Bs[0][a_k + 0][a_m] = bv.x;
    Bs[0][a_k + 1][a_m] = bv.y;
    Bs[0][a_k + 2][a_m] = bv.z;
    Bs[0][a_k + 3][a_m] = bv.w;
    __syncthreads();

    float acc[8][8];
    #pragma unroll
    for (int i = 0; i < 8; i++)
        #pragma unroll
        for (int j = 0; j < 8; j++) acc[i][j] = 0.f;

    int cur = 0;
    for (int k0 = 0; ; ) {
        int k1 = k0 + BKK;
        bool more = (k1 < HD);
        if (more) {
            av = *(const float4*)(Aload + k1);
            bv = *(const float4*)(Bload + k1);
        }
        #pragma unroll
        for (int kk = 0; kk < BKK; kk++) {
            float4 a0 = *(const float4*)&As[cur][kk][ty * 4];
            float4 a1 = *(const float4*)&As[cur][kk][64 + ty * 4];
            float4 b0 = *(const float4*)&Bs[cur][kk][tx * 4];
            float4 b1 = *(const float4*)&Bs[cur][kk][64 + tx * 4];
            float a[8] = {a0.x, a0.y, a0.z, a0.w, a1.x, a1.y, a1.z, a1.w};
            float b[8] = {b0.x, b0.y, b0.z, b0.w, b1.x, b1.y, b1.z, b1.w};
            #pragma unroll
            for (int i = 0; i < 8; i++)
                #pragma unroll
                for (int j = 0; j < 8; j++)
                    acc[i][j] = fmaf(a[i], b[j], acc[i][j]);
        }
        if (!more) break;

        int nxt = cur ^ 1;
        As[nxt][a_k + 0][a_m] = av.x;
        As[nxt][a_k + 1][a_m] = av.y;
        As[nxt][a_k + 2][a_m] = av.z;
        As[nxt][a_k + 3][a_m] = av.w;
        Bs[nxt][a_k + 0][a_m] = bv.x;
        Bs[nxt][a_k + 1][a_m] = bv.y;
        Bs[nxt][a_k + 2][a_m] = bv.z;
        Bs[nxt][a_k + 3][a_m] = bv.w;
        __syncthreads();
        cur = nxt;
        k0 = k1;
    }

    bool mirror = (bi != bj);
    #pragma unroll
    for (int ih = 0; ih < 2; ih++) {
        #pragma unroll
        for (int i = 0; i < 4; i++) {
            int m = m0 + ih * 64 + ty * 4 + i;
            #pragma unroll
            for (int jh = 0; jh < 2; jh++) {
                int n = n0 + jh * 64 + tx * 4;
                float4 r;
                r.x = acc[ih * 4 + i][jh * 4 + 0];
                r.y = acc[ih * 4 + i][jh * 4 + 1];
                r.z = acc[ih * 4 + i][jh * 4 + 2];
                r.w = acc[ih * 4 + i][jh * 4 + 3];
                *(float4*)(C + (long long)m * NN + n) = r;
                if (mirror) {
                    C[(long long)(n + 0) * NN + m] = r.x;
                    C[(long long)(n + 1) * NN + m] = r.y;
                    C[(long long)(n + 2) * NN + m] = r.z;
                    C[(long long)(n + 3) * NN + m] = r.w;
                }
            }
        }
    }
}

// ================= tf32 tensor-core GEMM, 3-stage cp.async ================
#define ASTRIDE 20
#define BN128STR 136
#define BN64STR  68

__device__ __forceinline__ void cpa16(void* dst, const void* src)
{
    uint32_t s = (uint32_t)__cvta_generic_to_shared(dst);
    asm volatile("cp.async.cg.shared.global [%0], [%1], 16;" :: "r"(s), "l"(src));
}
template<int N> __device__ __forceinline__ void cpa_wait()
{
    asm volatile("cp.async.wait_group %0;" :: "n"(N));
}
__device__ __forceinline__ void cpa_commit()
{
    asm volatile("cp.async.commit_group;");
}
__device__ __forceinline__ void mma_tf32(float* d, const uint32_t* a, uint32_t b0, uint32_t b1)
{
    asm volatile(
        "mma.sync.aligned.m16n8k8.row.col.f32.tf32.tf32.f32 "
        "{%0,%1,%2,%3}, {%4,%5,%6,%7}, {%8,%9}, {%0,%1,%2,%3};"
        : "+f"(d[0]), "+f"(d[1]), "+f"(d[2]), "+f"(d[3])
        : "r"(a[0]), "r"(a[1]), "r"(a[2]), "r"(a[3]), "r"(b0), "r"(b1));
}

template<bool TRANSB, bool RELU, bool TF32OUT, int NTILE>
__global__ void __launch_bounds__(256, 2)
tf32gemm_k(const float* __restrict__ A, const float* __restrict__ B,
           const float* __restrict__ bias, const float* __restrict__ Res,
           float* __restrict__ C,
           int K, int lda, int ldb, int ldc,
           long long sA, long long sAi, long long sB, long long sBi,
           long long sC, long long sCi, int zi, float alpha)
{
    constexpr int NT = NTILE / 16;
    constexpr int BSTR = (NTILE == 128) ? BN128STR : BN64STR;
    constexpr int ASZ = 128 * ASTRIDE;
    constexpr int BSZ = TRANSB ? (NTILE * ASTRIDE) : (16 * BSTR);

    extern __shared__ __align__(16) float dsm[];
    float* As = dsm;               // 3 * ASZ
    float* Bs = dsm + 3 * ASZ;     // 3 * BSZ

    int bz = blockIdx.z;
    int zo = bz / zi, zin = bz % zi;
    A += zo * sA + zin * sAi;
    B += zo * sB + zin * sBi;
    C += zo * sC + zin * sCi;
    if (Res) Res += zo * sC + zin * sCi;

    int m0 = blockIdx.y * 128;
    int n0 = blockIdx.x * NTILE;

    int tid = threadIdx.x;
    int lane = tid & 31;
    int wid = tid >> 5;
    int wm = (wid & 3) * 32;
    int wn = (wid >> 2) * (NTILE / 2);
    int tig = lane & 3;
    int grp = lane >> 2;

    int ra = tid >> 2;
    int ca = (tid & 3) * 4;
    const float* Asrc0 = A + (long long)(m0 + ra) * lda + ca;
    const float* Asrc1 = A + (long long)(m0 + ra + 64) * lda + ca;
    int aoff0 = ra * ASTRIDE + ca;
    int aoff1 = (ra + 64) * ASTRIDE + ca;

    const float *Bsrc0 = nullptr, *Bsrc1 = nullptr;
    int boff0 = 0, boff1 = 0;
    if (TRANSB) {
        if (NTILE == 128) {
            Bsrc0 = B + (long long)(n0 + ra) * ldb + ca;
            Bsrc1 = B + (long long)(n0 + ra + 64) * ldb + ca;
            boff0 = aoff0;
            boff1 = aoff1;
        } else {
            Bsrc0 = B + (long long)(n0 + ra) * ldb + ca;
            boff0 = ra * ASTRIDE + ca;
        }
    } else {
        if (NTILE == 128) {
            int rb = tid >> 5;
            int cb = (tid & 31) * 4;
            Bsrc0 = B + (long long)rb * ldb + n0 + cb;
            Bsrc1 = B + (long long)(rb + 8) * ldb + n0 + cb;
            boff0 = rb * BSTR + cb;
            boff1 = (rb + 8) * BSTR + cb;
        } else {
            int rb = tid >> 4;
            int cb = (tid & 15) * 4;
            Bsrc0 = B + (long long)rb * ldb + n0 + cb;
            boff0 = rb * BSTR + cb;
        }
    }
    constexpr bool BTWO = (NTILE == 128);

    const int kIters = K >> 4;

    {
        cpa16(&As[aoff0], Asrc0);
        cpa16(&As[aoff1], Asrc1);
        cpa16(&Bs[boff0], Bsrc0);
        if (BTWO) cpa16(&Bs[boff1], Bsrc1);
        cpa_commit();
        if (kIters > 1) {
            cpa16(&As[ASZ + aoff0], Asrc0 + 16);
            cpa16(&As[ASZ + aoff1], Asrc1 + 16);
            if (TRANSB) {
                cpa16(&Bs[BSZ + boff0], Bsrc0 + 16);
                if (BTWO) cpa16(&Bs[BSZ + boff1], Bsrc1 + 16);
            } else {
                cpa16(&Bs[BSZ + boff0], Bsrc0 + (long long)16 * ldb);
                if (BTWO) cpa16(&Bs[BSZ + boff1], Bsrc1 + (long long)16 * ldb);
            }
            cpa_commit();
        }
    }

    float acc[2][NT][4];
    #pragma unroll
    for (int mt = 0; mt < 2; mt++)
        #pragma unroll
        for (int nt = 0; nt < NT; nt++)
            #pragma unroll
            for (int r = 0; r < 4; r++) acc[mt][nt][r] = 0.f;

    int bufm = 0;
    for (int it = 0; it < kIters; it++) {
        if (it + 1 < kIters) cpa_wait<1>(); else cpa_wait<0>();
        __syncthreads();

        if (it + 2 < kIters) {
            int pb = bufm + 2; if (pb >= 3) pb -= 3;
            int kf = (it + 2) << 4;
            cpa16(&As[pb * ASZ + aoff0], Asrc0 + kf);
            cpa16(&As[pb * ASZ + aoff1], Asrc1 + kf);
            if (TRANSB) {
                cpa16(&Bs[pb * BSZ + boff0], Bsrc0 + kf);
                if (BTWO) cpa16(&Bs[pb * BSZ + boff1], Bsrc1 + kf);
            } else {
                cpa16(&Bs[pb * BSZ + boff0], Bsrc0 + (long long)kf * ldb);
                if (BTWO) cpa16(&Bs[pb * BSZ + boff1], Bsrc1 + (long long)kf * ldb);
            }
            cpa_commit();
        }

        const float* Ac = As + bufm * ASZ;
        const float* Bc = Bs + bufm * BSZ;
        #pragma unroll
        for (int ks = 0; ks < 16; ks += 8) {
            uint32_t af[2][4], bf[NT][2];
            #pragma unroll
            for (int mt = 0; mt < 2; mt++) {
                int mA = wm + mt * 16 + grp;
                af[mt][0] = __float_as_uint(Ac[mA * ASTRIDE + ks + tig]);
                af[mt][1] = __float_as_uint(Ac[(mA + 8) * ASTRIDE + ks + tig]);
                af[mt][2] = __float_as_uint(Ac[mA * ASTRIDE + ks + tig + 4]);
                af[mt][3] = __float_as_uint(Ac[(mA + 8) * ASTRIDE + ks + tig + 4]);
            }
            #pragma unroll
            for (int nt = 0; nt < NT; nt++) {
                int nB = wn + nt * 8 + grp;
                if (TRANSB) {
                    bf[nt][0] = __float_as_uint(Bc[nB * ASTRIDE + ks + tig]);
                    bf[nt][1] = __float_as_uint(Bc[nB * ASTRIDE + ks + tig + 4]);
                } else {
                    bf[nt][0] = __float_as_uint(Bc[(ks + tig) * BSTR + nB]);
                    bf[nt][1] = __float_as_uint(Bc[(ks + tig + 4) * BSTR + nB]);
                }
            }
            #pragma unroll
            for (int mt = 0; mt < 2; mt++)
                #pragma unroll
                for (int nt = 0; nt < NT; nt++)
                    mma_tf32(acc[mt][nt], af[mt], bf[nt][0], bf[nt][1]);
        }
        bufm++; if (bufm >= 3) bufm = 0;
    }

    #pragma unroll
    for (int mt = 0; mt < 2; mt++) {
        #pragma unroll
        for (int half = 0; half < 2; half++) {
            int m = m0 + wm + mt * 16 + grp + half * 8;
            #pragma unroll
            for (int nt = 0; nt < NT; nt++) {
                int n = n0 + wn + nt * 8 + 2 * tig;
                float2 r;
                r.x = acc[mt][nt][half * 2 + 0] * alpha;
                r.y = acc[mt][nt][half * 2 + 1] * alpha;
                if (bias) {
                    r.x += bias[n];
                    r.y += bias[n + 1];
                }
                if (Res) {
                    const float2 rr = *(const float2*)(Res + (long long)m * ldc + n);
                    r.x += rr.x; r.y += rr.y;
                }
                if (RELU) {
                    r.x = fmaxf(r.x, 0.f);
                    r.y = fmaxf(r.y, 0.f);
                }
                if (TF32OUT) {
                    r.x = rna_tf32(r.x);
                    r.y = rna_tf32(r.y);
                }
                *(float2*)(C + (long long)m * ldc + n) = r;
            }
        }
    }
}

// ================= fused flash attention (tf32 MMA, online softmax) ========
#define QSTR 132
#define KSTR 132
#define VSTR 136
#define PSTR 36
static const int FLASH_SMEM = (128*QSTR + 2*32*KSTR + 2*32*VSTR + 128*PSTR) * 4;

__global__ void __launch_bounds__(256, 1)
flash_attn_kernel(const float* __restrict__ qkv, float* __restrict__ ao)
{
    extern __shared__ __align__(16) float sm[];
    float* Qs = sm;
    float* Ks = Qs + 128 * QSTR;
    float* Vs = Ks + 2 * 32 * KSTR;
    float* Ps = Vs + 2 * 32 * VSTR;

    int qt = blockIdx.x;
    int bh = blockIdx.y;
    int b = bh / NHE, h = bh - b * NHE;
    const float* qbase = qkv + (long long)b * NN * HD4 + (long long)qt * 128 * HD4 + HD + h * DHE;
    const float* kbase = qkv + (long long)b * NN * HD4 + 2 * HD + h * DHE;
    const float* vbase = qkv + (long long)b * NN * HD4 + 3 * HD + h * DHE;

    int tid = threadIdx.x;
    int lane = tid & 31, wid = tid >> 5;
    int tig = lane & 3, grp = lane >> 2;
    int wq = wid * 16;

    #pragma unroll
    for (int c = 0; c < 16; c++) {
        int chunk = tid + c * 256;
        int row = chunk >> 5, col = (chunk & 31) * 4;
        cpa16(&Qs[row * QSTR + col], qbase + (long long)row * HD4 + col);
    }
    #pragma unroll
    for (int c = 0; c < 4; c++) {
        int chunk = tid + c * 256;
        int row = chunk >> 5, col = (chunk & 31) * 4;
        cpa16(&Ks[row * KSTR + col], kbase + (long long)row * HD4 + col);
        cpa16(&Vs[row * VSTR + col], vbase + (long long)row * HD4 + col);
    }
    cpa_commit();

    float Oacc[16][4];
    #pragma unroll
    for (int nt = 0; nt < 16; nt++)
        #pragma unroll
        for (int j = 0; j < 4; j++) Oacc[nt][j] = 0.f;
    float m0r = -1e30f, m1r = -1e30f;
    float l0 = 0.f, l1 = 0.f;
    const float alpha = 0.08838834764831843f;

    int cur = 0;
    for (int it = 0; it < 32; it++) {
        bool more = (it + 1 < 32);
        if (more) {
            int nxt = cur ^ 1;
            const float* kb = kbase + (long long)(it + 1) * 32 * HD4;
            const float* vb = vbase + (long long)(it + 1) * 32 * HD4;
            #pragma unroll
            for (int c = 0; c < 4; c++) {
                int chunk = tid + c * 256;
                int row = chunk >> 5, col = (chunk & 31) * 4;
                cpa16(&Ks[nxt * 32 * KSTR + row * KSTR + col], kb + (long long)row * HD4 + col);
                cpa16(&Vs[nxt * 32 * VSTR + row * VSTR + col], vb + (long long)row * HD4 + col);
            }
            cpa_commit();
            cpa_wait<1>();
        } else {
            cpa_wait<0>();
        }
        __syncthreads();

        const float* Kc = Ks + cur * 32 * KSTR;
        const float* Vc = Vs + cur * 32 * VSTR;

        float s[4][4];
        #pragma unroll
        for (int nt = 0; nt < 4; nt++)
            #pragma unroll
            for (int j = 0; j < 4; j++) s[nt][j] = 0.f;
        #pragma unroll
        for (int kc = 0; kc < 16; kc++) {
            uint32_t af[4];
            af[0] = __float_as_uint(Qs[(wq + grp) * QSTR + kc * 8 + tig]);
            af[1] = __float_as_uint(Qs[(wq + grp + 8) * QSTR + kc * 8 + tig]);
            af[2] = __float_as_uint(Qs[(wq + grp) * QSTR + kc * 8 + tig + 4]);
            af[3] = __float_as_uint(Qs[(wq + grp + 8) * QSTR + kc * 8 + tig + 4]);
            #pragma unroll
            for (int nt = 0; nt < 4; nt++) {
                uint32_t b0 = __float_as_uint(Kc[(nt * 8 + grp) * KSTR + kc * 8 + tig]);
                uint32_t b1 = __float_as_uint(Kc[(nt * 8 + grp) * KSTR + kc * 8 + tig + 4]);
                mma_tf32(s[nt], af, b0, b1);
            }
        }

        float t0 = -1e30f, t1 = -1e30f;
        #pragma unroll
        for (int nt = 0; nt < 4; nt++) {
            s[nt][0] *= alpha; s[nt][1] *= alpha;
            s[nt][2] *= alpha; s[nt][3] *= alpha;
            t0 = fmaxf(t0, fmaxf(s[nt][0], s[nt][1]));
            t1 = fmaxf(t1, fmaxf(s[nt][2], s[nt][3]));
        }
        t0 = fmaxf(t0, __shfl_xor_sync(0xffffffffu, t0, 1));
        t0 = fmaxf(t0, __shfl_xor_sync(0xffffffffu, t0, 2));
        t1 = fmaxf(t1, __shfl_xor_sync(0xffffffffu, t1, 1));
        t1 = fmaxf(t1, __shfl_xor_sync(0xffffffffu, t1, 2));
        float mn0 = fmaxf(m0r, t0), mn1 = fmaxf(m1r, t1);
        float f0 = __expf(m0r - mn0), f1 = __expf(m1r - mn1);
        float ps0 = 0.f, ps1 = 0.f;
        #pragma unroll
        for (int nt = 0; nt < 4; nt++) {
            float p0 = __expf(s[nt][0] - mn0);
            float p1 = __expf(s[nt][1] - mn0);
            float p2 = __expf(s[nt][2] - mn1);
            float p3 = __expf(s[nt][3] - mn1);
            ps0 += p0 + p1;
            ps1 += p2 + p3;
            float2 lo = { rna_tf32(p0), rna_tf32(p1) };
            float2 hi = { rna_tf32(p2), rna_tf32(p3) };
            *(float2*)&Ps[(wq + grp) * PSTR + nt * 8 + 2 * tig] = lo;
            *(float2*)&Ps[(wq + grp + 8) * PSTR + nt * 8 + 2 * tig] = hi;
        }
        ps0 += __shfl_xor_sync(0xffffffffu, ps0, 1);
        ps0 += __shfl_xor_sync(0xffffffffu, ps0, 2);
        ps1 += __shfl_xor_sync(0xffffffffu, ps1, 1);
        ps1 += __shfl_xor_sync(0xffffffffu, ps1, 2);
        l0 = l0 * f0 + ps0;
        l1 = l1 * f1 + ps1;
        m0r = mn0; m1r = mn1;
        #pragma unroll
        for (int nt = 0; nt < 16; nt++) {
            Oacc[nt][0] *= f0; Oacc[nt][1] *= f0;
            Oacc[nt][2] *= f1; Oacc[nt][3] *= f1;
        }
        __syncwarp();

        #pragma unroll
        for (int kc = 0; kc < 4; kc++) {
            uint32_t af[4];
            af[0] = __float_as_uint(Ps[(wq + grp) * PSTR + kc * 8 + tig]);
            af[1] = __float_as_uint(Ps[(wq + grp + 8) * PSTR + kc * 8 + tig]);
            af[2] = __float_as_uint(Ps[(wq + grp) * PSTR + kc * 8 + tig + 4]);
            af[3] = __float_as_uint(Ps[(wq + grp + 8) * PSTR + kc * 8 + tig + 4]);
            #pragma unroll
            for (int nt = 0; nt < 16; nt++) {
                uint32_t b0 = __float_as_uint(Vc[(kc * 8 + tig) * VSTR + nt * 8 + grp]);
                uint32_t b1 = __float_as_uint(Vc[(kc * 8 + tig + 4) * VSTR + nt * 8 + grp]);
                mma_tf32(Oacc[nt], af, b0, b1);
            }
        }
        if (!more) break;
        __syncthreads();
        cur ^= 1;
    }

    float inv0 = 1.f / l0, inv1 = 1.f / l1;
    int r0 = qt * 128 + wq + grp;
    float* o0 = ao + (long long)b * NN * HD + (long long)r0 * HD + h * DHE;
    float* o1 = o0 + 8 * HD;
    #pragma unroll
    for (int nt = 0; nt < 16; nt++) {
        int col = nt * 8 + 2 * tig;
        float2 va = { rna_tf32(Oacc[nt][0] * inv0), rna_tf32(Oacc[nt][1] * inv0) };
        float2 vb = { rna_tf32(Oacc[nt][2] * inv1), rna_tf32(Oacc[nt][3] * inv1) };
        *(float2*)(o0 + col) = va;
        *(float2*)(o1 + col) = vb;
    }
}

// ---------------- small kernels ----------------
__global__ void feats_kernel(const float* __restrict__ x, float* __restrict__ feats)
{
    long long i = (long long)blockIdx.x * blockDim.x + threadIdx.x;
    if (i >= (long long)NB * NN * CIN) return;
    int c = (int)(i & (CIN - 1));
    long long bn = i >> 6;
    int n = (int)(bn & (NN - 1));
    int b = (int)(bn >> 10);
    feats[i] = x[((long long)b * CIN + c) * NN + n];
}

__global__ void prep_kernel(const float* __restrict__ gcn_W, const float* __restrict__ Wq,
                            const float* __restrict__ Wk, const float* __restrict__ Wv,
                            const float* __restrict__ gcn_b, const float* __restrict__ bq,
                            const float* __restrict__ bk, const float* __restrict__ bv,
                            const float* __restrict__ Wo, const float* __restrict__ W1,
                            const float* __restrict__ W2,
                            float* __restrict__ wpack, float* __restrict__ bpack,
                            float* __restrict__ wr)
{
    int i = blockIdx.x * blockDim.x + threadIdx.x;
    const int NWP = 3 * 384 * 1536;
    const int NBP = 3 * 1536;
    const int NWO = 442368;
    const int NW1 = 884736;
    if (i < NWP) {
        int l = i / (384 * 1536);
        int rem = i - l * (384 * 1536);
        int r = rem / 1536;
        int c = rem - r * 1536;
        int sel = c / 384, cc = c - sel * 384;
        const float* src = (sel == 0) ? gcn_W : (sel == 1) ? Wq : (sel == 2) ? Wk : Wv;
        wpack[i] = rna_tf32(src[((long long)l * 384 + r) * 384 + cc]);
        return;
    }
    int j = i - NWP;
    if (j < NBP) {
        int l = j / 1536;
        int c = j - l * 1536;
        int sel = c / 384, cc = c - sel * 384;
        const float* src = (sel == 0) ? gcn_b : (sel == 1) ? bq : (sel == 2) ? bk : bv;
        bpack[j] = src[l * 384 + cc];
        return;
    }
    j -= NBP;
    if (j < NWO) { wr[WR_WO + j] = rna_tf32(Wo[j]); return; }
    j -= NWO;
    if (j < NW1) { wr[WR_W1 + j] = rna_tf32(W1[j]); return; }
    j -= NW1;
    if (j < NW1) { wr[WR_W2 + j] = rna_tf32(W2[j]); return; }
}

__device__ __forceinline__ void block_reduce2(float& s1, float& s2)
{
    __shared__ float b1[4], b2[4];
    #pragma unroll
    for (int o = 16; o > 0; o >>= 1) {
        s1 += __shfl_down_sync(0xffffffffu, s1, o);
        s2 += __shfl_down_sync(0xffffffffu, s2, o);
    }
    int w = threadIdx.x >> 5;
    if ((threadIdx.x & 31) == 0) { b1[w] = s1; b2[w] = s2; }
    __syncthreads();
    s1 = b1[0] + b1[1] + b1[2] + b1[3];
    s2 = b2[0] + b2[1] + b2[2] + b2[3];
}

__global__ void norm_kernel(const float* __restrict__ h0, float* __restrict__ nh,
                            float* __restrict__ h0r)
{
    long long bn = blockIdx.x;
    int t = threadIdx.x; // 128
    const float* r = h0 + bn * HD;
    float v0 = r[t], v1 = r[t + 128], v2 = r[t + 256];
    float ss = v0 * v0 + v1 * v1 + v2 * v2, dummy = 0.f;
    block_reduce2(ss, dummy);
    float rinv = rsqrtf(ss);
    float* o = nh + bn * HD;
    o[t] = v0 * rinv; o[t + 128] = v1 * rinv; o[t + 256] = v2 * rinv;
    float* o2 = h0r + bn * HD;
    o2[t] = rna_tf32(v0); o2[t + 128] = rna_tf32(v1); o2[t + 256] = rna_tf32(v2);
}

__global__ void topk_warp_kernel(const float* __restrict__ sim, int* __restrict__ knn)
{
    int warp = blockIdx.x * (blockDim.x >> 5) + (threadIdx.x >> 5);
    int lane = threadIdx.x & 31;
    int n = warp & (NN - 1);
    const float* row = sim + (long long)warp * NN;
    float v[32];
    #pragma unroll
    for (int j = 0; j < 32; j++) {
        int m = j * 32 + lane;
        v[j] = (m == n) ? -3e38f : row[m];
    }
    unsigned taken = 0;
    int* o = knn + (long long)warp * KNN;
    for (int r = 0; r < KNN; r++) {
        float bv = -3e38f; int bj = 0;
        #pragma unroll
        for (int j = 0; j < 32; j++) {
            bool free_ = !((taken >> j) & 1u);
            if (free_ && v[j] > bv) { bv = v[j]; bj = j; }
        }
        int bidx = bj * 32 + lane;
        #pragma unroll
        for (int off = 16; off > 0; off >>= 1) {
            float ov = __shfl_xor_sync(0xffffffffu, bv, off);
            int   oi = __shfl_xor_sync(0xffffffffu, bidx, off);
            if (ov > bv || (ov == bv && oi < bidx)) { bv = ov; bidx = oi; }
        }
        if ((bidx & 31) == lane) taken |= 1u << (bidx >> 5);
        if (lane == 0) o[r] = bidx;
    }
}

__global__ void gcn_agg_ln(const float* __restrict__ hcur, const float* __restrict__ xw,
                           int ldx,
                           const int* __restrict__ knn,
                           const float* __restrict__ scale, const float* __restrict__ bias,
                           float* __restrict__ out)
{
    int bn = blockIdx.x;
    int b = bn >> 10;
    int t = threadIdx.x; // 128
    __shared__ int sidx[KNN];
    if (t < KNN) sidx[t] = knn[(long long)bn * KNN + t];
    __syncthreads();
    const float* xr = xw + (long long)bn * ldx;
    float a0 = xr[t], a1 = xr[t + 128], a2 = xr[t + 256];
    #pragma unroll 4
    for (int j = 0; j < KNN; j++) {
        const float* r = xw + ((long long)(b * NN) + sidx[j]) * ldx;
        a0 += r[t]; a1 += r[t + 128]; a2 += r[t + 256];
    }
    const float* h = hcur + (long long)bn * HD;
    const float inv17 = 1.f / 17.f;
    float v0 = h[t] + a0 * inv17;
    float v1 = h[t + 128] + a1 * inv17;
    float v2 = h[t + 256] + a2 * inv17;
    float s1 = v0 + v1 + v2;
    float s2 = v0 * v0 + v1 * v1 + v2 * v2;
    block_reduce2(s1, s2);
    float mu = s1 * (1.f / HD);
    float var = s2 * (1.f / HD) - mu * mu;
    float rstd = rsqrtf(var + 1e-5f);
    float* o = out + (long long)bn * HD;
    o[t]       = (v0 - mu) * rstd * scale[t]       + bias[t];
    o[t + 128] = (v1 - mu) * rstd * scale[t + 128] + bias[t + 128];
    o[t + 256] = (v2 - mu) * rstd * scale[t + 256] + bias[t + 256];
}

__global__ void add_ln_kernel(const float* __restrict__ a, const float* __restrict__ b,
                              const float* __restrict__ plus,
                              const float* __restrict__ scale, const float* __restrict__ bias,
                              float* __restrict__ out, int rnd)
{
    long long bn = blockIdx.x;
    int t = threadIdx.x; // 128
    const float* ar = a + bn * HD;
    float v0 = ar[t], v1 = ar[t + 128], v2 = ar[t + 256];
    if (b) {
        const float* br = b + bn * HD;
        v0 += br[t]; v1 += br[t + 128]; v2 += br[t + 256];
    }
    float s1 = v0 + v1 + v2;
    float s2 = v0 * v0 + v1 * v1 + v2 * v2;
    block_reduce2(s1, s2);
    float mu = s1 * (1.f / HD);
    float var = s2 * (1.f / HD) - mu * mu;
    float rstd = rsqrtf(var + 1e-5f);
    float y0 = (v0 - mu) * rstd * scale[t]       + bias[t];
    float y1 = (v1 - mu) * rstd * scale[t + 128] + bias[t + 128];
    float y2 = (v2 - mu) * rstd * scale[t + 256] + bias[t + 256];
    if (plus) {
        const float* pr = plus + bn * HD;
        y0 += pr[t]; y1 += pr[t + 128]; y2 += pr[t + 256];
    }
    if (rnd) { y0 = rna_tf32(y0); y1 = rna_tf32(y1); y2 = rna_tf32(y2); }
    float* o = out + bn * HD;
    o[t] = y0; o[t + 128] = y1; o[t + 256] = y2;
}

__global__ void pool_kernel(const float* __restrict__ h, float* __restrict__ pooled)
{
    int b = blockIdx.x;
    int t = threadIdx.x; // 384
    float s = 0.f;
    const float* base = h + (long long)b * NN * HD + t;
    for (int n = 0; n < NN; n++) s += base[(long long)n * HD];
    pooled[b * HD + t] = s * (1.f / NN);
}

__global__ void fin1_kernel(const float* __restrict__ pooled, const float* __restrict__ W,
                            const float* __restrict__ bias, float* __restrict__ z)
{
    int b = blockIdx.x;
    int j = threadIdx.x; // 384
    const float* p = pooled + b * HD;
    float s = bias[j];
    for (int k = 0; k < HD; k++) s = fmaf(p[k], W[k * HD + j], s);
    z[b * HD + j] = fmaxf(s, 0.f);
}

__global__ void fin2_kernel(const float* __restrict__ z, const float* __restrict__ W,
                            const float* __restrict__ bias, float* __restrict__ out)
{
    int b = blockIdx.x;
    int j = threadIdx.x; // 128
    const float* p = z + b * HD;
    float s = bias[j];
    for (int k = 0; k < HD; k++) s = fmaf(p[k], W[k * 128 + j], s);
    out[b * 128 + j] = s;
}

// ---------------- host-side GEMM dispatchers ----------------
static void gemm_f32(const float* A, const float* B, const float* bias, const float* Res, float* C,
                     int M, int Nn, int K, int lda, int ldb, int ldc,
                     long long sA, long long sAi, long long sB, long long sBi,
                     long long sC, long long sCi, int zi, int nz,
                     float alpha, bool transb, bool relu, cudaStream_t st = 0)
{
    dim3 grid(Nn / BN, M / BM, nz), block(256);
    if (transb) {
        if (relu) gemm_k<true, true ><<<grid, block, 0, st>>>(A, B, bias, Res, C, M, Nn, K, lda, ldb, ldc, sA, sAi, sB, sBi, sC, sCi, zi, alpha);
        else      gemm_k<true, false><<<grid, block, 0, st>>>(A, B, bias, Res, C, M, Nn, K, lda, ldb, ldc, sA, sAi, sB, sBi, sC, sCi, zi, alpha);
    } else {
        if (relu) gemm_k<false, true ><<<grid, block, 0, st>>>(A, B, bias, Res, C, M, Nn, K, lda, ldb, ldc, sA, sAi, sB, sBi, sC, sCi, zi, alpha);
        else      gemm_k<false, false><<<grid, block, 0, st>>>(A, B, bias, Res, C, M, Nn, K, lda, ldb, ldc, sA, sAi, sB, sBi, sC, sCi, zi, alpha);
    }
}

static void gemm_tf(const float* A, const float* B, const float* bias, const float* Res, float* C,
                    int M, int Nn, int K, int lda, int ldb, int ldc,
                    long long sA, long long sAi, long long sB, long long sBi,
                    long long sC, long long sCi, int zi, int nz,
                    float alpha, bool transb, bool relu, bool tf32out, int ntile,
                    cudaStream_t st = 0)
{
    dim3 grid(Nn / ntile, M / 128, nz), block(256);
    #define DISP(TB, RL, TO, NTL) do { \
        constexpr int BSZc = TB ? (NTL * ASTRIDE) : (16 * ((NTL == 128) ? BN128STR : BN64STR)); \
        int smemb = (3 * 128 * ASTRIDE + 3 * BSZc) * 4; \
        cudaFuncSetAttribute(tf32gemm_k<TB, RL, TO, NTL>, cudaFuncAttributeMaxDynamicSharedMemorySize, smemb); \
        tf32gemm_k<TB, RL, TO, NTL><<<grid, block, smemb, st>>>(A, B, bias, Res, C, K, lda, ldb, ldc, sA, sAi, sB, sBi, sC, sCi, zi, alpha); \
    } while (0)
    if (ntile == 128) {
        if (transb) {
            if (relu)  { if (tf32out) DISP(true, true, true, 128);  else DISP(true, true, false, 128); }
            else       { if (tf32out) DISP(true, false, true, 128); else DISP(true, false, false, 128); }
        } else {
            if (relu)  { if (tf32out) DISP(false, true, true, 128);  else DISP(false, true, false, 128); }
            else       { if (tf32out) DISP(false, false, true, 128); else DISP(false, false, false, 128); }
        }
    } else {
        if (transb) {
            if (relu)  { if (tf32out) DISP(true, true, true, 64);  else DISP(true, true, false, 64); }
            else       { if (tf32out) DISP(true, false, true, 64); else DISP(true, false, false, 64); }
        } else {
            if (relu)  { if (tf32out) DISP(false, true, true, 64);  else DISP(false, true, false, 64); }
            else       { if (tf32out) DISP(false, false, true, 64); else DISP(false, false, false, 64); }
        }
    }
    #undef DISP
}

template<typename T> static T* sym_addr(const void* sym)
{
    void* p = nullptr;
    cudaGetSymbolAddress(&p, sym);
    return (T*)p;
}

extern "C" void kernel_launch(void* const* d_in, const int* in_sizes, int n_in,
                              void* d_out, int out_size)
{
    const float* x      = (const float*)d_in[0];
    const float* W_enc  = (const float*)d_in[1];
    const float* b_enc  = (const float*)d_in[2];
    const float* gcn_W  = (const float*)d_in[3];
    const float* gcn_b  = (const float*)d_in[4];
    const float* Wq     = (const float*)d_in[5];
    const float* bq     = (const float*)d_in[6];
    const float* Wk     = (const float*)d_in[7];
    const float* bk     = (const float*)d_in[8];
    const float* Wv     = (const float*)d_in[9];
    const float* bv     = (const float*)d_in[10];
    const float* Wo     = (const float*)d_in[11];
    const float* bo     = (const float*)d_in[12];
    const float* lnsc   = (const float*)d_in[13];
    const float* lnbi   = (const float*)d_in[14];
    const float* W1     = (const float*)d_in[15];
    const float* b1     = (const float*)d_in[16];
    const float* W2     = (const float*)d_in[17];
    const float* b2     = (const float*)d_in[18];
    const float* lin1_W = (const float*)d_in[19];
    const float* lin1_b = (const float*)d_in[20];
    const float* lin2_W = (const float*)d_in[21];
    const float* lin2_b = (const float*)d_in[22];
    float* outp = (float*)d_out;

    float* featsp = sym_addr<float>(g_feats);
    float* h0p    = sym_addr<float>(g_h0);
    float* h0rp   = sym_addr<float>(g_h0r);
    float* nhp    = sym_addr<float>(g_nh);
    float* simp   = sym_addr<float>(g_sim);
    int*   knnp   = sym_addr<int>(g_knn);
    float* hcurp  = sym_addr<float>(g_hcur);
    float* qkvgp  = sym_addr<float>(g_qkvg);
    float* hlocp  = sym_addr<float>(g_hloc);
    float* aop    = sym_addr<float>(g_ao);
    float* op     = sym_addr<float>(g_o);
    float* combp  = sym_addr<float>(g_comb);
    float* mlp1p  = sym_addr<float>(g_mlp1);
    float* ffp    = sym_addr<float>(g_ff);
    float* poolp  = sym_addr<float>(g_pool);
    float* zp     = sym_addr<float>(g_z);
    float* wpackp = sym_addr<float>(g_wpack);
    float* bpackp = sym_addr<float>(g_bpack);
    float* wrp    = sym_addr<float>(g_wr);

    cudaFuncSetAttribute(flash_attn_kernel, cudaFuncAttributeMaxDynamicSharedMemorySize, FLASH_SMEM);

    const long long NH  = (long long)NN * HD;
    const long long NH4 = (long long)NN * HD4;
    const int WSQ = HD * HD;

    cudaStream_t sB;
    cudaStreamCreateWithFlags(&sB, cudaStreamNonBlocking);
    cudaEvent_t evFork, evEnd;
    cudaEventCreateWithFlags(&evFork, cudaEventDisableTiming);
    cudaEventCreateWithFlags(&evEnd, cudaEventDisableTiming);

    // shared prologue on main: weight prep + feats
    {
        int total = 3 * 384 * 1536 + 3 * 1536 + 442368 + 884736 + 884736;
        prep_kernel<<<(total + 255) / 256, 256>>>(gcn_W, Wq, Wk, Wv, gcn_b, bq, bk, bv,
                                                  Wo, W1, W2, wpackp, bpackp, wrp);
    }
    feats_kernel<<<(NB * NN * CIN + 255) / 256, 256>>>(x, featsp);
    cudaEventRecord(evFork, 0);
    cudaStreamWaitEvent(sB, evFork, 0);

    // per-half independent pipeline (batches [hb*4, hb*4+4))
    auto run_half = [&](int hb, cudaStream_t st) {
        long long off   = (long long)hb * HB * NH;        // hidden-sized offset
        long long off4  = (long long)hb * HB * NH4;       // packed qkv offset
        long long offS  = (long long)hb * HB * NN * NN;   // sim offset
        long long offK  = (long long)hb * HB * NN * KNN;  // knn offset
        long long offF  = (long long)hb * HB * NN * CIN;  // feats offset
        const float* h0h   = h0p + off;
        float* nhh   = nhp + off;
        float* h0rh  = h0rp + off;
        float* simh  = simp + offS;
        int*   knnh  = knnp + offK;
        float* qkvh  = qkvgp + off4;
        float* hloch = hlocp + off;
        float* aoh   = aop + off;
        float* oh    = op + off;
        float* combh = combp + off;
        float* mlp1h = mlp1p + (long long)hb * HB * NN * 2 * HD;
        float* ffh   = ffp + off;
        float* hcurh = hcurp + off;

        // encoder (fp32 exact) + norm
        gemm_f32(featsp + offF, W_enc, b_enc, nullptr, h0p + off,
                 NN, HD, CIN, CIN, HD, HD,
                 (long long)NN * CIN, 0, 0, 0, NH, 0, 1, HB, 1.f, false, false, st);
        norm_kernel<<<HB * NN, 128, 0, st>>>(h0h, nhh, h0rh);

        // graph build (fp32 exact, symmetric)
        sim_gemm_k<<<dim3(36, 1, HB), 256, 0, st>>>(nhh, simh);
        topk_warp_kernel<<<HB * NN / 8, 256, 0, st>>>(simh, knnh);

        const float* hin = h0rh;
        for (int l = 0; l < NL; l++) {
            const float* scl = lnsc + (l * 3) * HD;
            const float* bil = lnbi + (l * 3) * HD;

            gemm_tf(hin, wpackp + (long long)l * HD * HD4, bpackp + l * HD4, nullptr, qkvh,
                    NN, HD4, HD, HD, HD4, HD4, NH, 0, 0, 0, NH4, 0, 1, HB,
                    1.f, false, false, true, 128, st);
            gcn_agg_ln<<<HB * NN, 128, 0, st>>>(hin, qkvh, HD4, knnh, scl, bil, hloch);
            flash_attn_kernel<<<dim3(NN / 128, HB * NHE), 256, FLASH_SMEM, st>>>(qkvh, aoh);
            gemm_tf(aoh, wrp + WR_WO + (long long)l * WSQ, bo + l * HD, nullptr, oh,
                    NN, HD, HD, HD, HD, HD, NH, 0, 0, 0, NH, 0, 1, HB,
                    1.f, false, false, false, 64, st);
            add_ln_kernel<<<HB * NN, 128, 0, st>>>(hin, oh, hloch, scl + HD, bil + HD, combh, 1);

            gemm_tf(combh, wrp + WR_W1 + (long long)l * HD * 2 * HD, b1 + l * 2 * HD, nullptr, mlp1h,
                    NN, 2 * HD, HD, HD, 2 * HD, 2 * HD,
                    NH, 0, 0, 0, (long long)NN * 2 * HD, 0, 1, HB, 1.f, false, true, true, 128, st);
            gemm_tf(mlp1h, wrp + WR_W2 + (long long)l * 2 * HD * HD, b2 + l * HD, combh, ffh,
                    NN, HD, 2 * HD, 2 * HD, HD, HD,
                    (long long)NN * 2 * HD, 0, 0, 0, NH, 0, 1, HB, 1.f, false, false, false, 64, st);
            add_ln_kernel<<<HB * NN, 128, 0, st>>>(ffh, nullptr, nullptr, scl + 2 * HD, bil + 2 * HD, hcurh, 1);
            hin = hcurh;
        }

        // head (per-half)
        pool_kernel<<<HB, HD, 0, st>>>(hin, poolp + hb * HB * HD);
        fin1_kernel<<<HB, HD, 0, st>>>(poolp + hb * HB * HD, lin1_W, lin1_b, zp + hb * HB * HD);
        fin2_kernel<<<HB, 128, 0, st>>>(zp + hb * HB * HD, lin2_W, lin2_b, outp + hb * HB * 128);
    };

    run_half(0, 0);    // batches 0..3 on main stream
    run_half(1, sB);   // batches 4..7 on side stream

    // join: main stream must order sB's output writes before capture end
    cudaEventRecord(evEnd, sB);
    cudaStreamWaitEvent(0, evEnd, 0);

    cudaEventDestroy(evFork);
    cudaEventDestroy(evEnd);
    cudaStreamDestroy(sB);
}